// round 1
// baseline (speedup 1.0000x reference)
#include <cuda_runtime.h>
#include <math.h>
#include <stdint.h>

// ---------------- problem constants ----------------
#define Bdoc 4
#define Lseq 1024
#define Ment 128
#define Rht  512
#define HID  1024
#define NH   16
#define NE   42
#define EMB  768
#define NBLK 12      // EMB/64
#define NCLS 97
#define NPROJ 128
#define NROW (Bdoc*Rht)   // 2048

// ---------------- scratch (__device__ globals; no allocation allowed) ------
__device__ float g_ent_emb[Bdoc*NE*HID];            // 0.7 MB
__device__ float g_attn_mean[Bdoc*NE*NH*Lseq];      // 11 MB
__device__ float g_hta[Bdoc*Rht*Lseq];              // 8.4 MB
__device__ float g_rel[NROW*HID];                   // 8.4 MB
__device__ float g_Xh[NROW*2*HID];                  // 16.8 MB
__device__ float g_Xt[NROW*2*HID];                  // 16.8 MB
__device__ float g_h[NROW*EMB];                     // 6.3 MB
__device__ float g_t[NROW*EMB];                     // 6.3 MB

// ---------------- K1: entity logsumexp pooling ----------------
__global__ void k_ent_emb(const float* __restrict__ ent,
                          const int* __restrict__ labels)
{
    int e = blockIdx.x, b = blockIdx.y;
    __shared__ int s_idx[Ment];
    __shared__ int s_cnt;
    int tid = threadIdx.x;
    if (tid == 0) s_cnt = 0;
    __syncthreads();
    if (tid < Ment) {
        if (labels[b*Ment + tid] == e) {
            int p = atomicAdd(&s_cnt, 1);
            s_idx[p] = tid;
        }
    }
    __syncthreads();
    int cnt = s_cnt;
    const float* eb = ent + (size_t)b*Ment*HID;
    float* out = g_ent_emb + ((size_t)(b*NE + e))*HID;
    for (int d = tid; d < HID; d += blockDim.x) {
        float r;
        if (cnt == 0) {
            r = 0.f;
        } else {
            float mx = -3.4e38f, s = 0.f;
            for (int i = 0; i < cnt; i++) {
                float v = eb[(size_t)s_idx[i]*HID + d];
                if (v > mx) { s = s*expf(mx - v) + 1.f; mx = v; }
                else        { s += expf(v - mx); }
            }
            r = mx + logf(s);
        }
        out[d] = r;
    }
}

// ---------------- K2: per-entity mean attention ----------------
__global__ void k_attn_mean(const float* __restrict__ attn,
                            const int* __restrict__ labels)
{
    int e = blockIdx.x, h = blockIdx.y, b = blockIdx.z;
    __shared__ int s_idx[Ment];
    __shared__ int s_cnt;
    int tid = threadIdx.x;
    if (tid == 0) s_cnt = 0;
    __syncthreads();
    if (tid < Ment) {
        if (labels[b*Ment + tid] == e) {
            int p = atomicAdd(&s_cnt, 1);
            s_idx[p] = tid;
        }
    }
    __syncthreads();
    int cnt = s_cnt;
    float inv = 1.f / (float)(cnt > 0 ? cnt : 1);
    const float* ab = attn + (((size_t)b*NH + h)*Ment)*Lseq;
    float* out = g_attn_mean + (((size_t)(b*NE + e))*NH + h)*Lseq;
    for (int l = tid; l < Lseq; l += blockDim.x) {
        float s = 0.f;
        for (int i = 0; i < cnt; i++) s += ab[(size_t)s_idx[i]*Lseq + l];
        out[l] = s * inv;
    }
}

// ---------------- K3: hta = normalize(mean_h(ha*ta)) ----------------
__global__ void k_hta(const int* __restrict__ hts)
{
    int r = blockIdx.x, b = blockIdx.y;
    int r2 = b*Rht + r;
    int e0 = hts[(size_t)r2*2 + 0];
    int e1 = hts[(size_t)r2*2 + 1];
    const float* a0 = g_attn_mean + ((size_t)(b*NE + e0))*NH*Lseq;
    const float* a1 = g_attn_mean + ((size_t)(b*NE + e1))*NH*Lseq;
    int tid = threadIdx.x;
    float v[4];
    float loc = 0.f;
#pragma unroll
    for (int i = 0; i < 4; i++) {
        int l = tid + i*256;
        float s = 0.f;
#pragma unroll
        for (int h = 0; h < NH; h++) s += a0[h*Lseq + l] * a1[h*Lseq + l];
        v[i] = s * (1.f/NH);
        loc += v[i];
    }
    __shared__ float red[256];
    red[tid] = loc;
    __syncthreads();
    for (int o = 128; o > 0; o >>= 1) {
        if (tid < o) red[tid] += red[tid + o];
        __syncthreads();
    }
    float scale = 1.f / (red[0] + 1e-5f);
    float* out = g_hta + (size_t)r2*Lseq;
#pragma unroll
    for (int i = 0; i < 4; i++) out[tid + i*256] = v[i] * scale;
}

// ---------------- K5: gather [hs|rel] and [ts|rel] ----------------
__global__ void k_gather(const int* __restrict__ hts)
{
    int r2 = blockIdx.x;
    int b = r2 / Rht;
    int e0 = hts[(size_t)r2*2 + 0];
    int e1 = hts[(size_t)r2*2 + 1];
    const float* emb0 = g_ent_emb + ((size_t)(b*NE + e0))*HID;
    const float* emb1 = g_ent_emb + ((size_t)(b*NE + e1))*HID;
    const float* rel  = g_rel + (size_t)r2*HID;
    float* xh = g_Xh + (size_t)r2*2*HID;
    float* xt = g_Xt + (size_t)r2*2*HID;
    for (int d = threadIdx.x; d < HID; d += blockDim.x) {
        float rv = rel[d];
        xh[d] = emb0[d];  xh[HID + d] = rv;
        xt[d] = emb1[d];  xt[HID + d] = rv;
    }
}

// ---------------- generic tiled SGEMM (row-major) ----------------
// C[M,N] = act(A[M,K] @ B[K,N] + bias), batched via blockIdx.z strides.
// ACT: 0 = none, 1 = tanh
template<int BM, int BN, int BK, int TM, int TN, int ACT>
__global__ __launch_bounds__((BM/TM)*(BN/TN))
void sgemm(const float* __restrict__ A, const float* __restrict__ B,
           const float* __restrict__ bias, float* __restrict__ C,
           int M, int N, int K, long sA, long sB, long sC)
{
    constexpr int THREADS = (BM/TM)*(BN/TN);
    A += (size_t)blockIdx.z * sA;
    B += (size_t)blockIdx.z * sB;
    C += (size_t)blockIdx.z * sC;
    __shared__ float As[BK][BM + 4];
    __shared__ float Bs[BK][BN];
    int tid = threadIdx.x;
    int tx = tid % (BN/TN);
    int ty = tid / (BN/TN);
    int row0 = blockIdx.y * BM, col0 = blockIdx.x * BN;
    float acc[TM][TN] = {};
    constexpr int AE = BM*BK/THREADS;
    constexpr int BE = BK*BN/THREADS;

    for (int k0 = 0; k0 < K; k0 += BK) {
#pragma unroll
        for (int u = 0; u < AE; u++) {
            int idx = tid + u*THREADS;
            int r = idx / BK, c = idx % BK;
            float v = 0.f;
            int gr = row0 + r;
            if (gr < M) v = A[(size_t)gr*K + k0 + c];
            As[c][r] = v;
        }
#pragma unroll
        for (int u = 0; u < BE; u++) {
            int idx = tid + u*THREADS;
            int r = idx / BN, c = idx % BN;
            float v = 0.f;
            int gc = col0 + c;
            if (gc < N) v = B[(size_t)(k0 + r)*N + gc];
            Bs[r][c] = v;
        }
        __syncthreads();
#pragma unroll
        for (int kk = 0; kk < BK; kk++) {
            float af[TM], bf[TN];
#pragma unroll
            for (int i = 0; i < TM; i += 4)
                *reinterpret_cast<float4*>(&af[i]) =
                    *reinterpret_cast<const float4*>(&As[kk][ty*TM + i]);
#pragma unroll
            for (int j = 0; j < TN; j += 4)
                *reinterpret_cast<float4*>(&bf[j]) =
                    *reinterpret_cast<const float4*>(&Bs[kk][tx*TN + j]);
#pragma unroll
            for (int i = 0; i < TM; i++)
#pragma unroll
                for (int j = 0; j < TN; j++)
                    acc[i][j] += af[i] * bf[j];
        }
        __syncthreads();
    }
#pragma unroll
    for (int i = 0; i < TM; i++) {
        int gr = row0 + ty*TM + i;
        if (gr >= M) continue;
#pragma unroll
        for (int j = 0; j < TN; j++) {
            int gc = col0 + tx*TN + j;
            if (gc >= N) continue;
            float v = acc[i][j];
            if (bias) v += bias[gc];
            if (ACT == 1) v = tanhf(v);
            C[(size_t)gr*N + gc] = v;
        }
    }
}

// ---------------- bilinear GEMM with implicit A ----------------
// embeds[r,o] = sum_{j,a,b} h[r,j*64+a]*t[r,j*64+b]*W[(j*4096+a*64+b), o] + bias[o]
// M=2048, N=768, K=49152. Tiles: 128x96x16, 256 threads, grid (8,16)=128 blocks.
__global__ __launch_bounds__(256, 1)
void k_bilinear(const float* __restrict__ h, const float* __restrict__ t,
                const float* __restrict__ W, const float* __restrict__ bias,
                float* __restrict__ out)
{
    __shared__ float Ts[128][65];   // t slice for current j (padded: bank-safe)
    __shared__ float As[16][132];   // generated A tile, transposed [k][m]
    __shared__ float Bs[16][96];
    int tid = threadIdx.x;
    int tx = tid % 16, ty = tid / 16;
    int row0 = blockIdx.y * 128, col0 = blockIdx.x * 96;
    float acc[8][6] = {};
    int ar = tid >> 1;          // row handled in A-gen (2 threads/row)
    int ac = (tid & 1) * 8;     // k-subrange within chunk

    for (int j = 0; j < NBLK; j++) {
        __syncthreads();
#pragma unroll
        for (int u = 0; u < 32; u++) {       // 128*64 / 256
            int idx = tid + u*256;
            int r = idx >> 6, c = idx & 63;
            Ts[r][c] = t[(size_t)(row0 + r)*EMB + j*64 + c];
        }
        __syncthreads();

        for (int kc = 0; kc < 4096; kc += 16) {
            int a   = kc >> 6;
            int bb0 = kc & 63;
            // h scalar for this row & (j,a): L1-resident (32KB slice, reused 256x)
            float hv = h[(size_t)(row0 + ar)*EMB + (j << 6) + a];
#pragma unroll
            for (int i = 0; i < 8; i++)
                As[ac + i][ar] = hv * Ts[ar][bb0 + ac + i];
            // load W tile (16 x 96), coalesced
            const float* Wb = W + ((size_t)(j*4096 + kc))*EMB + col0;
#pragma unroll
            for (int u = 0; u < 6; u++) {    // 16*96 / 256
                int idx = tid + u*256;
                int r = idx / 96, c = idx - r*96;
                Bs[r][c] = Wb[(size_t)r*EMB + c];
            }
            __syncthreads();
#pragma unroll
            for (int kk = 0; kk < 16; kk++) {
                float af[8], bf[6];
#pragma unroll
                for (int i = 0; i < 8; i += 4)
                    *reinterpret_cast<float4*>(&af[i]) =
                        *reinterpret_cast<const float4*>(&As[kk][ty*8 + i]);
#pragma unroll
                for (int jj = 0; jj < 6; jj++) bf[jj] = Bs[kk][tx*6 + jj];
#pragma unroll
                for (int i = 0; i < 8; i++)
#pragma unroll
                    for (int jj = 0; jj < 6; jj++)
                        acc[i][jj] += af[i] * bf[jj];
            }
            __syncthreads();
        }
    }
#pragma unroll
    for (int i = 0; i < 8; i++) {
        int gr = row0 + ty*8 + i;
#pragma unroll
        for (int jj = 0; jj < 6; jj++) {
            int gc = col0 + tx*6 + jj;
            out[(size_t)gr*EMB + gc] = acc[i][jj] + bias[gc];
        }
    }
}

// ---------------- launch ----------------
extern "C" void kernel_launch(void* const* d_in, const int* in_sizes, int n_in,
                              void* d_out, int out_size)
{
    const float* seq    = (const float*)d_in[0];
    const float* ent    = (const float*)d_in[1];
    const float* attn   = (const float*)d_in[2];
    const int*   labels = (const int*)  d_in[3];
    const int*   hts    = (const int*)  d_in[4];
    const float* W_head = (const float*)d_in[5];
    const float* b_head = (const float*)d_in[6];
    const float* W_tail = (const float*)d_in[7];
    const float* b_tail = (const float*)d_in[8];
    const float* W_bil  = (const float*)d_in[9];
    const float* b_bil  = (const float*)d_in[10];
    const float* W_cls  = (const float*)d_in[11];
    const float* b_cls  = (const float*)d_in[12];
    const float* W_proj = (const float*)d_in[13];
    const float* b_proj = (const float*)d_in[14];

    float* out      = (float*)d_out;
    float* out_cls  = out + (size_t)NROW*EMB;
    float* out_proj = out_cls + (size_t)NROW*NCLS;

    void *p_hta, *p_rel, *p_Xh, *p_Xt, *p_h, *p_t;
    cudaGetSymbolAddress(&p_hta, g_hta);
    cudaGetSymbolAddress(&p_rel, g_rel);
    cudaGetSymbolAddress(&p_Xh,  g_Xh);
    cudaGetSymbolAddress(&p_Xt,  g_Xt);
    cudaGetSymbolAddress(&p_h,   g_h);
    cudaGetSymbolAddress(&p_t,   g_t);

    // 1. entity logsumexp pooling
    k_ent_emb<<<dim3(NE, Bdoc), 256>>>(ent, labels);
    // 2. per-entity mean attention
    k_attn_mean<<<dim3(NE, NH, Bdoc), 256>>>(attn, labels);
    // 3. hta
    k_hta<<<dim3(Rht, Bdoc), 256>>>(hts);
    // 4. rel = hta @ seq   (batched over docs)
    sgemm<128,128,8,8,8,0><<<dim3(Lseq/128, Rht/128, Bdoc), 256>>>(
        (const float*)p_hta, seq, nullptr, (float*)p_rel,
        Rht, HID, Lseq, (long)Rht*Lseq, (long)Lseq*HID, (long)Rht*HID);
    // 5. gather X_head / X_tail
    k_gather<<<NROW, 256>>>(hts);
    // 6. h = tanh(Xh @ W_head + b), t = tanh(Xt @ W_tail + b)
    sgemm<128,64,8,8,4,1><<<dim3(EMB/64, NROW/128, 1), 256>>>(
        (const float*)p_Xh, W_head, b_head, (float*)p_h,
        NROW, EMB, 2*HID, 0, 0, 0);
    sgemm<128,64,8,8,4,1><<<dim3(EMB/64, NROW/128, 1), 256>>>(
        (const float*)p_Xt, W_tail, b_tail, (float*)p_t,
        NROW, EMB, 2*HID, 0, 0, 0);
    // 7. embeds = bilinear(h,t) @ W_bil + b_bil   -> d_out
    k_bilinear<<<dim3(EMB/96, NROW/128), 256>>>(
        (const float*)p_h, (const float*)p_t, W_bil, b_bil, out);
    // 8. class_logits = embeds @ W_cls + b_cls
    sgemm<128,64,8,8,4,0><<<dim3((NCLS+63)/64, NROW/128, 1), 256>>>(
        out, W_cls, b_cls, out_cls, NROW, NCLS, EMB, 0, 0, 0);
    // 9. proj_logits = tanh(embeds @ W_proj + b_proj)
    sgemm<128,64,8,8,4,1><<<dim3(NPROJ/64, NROW/128, 1), 256>>>(
        out, W_proj, b_proj, out_proj, NROW, NPROJ, EMB, 0, 0, 0);
}

// round 3
// speedup vs baseline: 2.3824x; 2.3824x over previous
#include <cuda_runtime.h>
#include <cuda_bf16.h>
#include <math.h>
#include <stdint.h>

// ---------------- problem constants ----------------
#define Bdoc 4
#define Lseq 1024
#define Ment 128
#define Rht  512
#define HID  1024
#define NH   16
#define NE   42
#define EMB  768
#define NBLK 12      // EMB/64
#define NCLS 97
#define NPROJ 128
#define NROW (Bdoc*Rht)   // 2048
#define KBIL (EMB*64)     // 49152
#define NCHUNK (NBLK*64)  // 768 chunks of K=64

// ---------------- scratch (__device__ globals) ------
__device__ float g_ent_emb[Bdoc*NE*HID];
__device__ float g_attn_mean[Bdoc*NE*NH*Lseq];
__device__ float g_hta[Bdoc*Rht*Lseq];
__device__ float g_rel[NROW*HID];
__device__ float g_Xh[NROW*2*HID];
__device__ float g_Xt[NROW*2*HID];
__device__ float g_h[NROW*EMB];
__device__ float g_t[NROW*EMB];
// W_bil split+transposed to bf16 hi/lo, [N=768][K=49152], packed bf16x2 along K
__device__ uint32_t g_WhiT32[(size_t)EMB*KBIL/2];   // 75.5 MB
__device__ uint32_t g_WloT32[(size_t)EMB*KBIL/2];   // 75.5 MB

// ---------------- K1: entity logsumexp pooling ----------------
__global__ void k_ent_emb(const float* __restrict__ ent,
                          const int* __restrict__ labels)
{
    int e = blockIdx.x, b = blockIdx.y;
    __shared__ int s_idx[Ment];
    __shared__ int s_cnt;
    int tid = threadIdx.x;
    if (tid == 0) s_cnt = 0;
    __syncthreads();
    if (tid < Ment) {
        if (labels[b*Ment + tid] == e) {
            int p = atomicAdd(&s_cnt, 1);
            s_idx[p] = tid;
        }
    }
    __syncthreads();
    int cnt = s_cnt;
    const float* eb = ent + (size_t)b*Ment*HID;
    float* out = g_ent_emb + ((size_t)(b*NE + e))*HID;
    for (int d = tid; d < HID; d += blockDim.x) {
        float r;
        if (cnt == 0) {
            r = 0.f;
        } else {
            float mx = -3.4e38f, s = 0.f;
            for (int i = 0; i < cnt; i++) {
                float v = eb[(size_t)s_idx[i]*HID + d];
                if (v > mx) { s = s*expf(mx - v) + 1.f; mx = v; }
                else        { s += expf(v - mx); }
            }
            r = mx + logf(s);
        }
        out[d] = r;
    }
}

// ---------------- K2: per-entity mean attention ----------------
__global__ void k_attn_mean(const float* __restrict__ attn,
                            const int* __restrict__ labels)
{
    int e = blockIdx.x, h = blockIdx.y, b = blockIdx.z;
    __shared__ int s_idx[Ment];
    __shared__ int s_cnt;
    int tid = threadIdx.x;
    if (tid == 0) s_cnt = 0;
    __syncthreads();
    if (tid < Ment) {
        if (labels[b*Ment + tid] == e) {
            int p = atomicAdd(&s_cnt, 1);
            s_idx[p] = tid;
        }
    }
    __syncthreads();
    int cnt = s_cnt;
    float inv = 1.f / (float)(cnt > 0 ? cnt : 1);
    const float* ab = attn + (((size_t)b*NH + h)*Ment)*Lseq;
    float* out = g_attn_mean + (((size_t)(b*NE + e))*NH + h)*Lseq;
    for (int l = tid; l < Lseq; l += blockDim.x) {
        float s = 0.f;
        for (int i = 0; i < cnt; i++) s += ab[(size_t)s_idx[i]*Lseq + l];
        out[l] = s * inv;
    }
}

// ---------------- K3: hta ----------------
__global__ void k_hta(const int* __restrict__ hts)
{
    int r = blockIdx.x, b = blockIdx.y;
    int r2 = b*Rht + r;
    int e0 = hts[(size_t)r2*2 + 0];
    int e1 = hts[(size_t)r2*2 + 1];
    const float* a0 = g_attn_mean + ((size_t)(b*NE + e0))*NH*Lseq;
    const float* a1 = g_attn_mean + ((size_t)(b*NE + e1))*NH*Lseq;
    int tid = threadIdx.x;
    float v[4];
    float loc = 0.f;
#pragma unroll
    for (int i = 0; i < 4; i++) {
        int l = tid + i*256;
        float s = 0.f;
#pragma unroll
        for (int h = 0; h < NH; h++) s += a0[h*Lseq + l] * a1[h*Lseq + l];
        v[i] = s * (1.f/NH);
        loc += v[i];
    }
    __shared__ float red[256];
    red[tid] = loc;
    __syncthreads();
    for (int o = 128; o > 0; o >>= 1) {
        if (tid < o) red[tid] += red[tid + o];
        __syncthreads();
    }
    float scale = 1.f / (red[0] + 1e-5f);
    float* out = g_hta + (size_t)r2*Lseq;
#pragma unroll
    for (int i = 0; i < 4; i++) out[tid + i*256] = v[i] * scale;
}

// ---------------- K5: gather ----------------
__global__ void k_gather(const int* __restrict__ hts)
{
    int r2 = blockIdx.x;
    int b = r2 / Rht;
    int e0 = hts[(size_t)r2*2 + 0];
    int e1 = hts[(size_t)r2*2 + 1];
    const float* emb0 = g_ent_emb + ((size_t)(b*NE + e0))*HID;
    const float* emb1 = g_ent_emb + ((size_t)(b*NE + e1))*HID;
    const float* rel  = g_rel + (size_t)r2*HID;
    float* xh = g_Xh + (size_t)r2*2*HID;
    float* xt = g_Xt + (size_t)r2*2*HID;
    for (int d = threadIdx.x; d < HID; d += blockDim.x) {
        float rv = rel[d];
        xh[d] = emb0[d];  xh[HID + d] = rv;
        xt[d] = emb1[d];  xt[HID + d] = rv;
    }
}

// ---------------- generic tiled SGEMM (row-major) ----------------
template<int BM, int BN, int BK, int TM, int TN, int ACT>
__global__ __launch_bounds__((BM/TM)*(BN/TN))
void sgemm(const float* __restrict__ A, const float* __restrict__ B,
           const float* __restrict__ bias, float* __restrict__ C,
           int M, int N, int K, long sA, long sB, long sC)
{
    constexpr int THREADS = (BM/TM)*(BN/TN);
    A += (size_t)blockIdx.z * sA;
    B += (size_t)blockIdx.z * sB;
    C += (size_t)blockIdx.z * sC;
    __shared__ float As[BK][BM + 4];
    __shared__ float Bs[BK][BN];
    int tid = threadIdx.x;
    int tx = tid % (BN/TN);
    int ty = tid / (BN/TN);
    int row0 = blockIdx.y * BM, col0 = blockIdx.x * BN;
    float acc[TM][TN] = {};
    constexpr int AE = BM*BK/THREADS;
    constexpr int BE = BK*BN/THREADS;

    for (int k0 = 0; k0 < K; k0 += BK) {
#pragma unroll
        for (int u = 0; u < AE; u++) {
            int idx = tid + u*THREADS;
            int r = idx / BK, c = idx % BK;
            float v = 0.f;
            int gr = row0 + r;
            if (gr < M) v = A[(size_t)gr*K + k0 + c];
            As[c][r] = v;
        }
#pragma unroll
        for (int u = 0; u < BE; u++) {
            int idx = tid + u*THREADS;
            int r = idx / BN, c = idx % BN;
            float v = 0.f;
            int gc = col0 + c;
            if (gc < N) v = B[(size_t)(k0 + r)*N + gc];
            Bs[r][c] = v;
        }
        __syncthreads();
#pragma unroll
        for (int kk = 0; kk < BK; kk++) {
            float af[TM], bf[TN];
#pragma unroll
            for (int i = 0; i < TM; i += 4)
                *reinterpret_cast<float4*>(&af[i]) =
                    *reinterpret_cast<const float4*>(&As[kk][ty*TM + i]);
#pragma unroll
            for (int j = 0; j < TN; j += 4)
                *reinterpret_cast<float4*>(&bf[j]) =
                    *reinterpret_cast<const float4*>(&Bs[kk][tx*TN + j]);
#pragma unroll
            for (int i = 0; i < TM; i++)
#pragma unroll
                for (int j = 0; j < TN; j++)
                    acc[i][j] += af[i] * bf[j];
        }
        __syncthreads();
    }
#pragma unroll
    for (int i = 0; i < TM; i++) {
        int gr = row0 + ty*TM + i;
        if (gr >= M) continue;
#pragma unroll
        for (int j = 0; j < TN; j++) {
            int gc = col0 + tx*TN + j;
            if (gc >= N) continue;
            float v = acc[i][j];
            if (bias) v += bias[gc];
            if (ACT == 1) v = tanhf(v);
            C[(size_t)gr*N + gc] = v;
        }
    }
}

// ---------------- W_bil split + transpose ----------------
// in:  W [KBIL, EMB] fp32 row-major
// out: g_WhiT32/g_WloT32 as bf16 [EMB, KBIL] row-major (packed pairs along K)
__global__ void k_wsplit(const float* __restrict__ W)
{
    __shared__ float s[64][65];
    int k0 = blockIdx.x*64, n0 = blockIdx.y*64;
    for (int idx = threadIdx.x; idx < 64*64; idx += 256) {
        int kk = idx >> 6, nn = idx & 63;
        s[kk][nn] = W[(size_t)(k0+kk)*EMB + n0+nn];
    }
    __syncthreads();
    for (int idx = threadIdx.x; idx < 64*32; idx += 256) {
        int nn = idx >> 5, p = idx & 31;
        float f0 = s[p*2+0][nn], f1 = s[p*2+1][nn];
        uint32_t hp;
        asm("cvt.rn.bf16x2.f32 %0, %1, %2;" : "=r"(hp) : "f"(f1), "f"(f0));
        float h0 = __uint_as_float(hp << 16);
        float h1 = __uint_as_float(hp & 0xffff0000u);
        float r0 = f0 - h0, r1 = f1 - h1;
        uint32_t lp;
        asm("cvt.rn.bf16x2.f32 %0, %1, %2;" : "=r"(lp) : "f"(r1), "f"(r0));
        size_t o = ((size_t)(n0+nn)*KBIL + k0)/2 + p;
        g_WhiT32[o] = hp;
        g_WloT32[o] = lp;
    }
}

// ---------------- mma.sync helpers (sm_80 baseline PTX; valid on compute_103) ----
__device__ __forceinline__ uint32_t smem_u32(const void* p) {
    uint32_t a;
    asm("{ .reg .u64 t; cvta.to.shared.u64 t, %1; cvt.u32.u64 %0, t; }"
        : "=r"(a) : "l"(p));
    return a;
}
#define SWZ(o) ((o) ^ ((((uint32_t)(o))>>3)&0x70))

#define MMA16816(d, a0,a1,a2,a3, b0,b1) \
    asm volatile("mma.sync.aligned.m16n8k16.row.col.f32.bf16.bf16.f32 " \
        "{%0,%1,%2,%3},{%4,%5,%6,%7},{%8,%9},{%0,%1,%2,%3};" \
        : "+f"((d)[0]), "+f"((d)[1]), "+f"((d)[2]), "+f"((d)[3]) \
        : "r"(a0), "r"(a1), "r"(a2), "r"(a3), "r"(b0), "r"(b1))

#define LDX4(r, addr) \
    asm volatile("ldmatrix.sync.aligned.m8n8.x4.shared.b16 {%0,%1,%2,%3},[%4];" \
        : "=r"((r)[0]), "=r"((r)[1]), "=r"((r)[2]), "=r"((r)[3]) : "r"(addr))

__device__ __forceinline__ uint32_t pack_bf2(float x, float y) {
    uint32_t r;  // low half = bf16(x), high half = bf16(y)
    asm("cvt.rn.bf16x2.f32 %0, %1, %2;" : "=r"(r) : "f"(y), "f"(x));
    return r;
}
__device__ __forceinline__ float lo_f(uint32_t u) { return __uint_as_float(u << 16); }
__device__ __forceinline__ float hi_f(uint32_t u) { return __uint_as_float(u & 0xffff0000u); }

// SMEM layout: B buffers [2 buf][hi 16KB | lo 16KB] = 64KB, then s_h, s_t
#define BIL_SH_OFF 65536
#define BIL_ST_OFF (65536 + 34816)
#define BIL_SMEM   (65536 + 2*34816)   // 135168

__device__ __forceinline__ void bil_load_B(uint32_t sb, int c, int col0, int tid)
{
    uint32_t dH = sb + (uint32_t)(c & 1)*32768u;
#pragma unroll
    for (int p = 0; p < 4; p++) {
        int idx = tid + p*256;
        int n = idx >> 3, seg = idx & 7;
        size_t go = (size_t)(col0 + n)*(KBIL/2) + (size_t)c*32 + seg*4;
        uint32_t off = SWZ((uint32_t)(n*128 + seg*16));
        asm volatile("cp.async.cg.shared.global [%0], [%1], 16;"
                     :: "r"(dH + off), "l"(g_WhiT32 + go));
        asm volatile("cp.async.cg.shared.global [%0], [%1], 16;"
                     :: "r"(dH + 16384u + off), "l"(g_WloT32 + go));
    }
}

// ---------------- bilinear GEMM via mma.sync bf16 (3x split) ----------------
// embeds[M=2048, N=768] = bl @ W_bil + b; bl[m, c*64+kb] = h[m,c]*t[m,kb'&blk]
// CTA tile 128x128, K loop over 768 chunks of 64. 256 threads, warps 4(M)x2(N).
__global__ void __launch_bounds__(256, 1)
k_bilinear_mma(const float* __restrict__ h, const float* __restrict__ t,
               const float* __restrict__ bias, float* __restrict__ out)
{
    extern __shared__ char smem[];
    uint32_t sb = smem_u32(smem);
    float* s_h = (float*)(smem + BIL_SH_OFF);   // [128][68]
    float* s_t = (float*)(smem + BIL_ST_OFF);   // [128][68]
    int tid = threadIdx.x, lid = tid & 31, wid = tid >> 5;
    int row0 = blockIdx.y * 128, col0 = blockIdx.x * 128;
    int wm = (wid >> 1) * 32;        // warp M offset (4 warps)
    int wn = (wid & 1) * 64;         // warp N offset (2 warps)

    float acc[2][8][4];
#pragma unroll
    for (int i = 0; i < 2; i++)
#pragma unroll
        for (int n = 0; n < 8; n++)
#pragma unroll
            for (int q = 0; q < 4; q++) acc[i][n][q] = 0.f;

    bil_load_B(sb, 0, col0, tid);
    asm volatile("cp.async.commit_group;");

#pragma unroll 1
    for (int c = 0; c < NCHUNK; ++c) {
        int j = c >> 6, a = c & 63, buf = c & 1;

        if (c + 1 < NCHUNK) bil_load_B(sb, c + 1, col0, tid);
        asm volatile("cp.async.commit_group;");
        asm volatile("cp.async.wait_group 1;");

        if (a == 0) {   // load h/t fp32 slices for this j-block
            for (int idx = tid; idx < 128*16; idx += 256) {
                int rr = idx >> 4, cc = (idx & 15) * 4;
                *(float4*)&s_h[rr*68 + cc] =
                    *(const float4*)&h[(size_t)(row0+rr)*EMB + j*64 + cc];
                *(float4*)&s_t[rr*68 + cc] =
                    *(const float4*)&t[(size_t)(row0+rr)*EMB + j*64 + cc];
            }
        }
        __syncthreads();

        uint32_t bbase = sb + (uint32_t)buf*32768u;
        // h scalars for this chunk (row depends on m-tile i)
        float h0[2], h1[2];
#pragma unroll
        for (int i = 0; i < 2; i++) {
            int r0 = wm + i*16 + (lid >> 2);
            h0[i] = s_h[r0*68 + a];
            h1[i] = s_h[(r0 + 8)*68 + a];
        }

        int msel = lid >> 3, r8 = lid & 7;
#pragma unroll
        for (int s = 0; s < 4; ++s) {
            // B fragments: 8 n-tiles x {b0,b1}, hi and lo
            uint32_t bh[16], bl[16];
#pragma unroll
            for (int pq = 0; pq < 4; ++pq) {
                uint32_t off = (uint32_t)((wn + (pq*2 + (msel >> 1))*8 + r8)*128
                                          + s*32 + (msel & 1)*16);
                uint32_t so = SWZ(off);
                LDX4(&bh[pq*4], bbase + so);
                LDX4(&bl[pq*4], bbase + 16384u + so);
            }
#pragma unroll
            for (int i = 0; i < 2; ++i) {
                int rb = (wm + i*16 + (lid >> 2))*68;
                int cc = s*16 + (lid & 3)*2;
                float2 ta = *(float2*)&s_t[rb + cc];
                float2 tb = *(float2*)&s_t[rb + cc + 8];
                float2 tc = *(float2*)&s_t[rb + 8*68 + cc];
                float2 td = *(float2*)&s_t[rb + 8*68 + cc + 8];
                float p00 = h0[i]*ta.x, p01 = h0[i]*ta.y;
                float p10 = h1[i]*tc.x, p11 = h1[i]*tc.y;
                float p02 = h0[i]*tb.x, p03 = h0[i]*tb.y;
                float p12 = h1[i]*td.x, p13 = h1[i]*td.y;
                uint32_t ah[4], al[4];
                ah[0] = pack_bf2(p00, p01);
                ah[1] = pack_bf2(p10, p11);
                ah[2] = pack_bf2(p02, p03);
                ah[3] = pack_bf2(p12, p13);
                al[0] = pack_bf2(p00 - lo_f(ah[0]), p01 - hi_f(ah[0]));
                al[1] = pack_bf2(p10 - lo_f(ah[1]), p11 - hi_f(ah[1]));
                al[2] = pack_bf2(p02 - lo_f(ah[2]), p03 - hi_f(ah[2]));
                al[3] = pack_bf2(p12 - lo_f(ah[3]), p13 - hi_f(ah[3]));
#pragma unroll
                for (int n = 0; n < 8; ++n) {
                    MMA16816(acc[i][n], ah[0],ah[1],ah[2],ah[3], bh[n*2], bh[n*2+1]);
                    MMA16816(acc[i][n], ah[0],ah[1],ah[2],ah[3], bl[n*2], bl[n*2+1]);
                    MMA16816(acc[i][n], al[0],al[1],al[2],al[3], bh[n*2], bh[n*2+1]);
                }
            }
        }
        __syncthreads();   // compute done before next prefetch overwrites buf
    }

    // epilogue
#pragma unroll
    for (int i = 0; i < 2; ++i) {
        int gr = row0 + wm + i*16 + (lid >> 2);
#pragma unroll
        for (int n = 0; n < 8; ++n) {
            int gc = col0 + wn + n*8 + (lid & 3)*2;
            float2 v0 = make_float2(acc[i][n][0] + bias[gc],
                                    acc[i][n][1] + bias[gc+1]);
            float2 v1 = make_float2(acc[i][n][2] + bias[gc],
                                    acc[i][n][3] + bias[gc+1]);
            *(float2*)&out[(size_t)gr*EMB + gc]       = v0;
            *(float2*)&out[(size_t)(gr+8)*EMB + gc]   = v1;
        }
    }
}

// ---------------- launch ----------------
extern "C" void kernel_launch(void* const* d_in, const int* in_sizes, int n_in,
                              void* d_out, int out_size)
{
    const float* seq    = (const float*)d_in[0];
    const float* ent    = (const float*)d_in[1];
    const float* attn   = (const float*)d_in[2];
    const int*   labels = (const int*)  d_in[3];
    const int*   hts    = (const int*)  d_in[4];
    const float* W_head = (const float*)d_in[5];
    const float* b_head = (const float*)d_in[6];
    const float* W_tail = (const float*)d_in[7];
    const float* b_tail = (const float*)d_in[8];
    const float* W_bil  = (const float*)d_in[9];
    const float* b_bil  = (const float*)d_in[10];
    const float* W_cls  = (const float*)d_in[11];
    const float* b_cls  = (const float*)d_in[12];
    const float* W_proj = (const float*)d_in[13];
    const float* b_proj = (const float*)d_in[14];

    float* out      = (float*)d_out;
    float* out_cls  = out + (size_t)NROW*EMB;
    float* out_proj = out_cls + (size_t)NROW*NCLS;

    void *p_hta, *p_rel, *p_Xh, *p_Xt, *p_h, *p_t;
    cudaGetSymbolAddress(&p_hta, g_hta);
    cudaGetSymbolAddress(&p_rel, g_rel);
    cudaGetSymbolAddress(&p_Xh,  g_Xh);
    cudaGetSymbolAddress(&p_Xt,  g_Xt);
    cudaGetSymbolAddress(&p_h,   g_h);
    cudaGetSymbolAddress(&p_t,   g_t);

    cudaFuncSetAttribute(k_bilinear_mma,
                         cudaFuncAttributeMaxDynamicSharedMemorySize, BIL_SMEM);

    // 0. split + transpose W_bil to bf16 hi/lo
    k_wsplit<<<dim3(KBIL/64, EMB/64), 256>>>(W_bil);
    // 1. entity logsumexp pooling
    k_ent_emb<<<dim3(NE, Bdoc), 256>>>(ent, labels);
    // 2. per-entity mean attention
    k_attn_mean<<<dim3(NE, NH, Bdoc), 256>>>(attn, labels);
    // 3. hta
    k_hta<<<dim3(Rht, Bdoc), 256>>>(hts);
    // 4. rel = hta @ seq
    sgemm<128,128,8,8,8,0><<<dim3(Lseq/128, Rht/128, Bdoc), 256>>>(
        (const float*)p_hta, seq, nullptr, (float*)p_rel,
        Rht, HID, Lseq, (long)Rht*Lseq, (long)Lseq*HID, (long)Rht*HID);
    // 5. gather
    k_gather<<<NROW, 256>>>(hts);
    // 6. h / t projections
    sgemm<128,64,8,8,4,1><<<dim3(EMB/64, NROW/128, 1), 256>>>(
        (const float*)p_Xh, W_head, b_head, (float*)p_h,
        NROW, EMB, 2*HID, 0, 0, 0);
    sgemm<128,64,8,8,4,1><<<dim3(EMB/64, NROW/128, 1), 256>>>(
        (const float*)p_Xt, W_tail, b_tail, (float*)p_t,
        NROW, EMB, 2*HID, 0, 0, 0);
    // 7. bilinear on tensor cores (mma.sync bf16 3x split) -> d_out
    k_bilinear_mma<<<dim3(EMB/128, NROW/128), 256, BIL_SMEM>>>(
        (const float*)p_h, (const float*)p_t, b_bil, out);
    // 8. class logits
    sgemm<128,64,8,8,4,0><<<dim3((NCLS+63)/64, NROW/128, 1), 256>>>(
        out, W_cls, b_cls, out_cls, NROW, NCLS, EMB, 0, 0, 0);
    // 9. proj logits
    sgemm<128,64,8,8,4,1><<<dim3(NPROJ/64, NROW/128, 1), 256>>>(
        out, W_proj, b_proj, out_proj, NROW, NPROJ, EMB, 0, 0, 0);
}

// round 4
// speedup vs baseline: 3.3542x; 1.4079x over previous
#include <cuda_runtime.h>
#include <cuda_bf16.h>
#include <math.h>
#include <stdint.h>

// ---------------- problem constants ----------------
#define Bdoc 4
#define Lseq 1024
#define Ment 128
#define Rht  512
#define HID  1024
#define NH   16
#define NE   42
#define EMB  768
#define NBLK 12
#define NCLS 97
#define NPROJ 128
#define NROW (Bdoc*Rht)   // 2048
#define KBIL (EMB*64)     // 49152
#define NCHUNK (NBLK*64)  // 768

// ---------------- scratch ----------------
__device__ float g_ent_emb[Bdoc*NE*HID];
__device__ float g_attn_mean[Bdoc*NE*NH*Lseq];
__device__ float g_rel[NROW*HID];
__device__ float g_ht[2*NROW*EMB];                    // h then t (fp32)
__device__ float g_bias_ht[2*EMB];
// packed bf16x2 operands
__device__ uint32_t g_WbilHi[(size_t)EMB*KBIL/2];     // 75.5 MB
__device__ uint32_t g_WbilLo[(size_t)EMB*KBIL/2];
__device__ uint32_t g_WhtHi[2*EMB*HID];               // [2][768][1024]
__device__ uint32_t g_WhtLo[2*EMB*HID];
__device__ uint32_t g_seqTHi[Bdoc*HID*Lseq/2];        // [4][1024][512]
__device__ uint32_t g_seqTLo[Bdoc*HID*Lseq/2];
__device__ uint32_t g_htaHi[NROW*Lseq/2];             // [2048][512]
__device__ uint32_t g_htaLo[NROW*Lseq/2];
__device__ uint32_t g_XHi[2*NROW*HID];                // [2][2048][1024]
__device__ uint32_t g_XLo[2*NROW*HID];

// ---------------- helpers ----------------
__device__ __forceinline__ uint32_t smem_u32(const void* p) {
    uint32_t a;
    asm("{ .reg .u64 t; cvta.to.shared.u64 t, %1; cvt.u32.u64 %0, t; }"
        : "=r"(a) : "l"(p));
    return a;
}
#define SWZ(o) ((o) ^ ((((uint32_t)(o))>>3)&0x70))

#define MMA16816(d, a0,a1,a2,a3, b0,b1) \
    asm volatile("mma.sync.aligned.m16n8k16.row.col.f32.bf16.bf16.f32 " \
        "{%0,%1,%2,%3},{%4,%5,%6,%7},{%8,%9},{%0,%1,%2,%3};" \
        : "+f"((d)[0]), "+f"((d)[1]), "+f"((d)[2]), "+f"((d)[3]) \
        : "r"(a0), "r"(a1), "r"(a2), "r"(a3), "r"(b0), "r"(b1))

#define LDX4(r, addr) \
    asm volatile("ldmatrix.sync.aligned.m8n8.x4.shared.b16 {%0,%1,%2,%3},[%4];" \
        : "=r"((r)[0]), "=r"((r)[1]), "=r"((r)[2]), "=r"((r)[3]) : "r"(addr))

#define CPA16(dst, src) \
    asm volatile("cp.async.cg.shared.global [%0], [%1], 16;" :: "r"(dst), "l"(src))

__device__ __forceinline__ uint32_t pack_bf2(float x, float y) {
    uint32_t r;
    asm("cvt.rn.bf16x2.f32 %0, %1, %2;" : "=r"(r) : "f"(y), "f"(x));
    return r;
}
__device__ __forceinline__ float lo_f(uint32_t u) { return __uint_as_float(u << 16); }
__device__ __forceinline__ float hi_f(uint32_t u) { return __uint_as_float(u & 0xffff0000u); }
__device__ __forceinline__ void split2(float x, float y, uint32_t& hp, uint32_t& lp) {
    hp = pack_bf2(x, y);
    lp = pack_bf2(x - lo_f(hp), y - hi_f(hp));
}

// ---------------- K1: entity logsumexp pooling ----------------
__global__ void k_ent_emb(const float* __restrict__ ent,
                          const int* __restrict__ labels)
{
    int e = blockIdx.x, b = blockIdx.y;
    __shared__ int s_idx[Ment];
    __shared__ int s_cnt;
    int tid = threadIdx.x;
    if (tid == 0) {                       // deterministic ascending scan
        int c = 0;
        for (int i = 0; i < Ment; i++)
            if (labels[b*Ment + i] == e) s_idx[c++] = i;
        s_cnt = c;
    }
    __syncthreads();
    int cnt = s_cnt;
    const float* eb = ent + (size_t)b*Ment*HID;
    float* out = g_ent_emb + ((size_t)(b*NE + e))*HID;
    for (int d = tid; d < HID; d += blockDim.x) {
        float r;
        if (cnt == 0) {
            r = 0.f;
        } else {
            float mx = -3.4e38f, s = 0.f;
            for (int i = 0; i < cnt; i++) {
                float v = eb[(size_t)s_idx[i]*HID + d];
                if (v > mx) { s = s*expf(mx - v) + 1.f; mx = v; }
                else        { s += expf(v - mx); }
            }
            r = mx + logf(s);
        }
        out[d] = r;
    }
}

// ---------------- K2: per-entity mean attention ----------------
__global__ void k_attn_mean(const float* __restrict__ attn,
                            const int* __restrict__ labels)
{
    int e = blockIdx.x, h = blockIdx.y, b = blockIdx.z;
    __shared__ int s_idx[Ment];
    __shared__ int s_cnt;
    int tid = threadIdx.x;
    if (tid == 0) {
        int c = 0;
        for (int i = 0; i < Ment; i++)
            if (labels[b*Ment + i] == e) s_idx[c++] = i;
        s_cnt = c;
    }
    __syncthreads();
    int cnt = s_cnt;
    float inv = 1.f / (float)(cnt > 0 ? cnt : 1);
    const float* ab = attn + (((size_t)b*NH + h)*Ment)*Lseq;
    float* out = g_attn_mean + (((size_t)(b*NE + e))*NH + h)*Lseq;
    for (int l = tid; l < Lseq; l += blockDim.x) {
        float s = 0.f;
        for (int i = 0; i < cnt; i++) s += ab[(size_t)s_idx[i]*Lseq + l];
        out[l] = s * inv;
    }
}

// ---------------- K3: hta -> split bf16 ----------------
__global__ void k_hta(const int* __restrict__ hts)
{
    int r = blockIdx.x, b = blockIdx.y;
    int r2 = b*Rht + r;
    int e0 = hts[(size_t)r2*2 + 0];
    int e1 = hts[(size_t)r2*2 + 1];
    const float* a0 = g_attn_mean + ((size_t)(b*NE + e0))*NH*Lseq;
    const float* a1 = g_attn_mean + ((size_t)(b*NE + e1))*NH*Lseq;
    int tid = threadIdx.x;
    int l0 = tid*4;
    float4 acc = make_float4(0.f,0.f,0.f,0.f);
#pragma unroll
    for (int h = 0; h < NH; h++) {
        float4 x = *(const float4*)&a0[h*Lseq + l0];
        float4 y = *(const float4*)&a1[h*Lseq + l0];
        acc.x += x.x*y.x; acc.y += x.y*y.y;
        acc.z += x.z*y.z; acc.w += x.w*y.w;
    }
    acc.x *= (1.f/NH); acc.y *= (1.f/NH); acc.z *= (1.f/NH); acc.w *= (1.f/NH);
    __shared__ float red[256];
    red[tid] = acc.x + acc.y + acc.z + acc.w;
    __syncthreads();
    for (int o = 128; o > 0; o >>= 1) {
        if (tid < o) red[tid] += red[tid + o];
        __syncthreads();
    }
    float sc = 1.f / (red[0] + 1e-5f);
    uint32_t h0, l0p, h1, l1p;
    split2(acc.x*sc, acc.y*sc, h0, l0p);
    split2(acc.z*sc, acc.w*sc, h1, l1p);
    size_t o = (size_t)r2*(Lseq/2) + tid*2;
    g_htaHi[o] = h0;  g_htaHi[o+1] = h1;
    g_htaLo[o] = l0p; g_htaLo[o+1] = l1p;
}

// ---------------- K5: gather -> split bf16 X ----------------
__global__ void k_gather(const int* __restrict__ hts)
{
    int r2 = blockIdx.x;
    int b = r2 / Rht;
    int e0 = hts[(size_t)r2*2 + 0];
    int e1 = hts[(size_t)r2*2 + 1];
    const float* emb0 = g_ent_emb + ((size_t)(b*NE + e0))*HID;
    const float* emb1 = g_ent_emb + ((size_t)(b*NE + e1))*HID;
    const float* rel  = g_rel + (size_t)r2*HID;
    for (int u = threadIdx.x; u < HID; u += 256) {
        uint32_t hp, lp;
        if (u < HID/2) {
            float2 v0 = *(const float2*)&emb0[2*u];
            split2(v0.x, v0.y, hp, lp);
            g_XHi[(size_t)r2*HID + u] = hp;
            g_XLo[(size_t)r2*HID + u] = lp;
            float2 v1 = *(const float2*)&emb1[2*u];
            split2(v1.x, v1.y, hp, lp);
            g_XHi[(size_t)(NROW + r2)*HID + u] = hp;
            g_XLo[(size_t)(NROW + r2)*HID + u] = lp;
        } else {
            float2 rv = *(const float2*)&rel[2*u - HID];
            split2(rv.x, rv.y, hp, lp);
            g_XHi[(size_t)r2*HID + u] = hp;
            g_XLo[(size_t)r2*HID + u] = lp;
            g_XHi[(size_t)(NROW + r2)*HID + u] = hp;
            g_XLo[(size_t)(NROW + r2)*HID + u] = lp;
        }
    }
}

// ---------------- split + transpose: [z][K][N] f32 -> [z][N][K/2] bf16x2 ----
__global__ void k_splitT(const float* __restrict__ in,
                         uint32_t* __restrict__ outHi, uint32_t* __restrict__ outLo,
                         int K, int N, long sIn, long sOut)
{
    __shared__ float s[64][65];
    in    += (size_t)blockIdx.z * sIn;
    outHi += (size_t)blockIdx.z * sOut;
    outLo += (size_t)blockIdx.z * sOut;
    int k0 = blockIdx.x*64, n0 = blockIdx.y*64;
    for (int idx = threadIdx.x; idx < 64*64; idx += 256) {
        int kk = idx >> 6, nn = idx & 63;
        s[kk][nn] = in[(size_t)(k0+kk)*N + n0+nn];
    }
    __syncthreads();
    int K2 = K >> 1;
    for (int idx = threadIdx.x; idx < 64*32; idx += 256) {
        int nn = idx >> 5, p = idx & 31;
        uint32_t hp, lp;
        split2(s[p*2][nn], s[p*2+1][nn], hp, lp);
        size_t o = (size_t)(n0+nn)*K2 + k0/2 + p;
        outHi[o] = hp;
        outLo[o] = lp;
    }
}

__global__ void k_bias2(const float* __restrict__ b0, const float* __restrict__ b1)
{
    int i = threadIdx.x + blockIdx.x*256;
    if (i < EMB) { g_bias_ht[i] = b0[i]; g_bias_ht[EMB+i] = b1[i]; }
}

// ---------------- generic 3-split bf16 mma GEMM ----------------
// C[z][M][N] = act(A[z] @ B[z]^T + bias[z]); A packed [M][K/2], B packed [N][K/2]
// CTA 128x128, chunk K=64, 256 threads, warps 4(M)x2(N).
template<int ACT>
__global__ void __launch_bounds__(256, 1)
k_gemm_split(const uint32_t* __restrict__ Ahi, const uint32_t* __restrict__ Alo,
             const uint32_t* __restrict__ Bhi, const uint32_t* __restrict__ Blo,
             const float* __restrict__ bias, float* __restrict__ C,
             int K, int N, long sA, long sB, long sC)
{
    extern __shared__ char smem[];   // [2][Ahi 16K|Alo 16K|Bhi 16K|Blo 16K] = 128KB
    uint32_t sb = smem_u32(smem);
    int tid = threadIdx.x, lid = tid & 31, wid = tid >> 5;
    int row0 = blockIdx.y*128, col0 = blockIdx.x*128;
    Ahi += (size_t)blockIdx.z * sA;  Alo += (size_t)blockIdx.z * sA;
    Bhi += (size_t)blockIdx.z * sB;  Blo += (size_t)blockIdx.z * sB;
    C   += (size_t)blockIdx.z * sC;
    const float* bz = bias ? bias + (size_t)blockIdx.z * N : nullptr;
    int K2 = K >> 1, nchunk = K >> 6;
    int wm = (wid >> 1)*32, wn = (wid & 1)*64;
    int msel = lid >> 3, r8 = lid & 7;

    float acc[2][8][4];
#pragma unroll
    for (int i = 0; i < 2; i++)
#pragma unroll
        for (int n = 0; n < 8; n++)
#pragma unroll
            for (int q = 0; q < 4; q++) acc[i][n][q] = 0.f;

#define GLOAD(c) { \
    uint32_t base = sb + (uint32_t)((c)&1)*65536u; \
    _Pragma("unroll") \
    for (int p = 0; p < 4; p++) { \
        int idx = tid + p*256; int r = idx >> 3, seg = idx & 7; \
        uint32_t off = SWZ((uint32_t)(r*128 + seg*16)); \
        size_t goA = (size_t)(row0+r)*K2 + (size_t)(c)*32 + seg*4; \
        size_t goB = (size_t)(col0+r)*K2 + (size_t)(c)*32 + seg*4; \
        CPA16(base + off,          Ahi + goA); \
        CPA16(base + 16384u + off, Alo + goA); \
        CPA16(base + 32768u + off, Bhi + goB); \
        CPA16(base + 49152u + off, Blo + goB); \
    } }

    GLOAD(0);
    asm volatile("cp.async.commit_group;");

#pragma unroll 1
    for (int c = 0; c < nchunk; ++c) {
        if (c + 1 < nchunk) GLOAD(c + 1);
        asm volatile("cp.async.commit_group;");
        asm volatile("cp.async.wait_group 1;");
        __syncthreads();

        uint32_t abase = sb + (uint32_t)(c & 1)*65536u;
        uint32_t bbase = abase + 32768u;
#pragma unroll
        for (int s = 0; s < 4; ++s) {
            uint32_t ah[2][4], al[2][4];
#pragma unroll
            for (int i = 0; i < 2; ++i) {
                uint32_t off = SWZ((uint32_t)((wm + i*16 + (lid & 15))*128
                                              + s*32 + (lid >> 4)*16));
                LDX4(ah[i], abase + off);
                LDX4(al[i], abase + 16384u + off);
            }
            uint32_t bh[16], bl[16];
#pragma unroll
            for (int pq = 0; pq < 4; ++pq) {
                uint32_t off = SWZ((uint32_t)((wn + (pq*2 + (msel >> 1))*8 + r8)*128
                                              + s*32 + (msel & 1)*16));
                LDX4(&bh[pq*4], bbase + off);
                LDX4(&bl[pq*4], bbase + 16384u + off);
            }
#pragma unroll
            for (int i = 0; i < 2; ++i)
#pragma unroll
                for (int n = 0; n < 8; ++n) {
                    MMA16816(acc[i][n], ah[i][0],ah[i][1],ah[i][2],ah[i][3], bh[n*2], bh[n*2+1]);
                    MMA16816(acc[i][n], ah[i][0],ah[i][1],ah[i][2],ah[i][3], bl[n*2], bl[n*2+1]);
                    MMA16816(acc[i][n], al[i][0],al[i][1],al[i][2],al[i][3], bh[n*2], bh[n*2+1]);
                }
        }
        __syncthreads();
    }
#undef GLOAD

#pragma unroll
    for (int i = 0; i < 2; ++i) {
        int gr = row0 + wm + i*16 + (lid >> 2);
#pragma unroll
        for (int n = 0; n < 8; ++n) {
            int gc = col0 + wn + n*8 + (lid & 3)*2;
            float b0v = bz ? bz[gc] : 0.f, b1v = bz ? bz[gc+1] : 0.f;
            float v0 = acc[i][n][0] + b0v, v1 = acc[i][n][1] + b1v;
            float v2 = acc[i][n][2] + b0v, v3 = acc[i][n][3] + b1v;
            if (ACT == 1) { v0 = tanhf(v0); v1 = tanhf(v1); v2 = tanhf(v2); v3 = tanhf(v3); }
            *(float2*)&C[(size_t)gr*N + gc]     = make_float2(v0, v1);
            *(float2*)&C[(size_t)(gr+8)*N + gc] = make_float2(v2, v3);
        }
    }
}

// ---------------- fp32 SIMT sgemm (small tails: cls/proj) ----------------
template<int BM, int BN, int BK, int TM, int TN, int ACT>
__global__ __launch_bounds__((BM/TM)*(BN/TN))
void sgemm(const float* __restrict__ A, const float* __restrict__ B,
           const float* __restrict__ bias, float* __restrict__ C,
           int M, int N, int K)
{
    constexpr int THREADS = (BM/TM)*(BN/TN);
    __shared__ float As[BK][BM + 4];
    __shared__ float Bs[BK][BN];
    int tid = threadIdx.x;
    int tx = tid % (BN/TN);
    int ty = tid / (BN/TN);
    int row0 = blockIdx.y * BM, col0 = blockIdx.x * BN;
    float acc[TM][TN] = {};
    constexpr int AE = BM*BK/THREADS;
    constexpr int BE = BK*BN/THREADS;

    for (int k0 = 0; k0 < K; k0 += BK) {
#pragma unroll
        for (int u = 0; u < AE; u++) {
            int idx = tid + u*THREADS;
            int r = idx / BK, c = idx % BK;
            float v = 0.f;
            int gr = row0 + r;
            if (gr < M) v = A[(size_t)gr*K + k0 + c];
            As[c][r] = v;
        }
#pragma unroll
        for (int u = 0; u < BE; u++) {
            int idx = tid + u*THREADS;
            int r = idx / BN, c = idx % BN;
            float v = 0.f;
            int gc = col0 + c;
            if (gc < N) v = B[(size_t)(k0 + r)*N + gc];
            Bs[r][c] = v;
        }
        __syncthreads();
#pragma unroll
        for (int kk = 0; kk < BK; kk++) {
            float af[TM], bf[TN];
#pragma unroll
            for (int i = 0; i < TM; i += 4)
                *reinterpret_cast<float4*>(&af[i]) =
                    *reinterpret_cast<const float4*>(&As[kk][ty*TM + i]);
#pragma unroll
            for (int j = 0; j < TN; j += 4)
                *reinterpret_cast<float4*>(&bf[j]) =
                    *reinterpret_cast<const float4*>(&Bs[kk][tx*TN + j]);
#pragma unroll
            for (int i = 0; i < TM; i++)
#pragma unroll
                for (int j = 0; j < TN; j++)
                    acc[i][j] += af[i] * bf[j];
        }
        __syncthreads();
    }
#pragma unroll
    for (int i = 0; i < TM; i++) {
        int gr = row0 + ty*TM + i;
        if (gr >= M) continue;
#pragma unroll
        for (int j = 0; j < TN; j++) {
            int gc = col0 + tx*TN + j;
            if (gc >= N) continue;
            float v = acc[i][j];
            if (bias) v += bias[gc];
            if (ACT == 1) v = tanhf(v);
            C[(size_t)gr*N + gc] = v;
        }
    }
}

// ---------------- bilinear GEMM via mma.sync (3x split, N-tile 96) ----------
#define BIL_SH_OFF 49152
#define BIL_ST_OFF (49152 + 34816)
#define BIL_SMEM   (49152 + 2*34816)   // 118784

__device__ __forceinline__ void bil_load_B(uint32_t sb, int c, int col0, int tid)
{
    uint32_t dH = sb + (uint32_t)(c & 1)*24576u;
#pragma unroll
    for (int p = 0; p < 3; p++) {
        int idx = tid + p*256;
        int n = idx >> 3, seg = idx & 7;
        size_t go = (size_t)(col0 + n)*(KBIL/2) + (size_t)c*32 + seg*4;
        uint32_t off = SWZ((uint32_t)(n*128 + seg*16));
        CPA16(dH + off,           g_WbilHi + go);
        CPA16(dH + 12288u + off,  g_WbilLo + go);
    }
}

__global__ void __launch_bounds__(256, 1)
k_bilinear_mma(const float* __restrict__ h, const float* __restrict__ t,
               const float* __restrict__ bias, float* __restrict__ out)
{
    extern __shared__ char smem[];
    uint32_t sb = smem_u32(smem);
    float* s_h = (float*)(smem + BIL_SH_OFF);   // [128][68]
    float* s_t = (float*)(smem + BIL_ST_OFF);   // [128][68]
    int tid = threadIdx.x, lid = tid & 31, wid = tid >> 5;
    int row0 = blockIdx.y * 128, col0 = blockIdx.x * 96;
    int wm = (wid >> 1) * 32;        // 4 warps in M
    int wn = (wid & 1) * 48;         // 2 warps in N (96/2)

    float acc[2][6][4];
#pragma unroll
    for (int i = 0; i < 2; i++)
#pragma unroll
        for (int n = 0; n < 6; n++)
#pragma unroll
            for (int q = 0; q < 4; q++) acc[i][n][q] = 0.f;

    bil_load_B(sb, 0, col0, tid);
    asm volatile("cp.async.commit_group;");

#pragma unroll 1
    for (int c = 0; c < NCHUNK; ++c) {
        int j = c >> 6, a = c & 63, buf = c & 1;

        if (c + 1 < NCHUNK) bil_load_B(sb, c + 1, col0, tid);
        asm volatile("cp.async.commit_group;");
        asm volatile("cp.async.wait_group 1;");

        if (a == 0) {
            for (int idx = tid; idx < 128*16; idx += 256) {
                int rr = idx >> 4, cc = (idx & 15) * 4;
                *(float4*)&s_h[rr*68 + cc] =
                    *(const float4*)&h[(size_t)(row0+rr)*EMB + j*64 + cc];
                *(float4*)&s_t[rr*68 + cc] =
                    *(const float4*)&t[(size_t)(row0+rr)*EMB + j*64 + cc];
            }
        }
        __syncthreads();

        uint32_t bbase = sb + (uint32_t)buf*24576u;
        float h0[2], h1[2];
#pragma unroll
        for (int i = 0; i < 2; i++) {
            int r0 = wm + i*16 + (lid >> 2);
            h0[i] = s_h[r0*68 + a];
            h1[i] = s_h[(r0 + 8)*68 + a];
        }

        int msel = lid >> 3, r8 = lid & 7;
#pragma unroll
        for (int s = 0; s < 4; ++s) {
            uint32_t bh[12], bl[12];
#pragma unroll
            for (int pq = 0; pq < 3; ++pq) {
                uint32_t off = SWZ((uint32_t)((wn + (pq*2 + (msel >> 1))*8 + r8)*128
                                              + s*32 + (msel & 1)*16));
                LDX4(&bh[pq*4], bbase + off);
                LDX4(&bl[pq*4], bbase + 12288u + off);
            }
#pragma unroll
            for (int i = 0; i < 2; ++i) {
                int rb = (wm + i*16 + (lid >> 2))*68;
                int cc = s*16 + (lid & 3)*2;
                float2 ta = *(float2*)&s_t[rb + cc];
                float2 tb = *(float2*)&s_t[rb + cc + 8];
                float2 tc = *(float2*)&s_t[rb + 8*68 + cc];
                float2 td = *(float2*)&s_t[rb + 8*68 + cc + 8];
                uint32_t ah[4], al[4];
                split2(h0[i]*ta.x, h0[i]*ta.y, ah[0], al[0]);
                split2(h1[i]*tc.x, h1[i]*tc.y, ah[1], al[1]);
                split2(h0[i]*tb.x, h0[i]*tb.y, ah[2], al[2]);
                split2(h1[i]*td.x, h1[i]*td.y, ah[3], al[3]);
#pragma unroll
                for (int n = 0; n < 6; ++n) {
                    MMA16816(acc[i][n], ah[0],ah[1],ah[2],ah[3], bh[n*2], bh[n*2+1]);
                    MMA16816(acc[i][n], ah[0],ah[1],ah[2],ah[3], bl[n*2], bl[n*2+1]);
                    MMA16816(acc[i][n], al[0],al[1],al[2],al[3], bh[n*2], bh[n*2+1]);
                }
            }
        }
        __syncthreads();
    }

#pragma unroll
    for (int i = 0; i < 2; ++i) {
        int gr = row0 + wm + i*16 + (lid >> 2);
#pragma unroll
        for (int n = 0; n < 6; ++n) {
            int gc = col0 + wn + n*8 + (lid & 3)*2;
            float2 v0 = make_float2(acc[i][n][0] + bias[gc],
                                    acc[i][n][1] + bias[gc+1]);
            float2 v1 = make_float2(acc[i][n][2] + bias[gc],
                                    acc[i][n][3] + bias[gc+1]);
            *(float2*)&out[(size_t)gr*EMB + gc]     = v0;
            *(float2*)&out[(size_t)(gr+8)*EMB + gc] = v1;
        }
    }
}

// ---------------- launch ----------------
extern "C" void kernel_launch(void* const* d_in, const int* in_sizes, int n_in,
                              void* d_out, int out_size)
{
    const float* seq    = (const float*)d_in[0];
    const float* ent    = (const float*)d_in[1];
    const float* attn   = (const float*)d_in[2];
    const int*   labels = (const int*)  d_in[3];
    const int*   hts    = (const int*)  d_in[4];
    const float* W_head = (const float*)d_in[5];
    const float* b_head = (const float*)d_in[6];
    const float* W_tail = (const float*)d_in[7];
    const float* b_tail = (const float*)d_in[8];
    const float* W_bil  = (const float*)d_in[9];
    const float* b_bil  = (const float*)d_in[10];
    const float* W_cls  = (const float*)d_in[11];
    const float* b_cls  = (const float*)d_in[12];
    const float* W_proj = (const float*)d_in[13];
    const float* b_proj = (const float*)d_in[14];

    float* out      = (float*)d_out;
    float* out_cls  = out + (size_t)NROW*EMB;
    float* out_proj = out_cls + (size_t)NROW*NCLS;

    void *p_rel, *p_ht, *p_biasht;
    void *p_WbHi, *p_WbLo, *p_WhtHi, *p_WhtLo, *p_seqHi, *p_seqLo;
    void *p_htaHi, *p_htaLo, *p_XHi, *p_XLo;
    cudaGetSymbolAddress(&p_rel,   g_rel);
    cudaGetSymbolAddress(&p_ht,    g_ht);
    cudaGetSymbolAddress(&p_biasht,g_bias_ht);
    cudaGetSymbolAddress(&p_WbHi,  g_WbilHi);
    cudaGetSymbolAddress(&p_WbLo,  g_WbilLo);
    cudaGetSymbolAddress(&p_WhtHi, g_WhtHi);
    cudaGetSymbolAddress(&p_WhtLo, g_WhtLo);
    cudaGetSymbolAddress(&p_seqHi, g_seqTHi);
    cudaGetSymbolAddress(&p_seqLo, g_seqTLo);
    cudaGetSymbolAddress(&p_htaHi, g_htaHi);
    cudaGetSymbolAddress(&p_htaLo, g_htaLo);
    cudaGetSymbolAddress(&p_XHi,   g_XHi);
    cudaGetSymbolAddress(&p_XLo,   g_XLo);

    cudaFuncSetAttribute(k_bilinear_mma,
                         cudaFuncAttributeMaxDynamicSharedMemorySize, BIL_SMEM);
    cudaFuncSetAttribute(k_gemm_split<0>,
                         cudaFuncAttributeMaxDynamicSharedMemorySize, 131072);
    cudaFuncSetAttribute(k_gemm_split<1>,
                         cudaFuncAttributeMaxDynamicSharedMemorySize, 131072);

    // ---- preprocessing splits ----
    k_splitT<<<dim3(KBIL/64, EMB/64), 256>>>(W_bil,
        (uint32_t*)p_WbHi, (uint32_t*)p_WbLo, KBIL, EMB, 0, 0);
    k_splitT<<<dim3(2*HID/64, EMB/64), 256>>>(W_head,
        (uint32_t*)p_WhtHi, (uint32_t*)p_WhtLo, 2*HID, EMB, 0, 0);
    k_splitT<<<dim3(2*HID/64, EMB/64), 256>>>(W_tail,
        (uint32_t*)p_WhtHi + (size_t)EMB*HID, (uint32_t*)p_WhtLo + (size_t)EMB*HID,
        2*HID, EMB, 0, 0);
    k_splitT<<<dim3(Lseq/64, HID/64, Bdoc), 256>>>(seq,
        (uint32_t*)p_seqHi, (uint32_t*)p_seqLo, Lseq, HID,
        (long)Lseq*HID, (long)HID*(Lseq/2));
    k_bias2<<<3, 256>>>(b_head, b_tail);

    // ---- pooling chain ----
    k_ent_emb<<<dim3(NE, Bdoc), 256>>>(ent, labels);
    k_attn_mean<<<dim3(NE, NH, Bdoc), 256>>>(attn, labels);
    k_hta<<<dim3(Rht, Bdoc), 256>>>(hts);

    // rel = hta @ seq  (split mma, batched over docs)
    k_gemm_split<0><<<dim3(HID/128, Rht/128, Bdoc), 256, 131072>>>(
        (const uint32_t*)p_htaHi, (const uint32_t*)p_htaLo,
        (const uint32_t*)p_seqHi, (const uint32_t*)p_seqLo,
        nullptr, (float*)p_rel,
        Lseq, HID, (long)Rht*(Lseq/2), (long)HID*(Lseq/2), (long)Rht*HID);

    k_gather<<<NROW, 256>>>(hts);

    // h and t in one launch (z = head/tail)
    k_gemm_split<1><<<dim3(EMB/128, NROW/128, 2), 256, 131072>>>(
        (const uint32_t*)p_XHi, (const uint32_t*)p_XLo,
        (const uint32_t*)p_WhtHi, (const uint32_t*)p_WhtLo,
        (const float*)p_biasht, (float*)p_ht,
        2*HID, EMB, (long)NROW*HID, (long)EMB*HID, (long)NROW*EMB);

    // bilinear -> d_out (embeds)
    k_bilinear_mma<<<dim3(EMB/96, NROW/128), 256, BIL_SMEM>>>(
        (const float*)p_ht, (const float*)p_ht + (size_t)NROW*EMB, b_bil, out);

    // class / proj logits (small fp32 tails)
    sgemm<128,64,8,8,4,0><<<dim3((NCLS+63)/64, NROW/128), 256>>>(
        out, W_cls, b_cls, out_cls, NROW, NCLS, EMB);
    sgemm<128,64,8,8,4,1><<<dim3(NPROJ/64, NROW/128), 256>>>(
        out, W_proj, b_proj, out_proj, NROW, NPROJ, EMB);
}

// round 5
// speedup vs baseline: 3.6996x; 1.1030x over previous
#include <cuda_runtime.h>
#include <cuda_bf16.h>
#include <math.h>
#include <stdint.h>

// ---------------- problem constants ----------------
#define Bdoc 4
#define Lseq 1024
#define Ment 128
#define Rht  512
#define HID  1024
#define NH   16
#define NE   42
#define EMB  768
#define NBLK 12
#define NCLS 97
#define NPROJ 128
#define NROW (Bdoc*Rht)   // 2048
#define KBIL (EMB*64)     // 49152
#define NCHUNK (NBLK*64)  // 768

// ---------------- scratch ----------------
__device__ float g_ent_emb[Bdoc*NE*HID];
__device__ float g_attn_mean[Bdoc*NE*NH*Lseq];
__device__ float g_rel[NROW*HID];
__device__ float g_ht[2*NROW*EMB];                    // h then t (fp32)
__device__ float g_bias_ht[2*EMB];
// packed bf16x2 operands
__device__ uint32_t g_WbilHi[(size_t)EMB*KBIL/2];     // 75.5 MB
__device__ uint32_t g_WbilLo[(size_t)EMB*KBIL/2];
__device__ uint32_t g_WhtHi[2*EMB*HID];               // [2][768][1024]
__device__ uint32_t g_WhtLo[2*EMB*HID];
__device__ uint32_t g_seqTHi[Bdoc*HID*Lseq/2];        // [4][1024][512]
__device__ uint32_t g_seqTLo[Bdoc*HID*Lseq/2];
__device__ uint32_t g_htaHi[NROW*Lseq/2];             // [2048][512]
__device__ uint32_t g_htaLo[NROW*Lseq/2];
__device__ uint32_t g_XHi[2*NROW*HID];                // [2][2048][1024]
__device__ uint32_t g_XLo[2*NROW*HID];

// ---------------- helpers ----------------
__device__ __forceinline__ uint32_t smem_u32(const void* p) {
    uint32_t a;
    asm("{ .reg .u64 t; cvta.to.shared.u64 t, %1; cvt.u32.u64 %0, t; }"
        : "=r"(a) : "l"(p));
    return a;
}
#define SWZ(o) ((o) ^ ((((uint32_t)(o))>>3)&0x70))

#define MMA16816(d, a0,a1,a2,a3, b0,b1) \
    asm volatile("mma.sync.aligned.m16n8k16.row.col.f32.bf16.bf16.f32 " \
        "{%0,%1,%2,%3},{%4,%5,%6,%7},{%8,%9},{%0,%1,%2,%3};" \
        : "+f"((d)[0]), "+f"((d)[1]), "+f"((d)[2]), "+f"((d)[3]) \
        : "r"(a0), "r"(a1), "r"(a2), "r"(a3), "r"(b0), "r"(b1))

#define LDX4(r, addr) \
    asm volatile("ldmatrix.sync.aligned.m8n8.x4.shared.b16 {%0,%1,%2,%3},[%4];" \
        : "=r"((r)[0]), "=r"((r)[1]), "=r"((r)[2]), "=r"((r)[3]) : "r"(addr))

#define CPA16(dst, src) \
    asm volatile("cp.async.cg.shared.global [%0], [%1], 16;" :: "r"(dst), "l"(src))

__device__ __forceinline__ uint32_t pack_bf2(float x, float y) {
    uint32_t r;
    asm("cvt.rn.bf16x2.f32 %0, %1, %2;" : "=r"(r) : "f"(y), "f"(x));
    return r;
}
__device__ __forceinline__ float lo_f(uint32_t u) { return __uint_as_float(u << 16); }
__device__ __forceinline__ float hi_f(uint32_t u) { return __uint_as_float(u & 0xffff0000u); }
__device__ __forceinline__ void split2(float x, float y, uint32_t& hp, uint32_t& lp) {
    hp = pack_bf2(x, y);
    lp = pack_bf2(x - lo_f(hp), y - hi_f(hp));
}

// ---------------- K1: entity logsumexp pooling ----------------
__global__ void k_ent_emb(const float* __restrict__ ent,
                          const int* __restrict__ labels)
{
    int e = blockIdx.x, b = blockIdx.y;
    __shared__ int s_idx[Ment];
    __shared__ int s_cnt;
    int tid = threadIdx.x;
    if (tid == 0) {
        int c = 0;
        for (int i = 0; i < Ment; i++)
            if (labels[b*Ment + i] == e) s_idx[c++] = i;
        s_cnt = c;
    }
    __syncthreads();
    int cnt = s_cnt;
    const float* eb = ent + (size_t)b*Ment*HID;
    float* out = g_ent_emb + ((size_t)(b*NE + e))*HID;
    for (int d = tid; d < HID; d += blockDim.x) {
        float r;
        if (cnt == 0) {
            r = 0.f;
        } else {
            float mx = -3.4e38f, s = 0.f;
            for (int i = 0; i < cnt; i++) {
                float v = eb[(size_t)s_idx[i]*HID + d];
                if (v > mx) { s = s*expf(mx - v) + 1.f; mx = v; }
                else        { s += expf(v - mx); }
            }
            r = mx + logf(s);
        }
        out[d] = r;
    }
}

// ---------------- K2: per-entity mean attention ----------------
__global__ void k_attn_mean(const float* __restrict__ attn,
                            const int* __restrict__ labels)
{
    int e = blockIdx.x, h = blockIdx.y, b = blockIdx.z;
    __shared__ int s_idx[Ment];
    __shared__ int s_cnt;
    int tid = threadIdx.x;
    if (tid == 0) {
        int c = 0;
        for (int i = 0; i < Ment; i++)
            if (labels[b*Ment + i] == e) s_idx[c++] = i;
        s_cnt = c;
    }
    __syncthreads();
    int cnt = s_cnt;
    float inv = 1.f / (float)(cnt > 0 ? cnt : 1);
    const float* ab = attn + (((size_t)b*NH + h)*Ment)*Lseq;
    float* out = g_attn_mean + (((size_t)(b*NE + e))*NH + h)*Lseq;
    for (int l = tid; l < Lseq; l += blockDim.x) {
        float s = 0.f;
        for (int i = 0; i < cnt; i++) s += ab[(size_t)s_idx[i]*Lseq + l];
        out[l] = s * inv;
    }
}

// ---------------- K3: hta -> split bf16 ----------------
__global__ void k_hta(const int* __restrict__ hts)
{
    int r = blockIdx.x, b = blockIdx.y;
    int r2 = b*Rht + r;
    int e0 = hts[(size_t)r2*2 + 0];
    int e1 = hts[(size_t)r2*2 + 1];
    const float* a0 = g_attn_mean + ((size_t)(b*NE + e0))*NH*Lseq;
    const float* a1 = g_attn_mean + ((size_t)(b*NE + e1))*NH*Lseq;
    int tid = threadIdx.x;
    int l0 = tid*4;
    float4 acc = make_float4(0.f,0.f,0.f,0.f);
#pragma unroll
    for (int h = 0; h < NH; h++) {
        float4 x = *(const float4*)&a0[h*Lseq + l0];
        float4 y = *(const float4*)&a1[h*Lseq + l0];
        acc.x += x.x*y.x; acc.y += x.y*y.y;
        acc.z += x.z*y.z; acc.w += x.w*y.w;
    }
    acc.x *= (1.f/NH); acc.y *= (1.f/NH); acc.z *= (1.f/NH); acc.w *= (1.f/NH);
    __shared__ float red[256];
    red[tid] = acc.x + acc.y + acc.z + acc.w;
    __syncthreads();
    for (int o = 128; o > 0; o >>= 1) {
        if (tid < o) red[tid] += red[tid + o];
        __syncthreads();
    }
    float sc = 1.f / (red[0] + 1e-5f);
    uint32_t h0, l0p, h1, l1p;
    split2(acc.x*sc, acc.y*sc, h0, l0p);
    split2(acc.z*sc, acc.w*sc, h1, l1p);
    size_t o = (size_t)r2*(Lseq/2) + tid*2;
    g_htaHi[o] = h0;  g_htaHi[o+1] = h1;
    g_htaLo[o] = l0p; g_htaLo[o+1] = l1p;
}

// ---------------- K5: gather -> split bf16 X ----------------
__global__ void k_gather(const int* __restrict__ hts)
{
    int r2 = blockIdx.x;
    int b = r2 / Rht;
    int e0 = hts[(size_t)r2*2 + 0];
    int e1 = hts[(size_t)r2*2 + 1];
    const float* emb0 = g_ent_emb + ((size_t)(b*NE + e0))*HID;
    const float* emb1 = g_ent_emb + ((size_t)(b*NE + e1))*HID;
    const float* rel  = g_rel + (size_t)r2*HID;
    for (int u = threadIdx.x; u < HID; u += 256) {
        uint32_t hp, lp;
        if (u < HID/2) {
            float2 v0 = *(const float2*)&emb0[2*u];
            split2(v0.x, v0.y, hp, lp);
            g_XHi[(size_t)r2*HID + u] = hp;
            g_XLo[(size_t)r2*HID + u] = lp;
            float2 v1 = *(const float2*)&emb1[2*u];
            split2(v1.x, v1.y, hp, lp);
            g_XHi[(size_t)(NROW + r2)*HID + u] = hp;
            g_XLo[(size_t)(NROW + r2)*HID + u] = lp;
        } else {
            float2 rv = *(const float2*)&rel[2*u - HID];
            split2(rv.x, rv.y, hp, lp);
            g_XHi[(size_t)r2*HID + u] = hp;
            g_XLo[(size_t)r2*HID + u] = lp;
            g_XHi[(size_t)(NROW + r2)*HID + u] = hp;
            g_XLo[(size_t)(NROW + r2)*HID + u] = lp;
        }
    }
}

// ---------------- split + transpose v2: [z][K][N] f32 -> [z][N][K/2] bf16x2 --
// 128(K) x 64(N) tiles, 256 threads, 8 independent float4 loads per thread.
__global__ void __launch_bounds__(256)
k_splitT(const float* __restrict__ in,
         uint32_t* __restrict__ outHi, uint32_t* __restrict__ outLo,
         int K, int N, long sIn, long sOut)
{
    __shared__ float s[128][65];
    in    += (size_t)blockIdx.z * sIn;
    outHi += (size_t)blockIdx.z * sOut;
    outLo += (size_t)blockIdx.z * sOut;
    int k0 = blockIdx.x*128, n0 = blockIdx.y*64;
    int tid = threadIdx.x;
#pragma unroll
    for (int u = 0; u < 8; u++) {
        int idx = tid + u*256;          // 2048 float4s
        int kk = idx >> 4;
        int cc = (idx & 15) * 4;
        float4 v = *(const float4*)&in[(size_t)(k0+kk)*N + n0 + cc];
        s[kk][cc+0] = v.x; s[kk][cc+1] = v.y;
        s[kk][cc+2] = v.z; s[kk][cc+3] = v.w;
    }
    __syncthreads();
    int K2 = K >> 1;
#pragma unroll
    for (int u = 0; u < 4; u++) {
        int idx = tid + u*256;          // 64 n * 16 quads
        int nn = idx >> 4, q = idx & 15;
        uint32_t hi[4], lo[4];
#pragma unroll
        for (int i = 0; i < 4; i++)
            split2(s[q*8 + i*2][nn], s[q*8 + i*2 + 1][nn], hi[i], lo[i]);
        size_t o = (size_t)(n0+nn)*K2 + (k0 >> 1) + q*4;
        *(uint4*)&outHi[o] = make_uint4(hi[0], hi[1], hi[2], hi[3]);
        *(uint4*)&outLo[o] = make_uint4(lo[0], lo[1], lo[2], lo[3]);
    }
}

__global__ void k_bias2(const float* __restrict__ b0, const float* __restrict__ b1)
{
    int i = threadIdx.x + blockIdx.x*256;
    if (i < EMB) { g_bias_ht[i] = b0[i]; g_bias_ht[EMB+i] = b1[i]; }
}

// ---------------- generic 3-split bf16 mma GEMM ----------------
template<int ACT>
__global__ void __launch_bounds__(256, 1)
k_gemm_split(const uint32_t* __restrict__ Ahi, const uint32_t* __restrict__ Alo,
             const uint32_t* __restrict__ Bhi, const uint32_t* __restrict__ Blo,
             const float* __restrict__ bias, float* __restrict__ C,
             int K, int N, long sA, long sB, long sC)
{
    extern __shared__ char smem[];   // [2][Ahi 16K|Alo 16K|Bhi 16K|Blo 16K]
    uint32_t sb = smem_u32(smem);
    int tid = threadIdx.x, lid = tid & 31, wid = tid >> 5;
    int row0 = blockIdx.y*128, col0 = blockIdx.x*128;
    Ahi += (size_t)blockIdx.z * sA;  Alo += (size_t)blockIdx.z * sA;
    Bhi += (size_t)blockIdx.z * sB;  Blo += (size_t)blockIdx.z * sB;
    C   += (size_t)blockIdx.z * sC;
    const float* bz = bias ? bias + (size_t)blockIdx.z * N : nullptr;
    int K2 = K >> 1, nchunk = K >> 6;
    int wm = (wid >> 1)*32, wn = (wid & 1)*64;
    int msel = lid >> 3, r8 = lid & 7;

    float acc[2][8][4];
#pragma unroll
    for (int i = 0; i < 2; i++)
#pragma unroll
        for (int n = 0; n < 8; n++)
#pragma unroll
            for (int q = 0; q < 4; q++) acc[i][n][q] = 0.f;

#define GLOAD(c) { \
    uint32_t base = sb + (uint32_t)((c)&1)*65536u; \
    _Pragma("unroll") \
    for (int p = 0; p < 4; p++) { \
        int idx = tid + p*256; int r = idx >> 3, seg = idx & 7; \
        uint32_t off = SWZ((uint32_t)(r*128 + seg*16)); \
        size_t goA = (size_t)(row0+r)*K2 + (size_t)(c)*32 + seg*4; \
        size_t goB = (size_t)(col0+r)*K2 + (size_t)(c)*32 + seg*4; \
        CPA16(base + off,          Ahi + goA); \
        CPA16(base + 16384u + off, Alo + goA); \
        CPA16(base + 32768u + off, Bhi + goB); \
        CPA16(base + 49152u + off, Blo + goB); \
    } }

    GLOAD(0);
    asm volatile("cp.async.commit_group;");

#pragma unroll 1
    for (int c = 0; c < nchunk; ++c) {
        if (c + 1 < nchunk) GLOAD(c + 1);
        asm volatile("cp.async.commit_group;");
        asm volatile("cp.async.wait_group 1;");
        __syncthreads();

        uint32_t abase = sb + (uint32_t)(c & 1)*65536u;
        uint32_t bbase = abase + 32768u;
#pragma unroll
        for (int s = 0; s < 4; ++s) {
            uint32_t ah[2][4], al[2][4];
#pragma unroll
            for (int i = 0; i < 2; ++i) {
                uint32_t off = SWZ((uint32_t)((wm + i*16 + (lid & 15))*128
                                              + s*32 + (lid >> 4)*16));
                LDX4(ah[i], abase + off);
                LDX4(al[i], abase + 16384u + off);
            }
            uint32_t bh[16], bl[16];
#pragma unroll
            for (int pq = 0; pq < 4; ++pq) {
                uint32_t off = SWZ((uint32_t)((wn + (pq*2 + (msel >> 1))*8 + r8)*128
                                              + s*32 + (msel & 1)*16));
                LDX4(&bh[pq*4], bbase + off);
                LDX4(&bl[pq*4], bbase + 16384u + off);
            }
#pragma unroll
            for (int i = 0; i < 2; ++i)
#pragma unroll
                for (int n = 0; n < 8; ++n) {
                    MMA16816(acc[i][n], ah[i][0],ah[i][1],ah[i][2],ah[i][3], bh[n*2], bh[n*2+1]);
                    MMA16816(acc[i][n], ah[i][0],ah[i][1],ah[i][2],ah[i][3], bl[n*2], bl[n*2+1]);
                    MMA16816(acc[i][n], al[i][0],al[i][1],al[i][2],al[i][3], bh[n*2], bh[n*2+1]);
                }
        }
        __syncthreads();
    }
#undef GLOAD

#pragma unroll
    for (int i = 0; i < 2; ++i) {
        int gr = row0 + wm + i*16 + (lid >> 2);
#pragma unroll
        for (int n = 0; n < 8; ++n) {
            int gc = col0 + wn + n*8 + (lid & 3)*2;
            float b0v = bz ? bz[gc] : 0.f, b1v = bz ? bz[gc+1] : 0.f;
            float v0 = acc[i][n][0] + b0v, v1 = acc[i][n][1] + b1v;
            float v2 = acc[i][n][2] + b0v, v3 = acc[i][n][3] + b1v;
            if (ACT == 1) { v0 = tanhf(v0); v1 = tanhf(v1); v2 = tanhf(v2); v3 = tanhf(v3); }
            *(float2*)&C[(size_t)gr*N + gc]     = make_float2(v0, v1);
            *(float2*)&C[(size_t)(gr+8)*N + gc] = make_float2(v2, v3);
        }
    }
}

// ---------------- fp32 SIMT sgemm (small tails: cls/proj) ----------------
template<int BM, int BN, int BK, int TM, int TN, int ACT>
__global__ __launch_bounds__((BM/TM)*(BN/TN))
void sgemm(const float* __restrict__ A, const float* __restrict__ B,
           const float* __restrict__ bias, float* __restrict__ C,
           int M, int N, int K)
{
    constexpr int THREADS = (BM/TM)*(BN/TN);
    __shared__ float As[BK][BM + 4];
    __shared__ float Bs[BK][BN];
    int tid = threadIdx.x;
    int tx = tid % (BN/TN);
    int ty = tid / (BN/TN);
    int row0 = blockIdx.y * BM, col0 = blockIdx.x * BN;
    float acc[TM][TN] = {};
    constexpr int AE = BM*BK/THREADS;
    constexpr int BE = BK*BN/THREADS;

    for (int k0 = 0; k0 < K; k0 += BK) {
#pragma unroll
        for (int u = 0; u < AE; u++) {
            int idx = tid + u*THREADS;
            int r = idx / BK, c = idx % BK;
            float v = 0.f;
            int gr = row0 + r;
            if (gr < M) v = A[(size_t)gr*K + k0 + c];
            As[c][r] = v;
        }
#pragma unroll
        for (int u = 0; u < BE; u++) {
            int idx = tid + u*THREADS;
            int r = idx / BN, c = idx % BN;
            float v = 0.f;
            int gc = col0 + c;
            if (gc < N) v = B[(size_t)(k0 + r)*N + gc];
            Bs[r][c] = v;
        }
        __syncthreads();
#pragma unroll
        for (int kk = 0; kk < BK; kk++) {
            float af[TM], bf[TN];
#pragma unroll
            for (int i = 0; i < TM; i += 4)
                *reinterpret_cast<float4*>(&af[i]) =
                    *reinterpret_cast<const float4*>(&As[kk][ty*TM + i]);
#pragma unroll
            for (int j = 0; j < TN; j += 4)
                *reinterpret_cast<float4*>(&bf[j]) =
                    *reinterpret_cast<const float4*>(&Bs[kk][tx*TN + j]);
#pragma unroll
            for (int i = 0; i < TM; i++)
#pragma unroll
                for (int j = 0; j < TN; j++)
                    acc[i][j] += af[i] * bf[j];
        }
        __syncthreads();
    }
#pragma unroll
    for (int i = 0; i < TM; i++) {
        int gr = row0 + ty*TM + i;
        if (gr >= M) continue;
#pragma unroll
        for (int j = 0; j < TN; j++) {
            int gc = col0 + tx*TN + j;
            if (gc >= N) continue;
            float v = acc[i][j];
            if (bias) v += bias[gc];
            if (ACT == 1) v = tanhf(v);
            C[(size_t)gr*N + gc] = v;
        }
    }
}

// ---------------- bilinear GEMM via mma.sync (3x split, N-tile 96) ----------
#define BIL_SH_OFF 49152
#define BIL_ST_OFF (49152 + 34816)
#define BIL_SMEM   (49152 + 2*34816)   // 118784

__device__ __forceinline__ void bil_load_B(uint32_t sb, int c, int col0, int tid)
{
    uint32_t dH = sb + (uint32_t)(c & 1)*24576u;
#pragma unroll
    for (int p = 0; p < 3; p++) {
        int idx = tid + p*256;
        int n = idx >> 3, seg = idx & 7;
        size_t go = (size_t)(col0 + n)*(KBIL/2) + (size_t)c*32 + seg*4;
        uint32_t off = SWZ((uint32_t)(n*128 + seg*16));
        CPA16(dH + off,           g_WbilHi + go);
        CPA16(dH + 12288u + off,  g_WbilLo + go);
    }
}

__global__ void __launch_bounds__(256, 1)
k_bilinear_mma(const float* __restrict__ h, const float* __restrict__ t,
               const float* __restrict__ bias, float* __restrict__ out)
{
    extern __shared__ char smem[];
    uint32_t sb = smem_u32(smem);
    float* s_h = (float*)(smem + BIL_SH_OFF);   // [128][68]
    float* s_t = (float*)(smem + BIL_ST_OFF);   // [128][68]
    int tid = threadIdx.x, lid = tid & 31, wid = tid >> 5;
    int row0 = blockIdx.y * 128, col0 = blockIdx.x * 96;
    int wm = (wid >> 1) * 32;
    int wn = (wid & 1) * 48;

    float acc[2][6][4];
#pragma unroll
    for (int i = 0; i < 2; i++)
#pragma unroll
        for (int n = 0; n < 6; n++)
#pragma unroll
            for (int q = 0; q < 4; q++) acc[i][n][q] = 0.f;

    bil_load_B(sb, 0, col0, tid);
    asm volatile("cp.async.commit_group;");

#pragma unroll 1
    for (int c = 0; c < NCHUNK; ++c) {
        int j = c >> 6, a = c & 63, buf = c & 1;

        if (c + 1 < NCHUNK) bil_load_B(sb, c + 1, col0, tid);
        asm volatile("cp.async.commit_group;");
        asm volatile("cp.async.wait_group 1;");

        if (a == 0) {
            for (int idx = tid; idx < 128*16; idx += 256) {
                int rr = idx >> 4, cc = (idx & 15) * 4;
                *(float4*)&s_h[rr*68 + cc] =
                    *(const float4*)&h[(size_t)(row0+rr)*EMB + j*64 + cc];
                *(float4*)&s_t[rr*68 + cc] =
                    *(const float4*)&t[(size_t)(row0+rr)*EMB + j*64 + cc];
            }
        }
        __syncthreads();

        uint32_t bbase = sb + (uint32_t)buf*24576u;
        float h0[2], h1[2];
#pragma unroll
        for (int i = 0; i < 2; i++) {
            int r0 = wm + i*16 + (lid >> 2);
            h0[i] = s_h[r0*68 + a];
            h1[i] = s_h[(r0 + 8)*68 + a];
        }

        int msel = lid >> 3, r8 = lid & 7;
#pragma unroll
        for (int s = 0; s < 4; ++s) {
            uint32_t bh[12], bl[12];
#pragma unroll
            for (int pq = 0; pq < 3; ++pq) {
                uint32_t off = SWZ((uint32_t)((wn + (pq*2 + (msel >> 1))*8 + r8)*128
                                              + s*32 + (msel & 1)*16));
                LDX4(&bh[pq*4], bbase + off);
                LDX4(&bl[pq*4], bbase + 12288u + off);
            }
#pragma unroll
            for (int i = 0; i < 2; ++i) {
                int rb = (wm + i*16 + (lid >> 2))*68;
                int cc = s*16 + (lid & 3)*2;
                float2 ta = *(float2*)&s_t[rb + cc];
                float2 tb = *(float2*)&s_t[rb + cc + 8];
                float2 tc = *(float2*)&s_t[rb + 8*68 + cc];
                float2 td = *(float2*)&s_t[rb + 8*68 + cc + 8];
                uint32_t ah[4], al[4];
                split2(h0[i]*ta.x, h0[i]*ta.y, ah[0], al[0]);
                split2(h1[i]*tc.x, h1[i]*tc.y, ah[1], al[1]);
                split2(h0[i]*tb.x, h0[i]*tb.y, ah[2], al[2]);
                split2(h1[i]*td.x, h1[i]*td.y, ah[3], al[3]);
#pragma unroll
                for (int n = 0; n < 6; ++n) {
                    MMA16816(acc[i][n], ah[0],ah[1],ah[2],ah[3], bh[n*2], bh[n*2+1]);
                    MMA16816(acc[i][n], ah[0],ah[1],ah[2],ah[3], bl[n*2], bl[n*2+1]);
                    MMA16816(acc[i][n], al[0],al[1],al[2],al[3], bh[n*2], bh[n*2+1]);
                }
            }
        }
        __syncthreads();
    }

#pragma unroll
    for (int i = 0; i < 2; ++i) {
        int gr = row0 + wm + i*16 + (lid >> 2);
#pragma unroll
        for (int n = 0; n < 6; ++n) {
            int gc = col0 + wn + n*8 + (lid & 3)*2;
            float2 v0 = make_float2(acc[i][n][0] + bias[gc],
                                    acc[i][n][1] + bias[gc+1]);
            float2 v1 = make_float2(acc[i][n][2] + bias[gc],
                                    acc[i][n][3] + bias[gc+1]);
            *(float2*)&out[(size_t)gr*EMB + gc]     = v0;
            *(float2*)&out[(size_t)(gr+8)*EMB + gc] = v1;
        }
    }
}

// ---------------- launch ----------------
extern "C" void kernel_launch(void* const* d_in, const int* in_sizes, int n_in,
                              void* d_out, int out_size)
{
    const float* seq    = (const float*)d_in[0];
    const float* ent    = (const float*)d_in[1];
    const float* attn   = (const float*)d_in[2];
    const int*   labels = (const int*)  d_in[3];
    const int*   hts    = (const int*)  d_in[4];
    const float* W_head = (const float*)d_in[5];
    const float* b_head = (const float*)d_in[6];
    const float* W_tail = (const float*)d_in[7];
    const float* b_tail = (const float*)d_in[8];
    const float* W_bil  = (const float*)d_in[9];
    const float* b_bil  = (const float*)d_in[10];
    const float* W_cls  = (const float*)d_in[11];
    const float* b_cls  = (const float*)d_in[12];
    const float* W_proj = (const float*)d_in[13];
    const float* b_proj = (const float*)d_in[14];

    float* out      = (float*)d_out;
    float* out_cls  = out + (size_t)NROW*EMB;
    float* out_proj = out_cls + (size_t)NROW*NCLS;

    void *p_rel, *p_ht, *p_biasht;
    void *p_WbHi, *p_WbLo, *p_WhtHi, *p_WhtLo, *p_seqHi, *p_seqLo;
    void *p_htaHi, *p_htaLo, *p_XHi, *p_XLo;
    cudaGetSymbolAddress(&p_rel,   g_rel);
    cudaGetSymbolAddress(&p_ht,    g_ht);
    cudaGetSymbolAddress(&p_biasht,g_bias_ht);
    cudaGetSymbolAddress(&p_WbHi,  g_WbilHi);
    cudaGetSymbolAddress(&p_WbLo,  g_WbilLo);
    cudaGetSymbolAddress(&p_WhtHi, g_WhtHi);
    cudaGetSymbolAddress(&p_WhtLo, g_WhtLo);
    cudaGetSymbolAddress(&p_seqHi, g_seqTHi);
    cudaGetSymbolAddress(&p_seqLo, g_seqTLo);
    cudaGetSymbolAddress(&p_htaHi, g_htaHi);
    cudaGetSymbolAddress(&p_htaLo, g_htaLo);
    cudaGetSymbolAddress(&p_XHi,   g_XHi);
    cudaGetSymbolAddress(&p_XLo,   g_XLo);

    cudaFuncSetAttribute(k_bilinear_mma,
                         cudaFuncAttributeMaxDynamicSharedMemorySize, BIL_SMEM);
    cudaFuncSetAttribute(k_gemm_split<0>,
                         cudaFuncAttributeMaxDynamicSharedMemorySize, 131072);
    cudaFuncSetAttribute(k_gemm_split<1>,
                         cudaFuncAttributeMaxDynamicSharedMemorySize, 131072);

    // side stream for weight preprocessing (created once; event-forked so
    // graph capture sees a single connected DAG)
    static cudaStream_t s1 = nullptr;
    static cudaEvent_t evFork = nullptr, evJoin = nullptr;
    if (!s1) {
        cudaStreamCreateWithFlags(&s1, cudaStreamNonBlocking);
        cudaEventCreateWithFlags(&evFork, cudaEventDisableTiming);
        cudaEventCreateWithFlags(&evJoin, cudaEventDisableTiming);
    }

    cudaEventRecord(evFork, 0);
    cudaStreamWaitEvent(s1, evFork, 0);

    // ---- weight preprocessing on s1 (launches #1-#4; Wbil split is #4 for ncu)
    k_bias2<<<3, 256, 0, s1>>>(b_head, b_tail);
    k_splitT<<<dim3(2*HID/128, EMB/64), 256, 0, s1>>>(W_head,
        (uint32_t*)p_WhtHi, (uint32_t*)p_WhtLo, 2*HID, EMB, 0, 0);
    k_splitT<<<dim3(2*HID/128, EMB/64), 256, 0, s1>>>(W_tail,
        (uint32_t*)p_WhtHi + (size_t)EMB*HID, (uint32_t*)p_WhtLo + (size_t)EMB*HID,
        2*HID, EMB, 0, 0);
    k_splitT<<<dim3(KBIL/128, EMB/64), 256, 0, s1>>>(W_bil,
        (uint32_t*)p_WbHi, (uint32_t*)p_WbLo, KBIL, EMB, 0, 0);
    cudaEventRecord(evJoin, s1);

    // ---- pooling chain + rel on default stream (concurrent with s1)
    k_splitT<<<dim3(Lseq/128, HID/64, Bdoc), 256>>>(seq,
        (uint32_t*)p_seqHi, (uint32_t*)p_seqLo, Lseq, HID,
        (long)Lseq*HID, (long)HID*(Lseq/2));
    k_ent_emb<<<dim3(NE, Bdoc), 256>>>(ent, labels);
    k_attn_mean<<<dim3(NE, NH, Bdoc), 256>>>(attn, labels);
    k_hta<<<dim3(Rht, Bdoc), 256>>>(hts);

    k_gemm_split<0><<<dim3(HID/128, Rht/128, Bdoc), 256, 131072>>>(
        (const uint32_t*)p_htaHi, (const uint32_t*)p_htaLo,
        (const uint32_t*)p_seqHi, (const uint32_t*)p_seqLo,
        nullptr, (float*)p_rel,
        Lseq, HID, (long)Rht*(Lseq/2), (long)HID*(Lseq/2), (long)Rht*HID);

    k_gather<<<NROW, 256>>>(hts);

    // join: weights ready
    cudaStreamWaitEvent(0, evJoin, 0);

    // h and t in one launch (z = head/tail)
    k_gemm_split<1><<<dim3(EMB/128, NROW/128, 2), 256, 131072>>>(
        (const uint32_t*)p_XHi, (const uint32_t*)p_XLo,
        (const uint32_t*)p_WhtHi, (const uint32_t*)p_WhtLo,
        (const float*)p_biasht, (float*)p_ht,
        2*HID, EMB, (long)NROW*HID, (long)EMB*HID, (long)NROW*EMB);

    // bilinear -> d_out (embeds)
    k_bilinear_mma<<<dim3(EMB/96, NROW/128), 256, BIL_SMEM>>>(
        (const float*)p_ht, (const float*)p_ht + (size_t)NROW*EMB, b_bil, out);

    // class / proj logits (small fp32 tails, many CTAs)
    sgemm<64,32,16,4,4,0><<<dim3((NCLS+31)/32, NROW/64), 128>>>(
        out, W_cls, b_cls, out_cls, NROW, NCLS, EMB);
    sgemm<64,32,16,4,4,1><<<dim3(NPROJ/32, NROW/64), 128>>>(
        out, W_proj, b_proj, out_proj, NROW, NPROJ, EMB);
}

// round 6
// speedup vs baseline: 4.5961x; 1.2423x over previous
#include <cuda_runtime.h>
#include <cuda_bf16.h>
#include <cuda_fp16.h>
#include <math.h>
#include <stdint.h>

// ---------------- problem constants ----------------
#define Bdoc 4
#define Lseq 1024
#define Ment 128
#define Rht  512
#define HID  1024
#define NH   16
#define NE   42
#define EMB  768
#define NBLK 12
#define NCLS 97
#define NPROJ 128
#define NROW (Bdoc*Rht)   // 2048
#define KBIL (EMB*64)     // 49152
#define NCHUNK (NBLK*64)  // 768

// ---------------- scratch ----------------
__device__ float g_ent_emb[Bdoc*NE*HID];
__device__ float g_attn_mean[Bdoc*NE*NH*Lseq];
__device__ float g_rel[NROW*HID];
__device__ float g_ht[2*NROW*EMB];                    // h then t (fp32)
__device__ float g_bias_ht[2*EMB];
// packed 16-bit x2 operands
__device__ uint32_t g_WbilHi[(size_t)EMB*KBIL/2];     // fp16 pairs, 75.5 MB
__device__ uint32_t g_WbilLo[(size_t)EMB*KBIL/2];     // fp16 residual pairs
__device__ uint32_t g_WhtHi[2*EMB*HID];               // bf16 [2][768][1024]
__device__ uint32_t g_WhtLo[2*EMB*HID];
__device__ uint32_t g_seqTHi[Bdoc*HID*Lseq/2];
__device__ uint32_t g_seqTLo[Bdoc*HID*Lseq/2];
__device__ uint32_t g_htaHi[NROW*Lseq/2];
__device__ uint32_t g_htaLo[NROW*Lseq/2];
__device__ uint32_t g_XHi[2*NROW*HID];
__device__ uint32_t g_XLo[2*NROW*HID];

// ---------------- helpers ----------------
__device__ __forceinline__ uint32_t smem_u32(const void* p) {
    uint32_t a;
    asm("{ .reg .u64 t; cvta.to.shared.u64 t, %1; cvt.u32.u64 %0, t; }"
        : "=r"(a) : "l"(p));
    return a;
}
#define SWZ(o) ((o) ^ ((((uint32_t)(o))>>3)&0x70))

#define MMA16816(d, a0,a1,a2,a3, b0,b1) \
    asm volatile("mma.sync.aligned.m16n8k16.row.col.f32.bf16.bf16.f32 " \
        "{%0,%1,%2,%3},{%4,%5,%6,%7},{%8,%9},{%0,%1,%2,%3};" \
        : "+f"((d)[0]), "+f"((d)[1]), "+f"((d)[2]), "+f"((d)[3]) \
        : "r"(a0), "r"(a1), "r"(a2), "r"(a3), "r"(b0), "r"(b1))

#define MMA16816H(d, a0,a1,a2,a3, b0,b1) \
    asm volatile("mma.sync.aligned.m16n8k16.row.col.f32.f16.f16.f32 " \
        "{%0,%1,%2,%3},{%4,%5,%6,%7},{%8,%9},{%0,%1,%2,%3};" \
        : "+f"((d)[0]), "+f"((d)[1]), "+f"((d)[2]), "+f"((d)[3]) \
        : "r"(a0), "r"(a1), "r"(a2), "r"(a3), "r"(b0), "r"(b1))

#define LDX4(r, addr) \
    asm volatile("ldmatrix.sync.aligned.m8n8.x4.shared.b16 {%0,%1,%2,%3},[%4];" \
        : "=r"((r)[0]), "=r"((r)[1]), "=r"((r)[2]), "=r"((r)[3]) : "r"(addr))

#define CPA16(dst, src) \
    asm volatile("cp.async.cg.shared.global [%0], [%1], 16;" :: "r"(dst), "l"(src))

__device__ __forceinline__ uint32_t pack_bf2(float x, float y) {
    uint32_t r;
    asm("cvt.rn.bf16x2.f32 %0, %1, %2;" : "=r"(r) : "f"(y), "f"(x));
    return r;
}
__device__ __forceinline__ uint32_t pack_h2(float x, float y) {
    uint32_t r;
    asm("cvt.rn.f16x2.f32 %0, %1, %2;" : "=r"(r) : "f"(y), "f"(x));
    return r;
}
__device__ __forceinline__ float lo_f(uint32_t u) { return __uint_as_float(u << 16); }
__device__ __forceinline__ float hi_f(uint32_t u) { return __uint_as_float(u & 0xffff0000u); }
__device__ __forceinline__ void split2(float x, float y, uint32_t& hp, uint32_t& lp) {
    hp = pack_bf2(x, y);
    lp = pack_bf2(x - lo_f(hp), y - hi_f(hp));
}
__device__ __forceinline__ void split2h(float x, float y, uint32_t& hp, uint32_t& lp) {
    hp = pack_h2(x, y);
    __half2 h2 = *reinterpret_cast<__half2*>(&hp);
    lp = pack_h2(x - __low2float(h2), y - __high2float(h2));
}

// ---------------- K1: entity logsumexp pooling ----------------
__global__ void k_ent_emb(const float* __restrict__ ent,
                          const int* __restrict__ labels)
{
    int e = blockIdx.x, b = blockIdx.y;
    __shared__ int s_idx[Ment];
    __shared__ int s_cnt;
    int tid = threadIdx.x;
    if (tid == 0) {
        int c = 0;
        for (int i = 0; i < Ment; i++)
            if (labels[b*Ment + i] == e) s_idx[c++] = i;
        s_cnt = c;
    }
    __syncthreads();
    int cnt = s_cnt;
    const float* eb = ent + (size_t)b*Ment*HID;
    float* out = g_ent_emb + ((size_t)(b*NE + e))*HID;
    for (int d = tid; d < HID; d += blockDim.x) {
        float r;
        if (cnt == 0) {
            r = 0.f;
        } else {
            float mx = -3.4e38f, s = 0.f;
            for (int i = 0; i < cnt; i++) {
                float v = eb[(size_t)s_idx[i]*HID + d];
                if (v > mx) { s = s*expf(mx - v) + 1.f; mx = v; }
                else        { s += expf(v - mx); }
            }
            r = mx + logf(s);
        }
        out[d] = r;
    }
}

// ---------------- K2: per-entity mean attention ----------------
__global__ void k_attn_mean(const float* __restrict__ attn,
                            const int* __restrict__ labels)
{
    int e = blockIdx.x, h = blockIdx.y, b = blockIdx.z;
    __shared__ int s_idx[Ment];
    __shared__ int s_cnt;
    int tid = threadIdx.x;
    if (tid == 0) {
        int c = 0;
        for (int i = 0; i < Ment; i++)
            if (labels[b*Ment + i] == e) s_idx[c++] = i;
        s_cnt = c;
    }
    __syncthreads();
    int cnt = s_cnt;
    float inv = 1.f / (float)(cnt > 0 ? cnt : 1);
    const float* ab = attn + (((size_t)b*NH + h)*Ment)*Lseq;
    float* out = g_attn_mean + (((size_t)(b*NE + e))*NH + h)*Lseq;
    for (int l = tid; l < Lseq; l += blockDim.x) {
        float s = 0.f;
        for (int i = 0; i < cnt; i++) s += ab[(size_t)s_idx[i]*Lseq + l];
        out[l] = s * inv;
    }
}

// ---------------- K3: hta -> split bf16 ----------------
__global__ void k_hta(const int* __restrict__ hts)
{
    int r = blockIdx.x, b = blockIdx.y;
    int r2 = b*Rht + r;
    int e0 = hts[(size_t)r2*2 + 0];
    int e1 = hts[(size_t)r2*2 + 1];
    const float* a0 = g_attn_mean + ((size_t)(b*NE + e0))*NH*Lseq;
    const float* a1 = g_attn_mean + ((size_t)(b*NE + e1))*NH*Lseq;
    int tid = threadIdx.x;
    int l0 = tid*4;
    float4 acc = make_float4(0.f,0.f,0.f,0.f);
#pragma unroll
    for (int h = 0; h < NH; h++) {
        float4 x = *(const float4*)&a0[h*Lseq + l0];
        float4 y = *(const float4*)&a1[h*Lseq + l0];
        acc.x += x.x*y.x; acc.y += x.y*y.y;
        acc.z += x.z*y.z; acc.w += x.w*y.w;
    }
    acc.x *= (1.f/NH); acc.y *= (1.f/NH); acc.z *= (1.f/NH); acc.w *= (1.f/NH);
    __shared__ float red[256];
    red[tid] = acc.x + acc.y + acc.z + acc.w;
    __syncthreads();
    for (int o = 128; o > 0; o >>= 1) {
        if (tid < o) red[tid] += red[tid + o];
        __syncthreads();
    }
    float sc = 1.f / (red[0] + 1e-5f);
    uint32_t h0, l0p, h1, l1p;
    split2(acc.x*sc, acc.y*sc, h0, l0p);
    split2(acc.z*sc, acc.w*sc, h1, l1p);
    size_t o = (size_t)r2*(Lseq/2) + tid*2;
    g_htaHi[o] = h0;  g_htaHi[o+1] = h1;
    g_htaLo[o] = l0p; g_htaLo[o+1] = l1p;
}

// ---------------- K5: gather -> split bf16 X ----------------
__global__ void k_gather(const int* __restrict__ hts)
{
    int r2 = blockIdx.x;
    int b = r2 / Rht;
    int e0 = hts[(size_t)r2*2 + 0];
    int e1 = hts[(size_t)r2*2 + 1];
    const float* emb0 = g_ent_emb + ((size_t)(b*NE + e0))*HID;
    const float* emb1 = g_ent_emb + ((size_t)(b*NE + e1))*HID;
    const float* rel  = g_rel + (size_t)r2*HID;
    for (int u = threadIdx.x; u < HID; u += 256) {
        uint32_t hp, lp;
        if (u < HID/2) {
            float2 v0 = *(const float2*)&emb0[2*u];
            split2(v0.x, v0.y, hp, lp);
            g_XHi[(size_t)r2*HID + u] = hp;
            g_XLo[(size_t)r2*HID + u] = lp;
            float2 v1 = *(const float2*)&emb1[2*u];
            split2(v1.x, v1.y, hp, lp);
            g_XHi[(size_t)(NROW + r2)*HID + u] = hp;
            g_XLo[(size_t)(NROW + r2)*HID + u] = lp;
        } else {
            float2 rv = *(const float2*)&rel[2*u - HID];
            split2(rv.x, rv.y, hp, lp);
            g_XHi[(size_t)r2*HID + u] = hp;
            g_XLo[(size_t)r2*HID + u] = lp;
            g_XHi[(size_t)(NROW + r2)*HID + u] = hp;
            g_XLo[(size_t)(NROW + r2)*HID + u] = lp;
        }
    }
}

// ---------------- split + transpose: [z][K][N] f32 -> [z][N][K/2] 16bitx2 ----
// FMT 0 = bf16 hi/lo, FMT 1 = fp16 hi/lo
template<int FMT>
__global__ void __launch_bounds__(256)
k_splitT(const float* __restrict__ in,
         uint32_t* __restrict__ outHi, uint32_t* __restrict__ outLo,
         int K, int N, long sIn, long sOut)
{
    __shared__ float s[128][65];
    in    += (size_t)blockIdx.z * sIn;
    outHi += (size_t)blockIdx.z * sOut;
    outLo += (size_t)blockIdx.z * sOut;
    int k0 = blockIdx.x*128, n0 = blockIdx.y*64;
    int tid = threadIdx.x;
#pragma unroll
    for (int u = 0; u < 8; u++) {
        int idx = tid + u*256;
        int kk = idx >> 4;
        int cc = (idx & 15) * 4;
        float4 v = *(const float4*)&in[(size_t)(k0+kk)*N + n0 + cc];
        s[kk][cc+0] = v.x; s[kk][cc+1] = v.y;
        s[kk][cc+2] = v.z; s[kk][cc+3] = v.w;
    }
    __syncthreads();
    int K2 = K >> 1;
#pragma unroll
    for (int u = 0; u < 4; u++) {
        int idx = tid + u*256;
        int nn = idx >> 4, q = idx & 15;
        uint32_t hi[4], lo[4];
#pragma unroll
        for (int i = 0; i < 4; i++) {
            if (FMT == 0) split2 (s[q*8 + i*2][nn], s[q*8 + i*2 + 1][nn], hi[i], lo[i]);
            else          split2h(s[q*8 + i*2][nn], s[q*8 + i*2 + 1][nn], hi[i], lo[i]);
        }
        size_t o = (size_t)(n0+nn)*K2 + (k0 >> 1) + q*4;
        *(uint4*)&outHi[o] = make_uint4(hi[0], hi[1], hi[2], hi[3]);
        *(uint4*)&outLo[o] = make_uint4(lo[0], lo[1], lo[2], lo[3]);
    }
}

__global__ void k_bias2(const float* __restrict__ b0, const float* __restrict__ b1)
{
    int i = threadIdx.x + blockIdx.x*256;
    if (i < EMB) { g_bias_ht[i] = b0[i]; g_bias_ht[EMB+i] = b1[i]; }
}

// ---------------- generic 3-split bf16 mma GEMM ----------------
template<int ACT>
__global__ void __launch_bounds__(256, 1)
k_gemm_split(const uint32_t* __restrict__ Ahi, const uint32_t* __restrict__ Alo,
             const uint32_t* __restrict__ Bhi, const uint32_t* __restrict__ Blo,
             const float* __restrict__ bias, float* __restrict__ C,
             int K, int N, long sA, long sB, long sC)
{
    extern __shared__ char smem[];
    uint32_t sb = smem_u32(smem);
    int tid = threadIdx.x, lid = tid & 31, wid = tid >> 5;
    int row0 = blockIdx.y*128, col0 = blockIdx.x*128;
    Ahi += (size_t)blockIdx.z * sA;  Alo += (size_t)blockIdx.z * sA;
    Bhi += (size_t)blockIdx.z * sB;  Blo += (size_t)blockIdx.z * sB;
    C   += (size_t)blockIdx.z * sC;
    const float* bz = bias ? bias + (size_t)blockIdx.z * N : nullptr;
    int K2 = K >> 1, nchunk = K >> 6;
    int wm = (wid >> 1)*32, wn = (wid & 1)*64;
    int msel = lid >> 3, r8 = lid & 7;

    float acc[2][8][4];
#pragma unroll
    for (int i = 0; i < 2; i++)
#pragma unroll
        for (int n = 0; n < 8; n++)
#pragma unroll
            for (int q = 0; q < 4; q++) acc[i][n][q] = 0.f;

#define GLOAD(c) { \
    uint32_t base = sb + (uint32_t)((c)&1)*65536u; \
    _Pragma("unroll") \
    for (int p = 0; p < 4; p++) { \
        int idx = tid + p*256; int r = idx >> 3, seg = idx & 7; \
        uint32_t off = SWZ((uint32_t)(r*128 + seg*16)); \
        size_t goA = (size_t)(row0+r)*K2 + (size_t)(c)*32 + seg*4; \
        size_t goB = (size_t)(col0+r)*K2 + (size_t)(c)*32 + seg*4; \
        CPA16(base + off,          Ahi + goA); \
        CPA16(base + 16384u + off, Alo + goA); \
        CPA16(base + 32768u + off, Bhi + goB); \
        CPA16(base + 49152u + off, Blo + goB); \
    } }

    GLOAD(0);
    asm volatile("cp.async.commit_group;");

#pragma unroll 1
    for (int c = 0; c < nchunk; ++c) {
        if (c + 1 < nchunk) GLOAD(c + 1);
        asm volatile("cp.async.commit_group;");
        asm volatile("cp.async.wait_group 1;");
        __syncthreads();

        uint32_t abase = sb + (uint32_t)(c & 1)*65536u;
        uint32_t bbase = abase + 32768u;
#pragma unroll
        for (int s = 0; s < 4; ++s) {
            uint32_t ah[2][4], al[2][4];
#pragma unroll
            for (int i = 0; i < 2; ++i) {
                uint32_t off = SWZ((uint32_t)((wm + i*16 + (lid & 15))*128
                                              + s*32 + (lid >> 4)*16));
                LDX4(ah[i], abase + off);
                LDX4(al[i], abase + 16384u + off);
            }
            uint32_t bh[16], bl[16];
#pragma unroll
            for (int pq = 0; pq < 4; ++pq) {
                uint32_t off = SWZ((uint32_t)((wn + (pq*2 + (msel >> 1))*8 + r8)*128
                                              + s*32 + (msel & 1)*16));
                LDX4(&bh[pq*4], bbase + off);
                LDX4(&bl[pq*4], bbase + 16384u + off);
            }
#pragma unroll
            for (int i = 0; i < 2; ++i)
#pragma unroll
                for (int n = 0; n < 8; ++n) {
                    MMA16816(acc[i][n], ah[i][0],ah[i][1],ah[i][2],ah[i][3], bh[n*2], bh[n*2+1]);
                    MMA16816(acc[i][n], ah[i][0],ah[i][1],ah[i][2],ah[i][3], bl[n*2], bl[n*2+1]);
                    MMA16816(acc[i][n], al[i][0],al[i][1],al[i][2],al[i][3], bh[n*2], bh[n*2+1]);
                }
        }
        __syncthreads();
    }
#undef GLOAD

#pragma unroll
    for (int i = 0; i < 2; ++i) {
        int gr = row0 + wm + i*16 + (lid >> 2);
#pragma unroll
        for (int n = 0; n < 8; ++n) {
            int gc = col0 + wn + n*8 + (lid & 3)*2;
            float b0v = bz ? bz[gc] : 0.f, b1v = bz ? bz[gc+1] : 0.f;
            float v0 = acc[i][n][0] + b0v, v1 = acc[i][n][1] + b1v;
            float v2 = acc[i][n][2] + b0v, v3 = acc[i][n][3] + b1v;
            if (ACT == 1) { v0 = tanhf(v0); v1 = tanhf(v1); v2 = tanhf(v2); v3 = tanhf(v3); }
            *(float2*)&C[(size_t)gr*N + gc]     = make_float2(v0, v1);
            *(float2*)&C[(size_t)(gr+8)*N + gc] = make_float2(v2, v3);
        }
    }
}

// ---------------- fp32 SIMT sgemm (small tails: cls/proj) ----------------
template<int BM, int BN, int BK, int TM, int TN, int ACT>
__global__ __launch_bounds__((BM/TM)*(BN/TN))
void sgemm(const float* __restrict__ A, const float* __restrict__ B,
           const float* __restrict__ bias, float* __restrict__ C,
           int M, int N, int K)
{
    constexpr int THREADS = (BM/TM)*(BN/TN);
    __shared__ float As[BK][BM + 4];
    __shared__ float Bs[BK][BN];
    int tid = threadIdx.x;
    int tx = tid % (BN/TN);
    int ty = tid / (BN/TN);
    int row0 = blockIdx.y * BM, col0 = blockIdx.x * BN;
    float acc[TM][TN] = {};
    constexpr int AE = BM*BK/THREADS;
    constexpr int BE = BK*BN/THREADS;

    for (int k0 = 0; k0 < K; k0 += BK) {
#pragma unroll
        for (int u = 0; u < AE; u++) {
            int idx = tid + u*THREADS;
            int r = idx / BK, c = idx % BK;
            float v = 0.f;
            int gr = row0 + r;
            if (gr < M) v = A[(size_t)gr*K + k0 + c];
            As[c][r] = v;
        }
#pragma unroll
        for (int u = 0; u < BE; u++) {
            int idx = tid + u*THREADS;
            int r = idx / BN, c = idx % BN;
            float v = 0.f;
            int gc = col0 + c;
            if (gc < N) v = B[(size_t)(k0 + r)*N + gc];
            Bs[r][c] = v;
        }
        __syncthreads();
#pragma unroll
        for (int kk = 0; kk < BK; kk++) {
            float af[TM], bf[TN];
#pragma unroll
            for (int i = 0; i < TM; i += 4)
                *reinterpret_cast<float4*>(&af[i]) =
                    *reinterpret_cast<const float4*>(&As[kk][ty*TM + i]);
#pragma unroll
            for (int j = 0; j < TN; j += 4)
                *reinterpret_cast<float4*>(&bf[j]) =
                    *reinterpret_cast<const float4*>(&Bs[kk][tx*TN + j]);
#pragma unroll
            for (int i = 0; i < TM; i++)
#pragma unroll
                for (int j = 0; j < TN; j++)
                    acc[i][j] += af[i] * bf[j];
        }
        __syncthreads();
    }
#pragma unroll
    for (int i = 0; i < TM; i++) {
        int gr = row0 + ty*TM + i;
        if (gr >= M) continue;
#pragma unroll
        for (int j = 0; j < TN; j++) {
            int gc = col0 + tx*TN + j;
            if (gc >= N) continue;
            float v = acc[i][j];
            if (bias) v += bias[gc];
            if (ACT == 1) v = tanhf(v);
            C[(size_t)gr*N + gc] = v;
        }
    }
}

// ---------------- bilinear GEMM via fp16 mma (2-pass, N-tile 96) ----------
#define BIL_SH_OFF 49152
#define BIL_ST_OFF (49152 + 34816)
#define BIL_SMEM   (49152 + 2*34816)   // 118784

__device__ __forceinline__ void bil_load_B(uint32_t sb, int c, int col0, int tid)
{
    uint32_t dH = sb + (uint32_t)(c & 1)*24576u;
#pragma unroll
    for (int p = 0; p < 3; p++) {
        int idx = tid + p*256;
        int n = idx >> 3, seg = idx & 7;
        size_t go = (size_t)(col0 + n)*(KBIL/2) + (size_t)c*32 + seg*4;
        uint32_t off = SWZ((uint32_t)(n*128 + seg*16));
        CPA16(dH + off,           g_WbilHi + go);
        CPA16(dH + 12288u + off,  g_WbilLo + go);
    }
}

__global__ void __launch_bounds__(256, 1)
k_bilinear_mma(const float* __restrict__ h, const float* __restrict__ t,
               const float* __restrict__ bias, float* __restrict__ out)
{
    extern __shared__ char smem[];
    uint32_t sb = smem_u32(smem);
    float* s_h = (float*)(smem + BIL_SH_OFF);   // [128][68]
    float* s_t = (float*)(smem + BIL_ST_OFF);   // [128][68]
    int tid = threadIdx.x, lid = tid & 31, wid = tid >> 5;
    int row0 = blockIdx.y * 128, col0 = blockIdx.x * 96;
    int wm = (wid >> 1) * 32;
    int wn = (wid & 1) * 48;

    float acc[2][6][4];
#pragma unroll
    for (int i = 0; i < 2; i++)
#pragma unroll
        for (int n = 0; n < 6; n++)
#pragma unroll
            for (int q = 0; q < 4; q++) acc[i][n][q] = 0.f;

    bil_load_B(sb, 0, col0, tid);
    asm volatile("cp.async.commit_group;");

#pragma unroll 1
    for (int c = 0; c < NCHUNK; ++c) {
        int j = c >> 6, a = c & 63, buf = c & 1;

        if (c + 1 < NCHUNK) bil_load_B(sb, c + 1, col0, tid);
        asm volatile("cp.async.commit_group;");
        asm volatile("cp.async.wait_group 1;");

        if (a == 0) {
            for (int idx = tid; idx < 128*16; idx += 256) {
                int rr = idx >> 4, cc = (idx & 15) * 4;
                *(float4*)&s_h[rr*68 + cc] =
                    *(const float4*)&h[(size_t)(row0+rr)*EMB + j*64 + cc];
                *(float4*)&s_t[rr*68 + cc] =
                    *(const float4*)&t[(size_t)(row0+rr)*EMB + j*64 + cc];
            }
        }
        __syncthreads();

        uint32_t bbase = sb + (uint32_t)buf*24576u;
        float h0[2], h1[2];
#pragma unroll
        for (int i = 0; i < 2; i++) {
            int r0 = wm + i*16 + (lid >> 2);
            h0[i] = s_h[r0*68 + a];
            h1[i] = s_h[(r0 + 8)*68 + a];
        }

        int msel = lid >> 3, r8 = lid & 7;
#pragma unroll
        for (int s = 0; s < 4; ++s) {
            uint32_t bh[12], bl[12];
#pragma unroll
            for (int pq = 0; pq < 3; ++pq) {
                uint32_t off = SWZ((uint32_t)((wn + (pq*2 + (msel >> 1))*8 + r8)*128
                                              + s*32 + (msel & 1)*16));
                LDX4(&bh[pq*4], bbase + off);
                LDX4(&bl[pq*4], bbase + 12288u + off);
            }
#pragma unroll
            for (int i = 0; i < 2; ++i) {
                int rb = (wm + i*16 + (lid >> 2))*68;
                int cc = s*16 + (lid & 3)*2;
                float2 ta = *(float2*)&s_t[rb + cc];
                float2 tb = *(float2*)&s_t[rb + cc + 8];
                float2 tc = *(float2*)&s_t[rb + 8*68 + cc];
                float2 td = *(float2*)&s_t[rb + 8*68 + cc + 8];
                // A in single fp16 (products |p|<=1); B carries hi+lo fp16
                uint32_t ah[4];
                ah[0] = pack_h2(h0[i]*ta.x, h0[i]*ta.y);
                ah[1] = pack_h2(h1[i]*tc.x, h1[i]*tc.y);
                ah[2] = pack_h2(h0[i]*tb.x, h0[i]*tb.y);
                ah[3] = pack_h2(h1[i]*td.x, h1[i]*td.y);
#pragma unroll
                for (int n = 0; n < 6; ++n) {
                    MMA16816H(acc[i][n], ah[0],ah[1],ah[2],ah[3], bh[n*2], bh[n*2+1]);
                    MMA16816H(acc[i][n], ah[0],ah[1],ah[2],ah[3], bl[n*2], bl[n*2+1]);
                }
            }
        }
        __syncthreads();
    }

#pragma unroll
    for (int i = 0; i < 2; ++i) {
        int gr = row0 + wm + i*16 + (lid >> 2);
#pragma unroll
        for (int n = 0; n < 6; ++n) {
            int gc = col0 + wn + n*8 + (lid & 3)*2;
            float2 v0 = make_float2(acc[i][n][0] + bias[gc],
                                    acc[i][n][1] + bias[gc+1]);
            float2 v1 = make_float2(acc[i][n][2] + bias[gc],
                                    acc[i][n][3] + bias[gc+1]);
            *(float2*)&out[(size_t)gr*EMB + gc]     = v0;
            *(float2*)&out[(size_t)(gr+8)*EMB + gc] = v1;
        }
    }
}

// ---------------- launch ----------------
extern "C" void kernel_launch(void* const* d_in, const int* in_sizes, int n_in,
                              void* d_out, int out_size)
{
    const float* seq    = (const float*)d_in[0];
    const float* ent    = (const float*)d_in[1];
    const float* attn   = (const float*)d_in[2];
    const int*   labels = (const int*)  d_in[3];
    const int*   hts    = (const int*)  d_in[4];
    const float* W_head = (const float*)d_in[5];
    const float* b_head = (const float*)d_in[6];
    const float* W_tail = (const float*)d_in[7];
    const float* b_tail = (const float*)d_in[8];
    const float* W_bil  = (const float*)d_in[9];
    const float* b_bil  = (const float*)d_in[10];
    const float* W_cls  = (const float*)d_in[11];
    const float* b_cls  = (const float*)d_in[12];
    const float* W_proj = (const float*)d_in[13];
    const float* b_proj = (const float*)d_in[14];

    float* out      = (float*)d_out;
    float* out_cls  = out + (size_t)NROW*EMB;
    float* out_proj = out_cls + (size_t)NROW*NCLS;

    void *p_rel, *p_ht, *p_biasht;
    void *p_WbHi, *p_WbLo, *p_WhtHi, *p_WhtLo, *p_seqHi, *p_seqLo;
    void *p_htaHi, *p_htaLo, *p_XHi, *p_XLo;
    cudaGetSymbolAddress(&p_rel,   g_rel);
    cudaGetSymbolAddress(&p_ht,    g_ht);
    cudaGetSymbolAddress(&p_biasht,g_bias_ht);
    cudaGetSymbolAddress(&p_WbHi,  g_WbilHi);
    cudaGetSymbolAddress(&p_WbLo,  g_WbilLo);
    cudaGetSymbolAddress(&p_WhtHi, g_WhtHi);
    cudaGetSymbolAddress(&p_WhtLo, g_WhtLo);
    cudaGetSymbolAddress(&p_seqHi, g_seqTHi);
    cudaGetSymbolAddress(&p_seqLo, g_seqTLo);
    cudaGetSymbolAddress(&p_htaHi, g_htaHi);
    cudaGetSymbolAddress(&p_htaLo, g_htaLo);
    cudaGetSymbolAddress(&p_XHi,   g_XHi);
    cudaGetSymbolAddress(&p_XLo,   g_XLo);

    cudaFuncSetAttribute(k_bilinear_mma,
                         cudaFuncAttributeMaxDynamicSharedMemorySize, BIL_SMEM);
    cudaFuncSetAttribute(k_gemm_split<0>,
                         cudaFuncAttributeMaxDynamicSharedMemorySize, 131072);
    cudaFuncSetAttribute(k_gemm_split<1>,
                         cudaFuncAttributeMaxDynamicSharedMemorySize, 131072);

    static cudaStream_t s1 = nullptr;
    static cudaEvent_t evFork = nullptr, evJoin = nullptr;
    if (!s1) {
        cudaStreamCreateWithFlags(&s1, cudaStreamNonBlocking);
        cudaEventCreateWithFlags(&evFork, cudaEventDisableTiming);
        cudaEventCreateWithFlags(&evJoin, cudaEventDisableTiming);
    }

    cudaEventRecord(evFork, 0);
    cudaStreamWaitEvent(s1, evFork, 0);

    // ---- weight preprocessing on s1 (concurrent with pooling chain)
    k_bias2<<<3, 256, 0, s1>>>(b_head, b_tail);
    k_splitT<0><<<dim3(2*HID/128, EMB/64), 256, 0, s1>>>(W_head,
        (uint32_t*)p_WhtHi, (uint32_t*)p_WhtLo, 2*HID, EMB, 0, 0);
    k_splitT<0><<<dim3(2*HID/128, EMB/64), 256, 0, s1>>>(W_tail,
        (uint32_t*)p_WhtHi + (size_t)EMB*HID, (uint32_t*)p_WhtLo + (size_t)EMB*HID,
        2*HID, EMB, 0, 0);
    k_splitT<1><<<dim3(KBIL/128, EMB/64), 256, 0, s1>>>(W_bil,
        (uint32_t*)p_WbHi, (uint32_t*)p_WbLo, KBIL, EMB, 0, 0);
    cudaEventRecord(evJoin, s1);

    // ---- pooling chain + rel on default stream
    k_splitT<0><<<dim3(Lseq/128, HID/64, Bdoc), 256>>>(seq,
        (uint32_t*)p_seqHi, (uint32_t*)p_seqLo, Lseq, HID,
        (long)Lseq*HID, (long)HID*(Lseq/2));
    k_ent_emb<<<dim3(NE, Bdoc), 256>>>(ent, labels);
    k_attn_mean<<<dim3(NE, NH, Bdoc), 256>>>(attn, labels);
    k_hta<<<dim3(Rht, Bdoc), 256>>>(hts);

    k_gemm_split<0><<<dim3(HID/128, Rht/128, Bdoc), 256, 131072>>>(
        (const uint32_t*)p_htaHi, (const uint32_t*)p_htaLo,
        (const uint32_t*)p_seqHi, (const uint32_t*)p_seqLo,
        nullptr, (float*)p_rel,
        Lseq, HID, (long)Rht*(Lseq/2), (long)HID*(Lseq/2), (long)Rht*HID);

    k_gather<<<NROW, 256>>>(hts);

    cudaStreamWaitEvent(0, evJoin, 0);

    // h and t in one launch (z = head/tail)
    k_gemm_split<1><<<dim3(EMB/128, NROW/128, 2), 256, 131072>>>(
        (const uint32_t*)p_XHi, (const uint32_t*)p_XLo,
        (const uint32_t*)p_WhtHi, (const uint32_t*)p_WhtLo,
        (const float*)p_biasht, (float*)p_ht,
        2*HID, EMB, (long)NROW*HID, (long)EMB*HID, (long)NROW*EMB);

    // bilinear (fp16 2-pass) -> d_out (embeds)
    k_bilinear_mma<<<dim3(EMB/96, NROW/128), 256, BIL_SMEM>>>(
        (const float*)p_ht, (const float*)p_ht + (size_t)NROW*EMB, b_bil, out);

    // class / proj logits
    sgemm<64,32,16,4,4,0><<<dim3((NCLS+31)/32, NROW/64), 128>>>(
        out, W_cls, b_cls, out_cls, NROW, NCLS, EMB);
    sgemm<64,32,16,4,4,1><<<dim3(NPROJ/32, NROW/64), 128>>>(
        out, W_proj, b_proj, out_proj, NROW, NPROJ, EMB);
}

// round 7
// speedup vs baseline: 5.6567x; 1.2308x over previous
#include <cuda_runtime.h>
#include <cuda_bf16.h>
#include <cuda_fp16.h>
#include <math.h>
#include <stdint.h>

// ---------------- problem constants ----------------
#define Bdoc 4
#define Lseq 1024
#define Ment 128
#define Rht  512
#define HID  1024
#define NH   16
#define NE   42
#define EMB  768
#define NBLK 12
#define NCLS 97
#define NPROJ 128
#define NROW (Bdoc*Rht)   // 2048
#define KBIL (EMB*64)     // 49152
#define NCHUNK (NBLK*64)  // 768

// ---------------- scratch ----------------
__device__ float g_ent_emb[Bdoc*NE*HID];
__device__ float g_attn_mean[Bdoc*NE*NH*Lseq];
__device__ float g_rel[NROW*HID];
__device__ float g_ht[2*NROW*EMB];                    // h then t (fp32)
__device__ float g_bias_ht[2*EMB];
// packed 16-bit x2 operands
__device__ uint32_t g_WbilHi[(size_t)EMB*KBIL/2];     // fp16 pairs, 75.5 MB
__device__ uint32_t g_WhtHi[2*EMB*HID];               // bf16 [2][768][1024]
__device__ uint32_t g_WhtLo[2*EMB*HID];
__device__ uint32_t g_seqTHi[Bdoc*HID*Lseq/2];
__device__ uint32_t g_seqTLo[Bdoc*HID*Lseq/2];
__device__ uint32_t g_htaHi[NROW*Lseq/2];
__device__ uint32_t g_htaLo[NROW*Lseq/2];
__device__ uint32_t g_XHi[2*NROW*HID];
__device__ uint32_t g_XLo[2*NROW*HID];

// ---------------- helpers ----------------
__device__ __forceinline__ uint32_t smem_u32(const void* p) {
    uint32_t a;
    asm("{ .reg .u64 t; cvta.to.shared.u64 t, %1; cvt.u32.u64 %0, t; }"
        : "=r"(a) : "l"(p));
    return a;
}
#define SWZ(o) ((o) ^ ((((uint32_t)(o))>>3)&0x70))

#define MMA16816(d, a0,a1,a2,a3, b0,b1) \
    asm volatile("mma.sync.aligned.m16n8k16.row.col.f32.bf16.bf16.f32 " \
        "{%0,%1,%2,%3},{%4,%5,%6,%7},{%8,%9},{%0,%1,%2,%3};" \
        : "+f"((d)[0]), "+f"((d)[1]), "+f"((d)[2]), "+f"((d)[3]) \
        : "r"(a0), "r"(a1), "r"(a2), "r"(a3), "r"(b0), "r"(b1))

#define MMA16816H(d, a0,a1,a2,a3, b0,b1) \
    asm volatile("mma.sync.aligned.m16n8k16.row.col.f32.f16.f16.f32 " \
        "{%0,%1,%2,%3},{%4,%5,%6,%7},{%8,%9},{%0,%1,%2,%3};" \
        : "+f"((d)[0]), "+f"((d)[1]), "+f"((d)[2]), "+f"((d)[3]) \
        : "r"(a0), "r"(a1), "r"(a2), "r"(a3), "r"(b0), "r"(b1))

#define LDX4(r, addr) \
    asm volatile("ldmatrix.sync.aligned.m8n8.x4.shared.b16 {%0,%1,%2,%3},[%4];" \
        : "=r"((r)[0]), "=r"((r)[1]), "=r"((r)[2]), "=r"((r)[3]) : "r"(addr))

#define CPA16(dst, src) \
    asm volatile("cp.async.cg.shared.global [%0], [%1], 16;" :: "r"(dst), "l"(src))

__device__ __forceinline__ uint32_t pack_bf2(float x, float y) {
    uint32_t r;
    asm("cvt.rn.bf16x2.f32 %0, %1, %2;" : "=r"(r) : "f"(y), "f"(x));
    return r;
}
__device__ __forceinline__ uint32_t pack_h2(float x, float y) {
    uint32_t r;
    asm("cvt.rn.f16x2.f32 %0, %1, %2;" : "=r"(r) : "f"(y), "f"(x));
    return r;
}
__device__ __forceinline__ float lo_f(uint32_t u) { return __uint_as_float(u << 16); }
__device__ __forceinline__ float hi_f(uint32_t u) { return __uint_as_float(u & 0xffff0000u); }
__device__ __forceinline__ void split2(float x, float y, uint32_t& hp, uint32_t& lp) {
    hp = pack_bf2(x, y);
    lp = pack_bf2(x - lo_f(hp), y - hi_f(hp));
}

// ---------------- K1: entity logsumexp pooling ----------------
__global__ void k_ent_emb(const float* __restrict__ ent,
                          const int* __restrict__ labels)
{
    int e = blockIdx.x, b = blockIdx.y;
    __shared__ int s_idx[Ment];
    __shared__ int s_cnt;
    int tid = threadIdx.x;
    if (tid == 0) {
        int c = 0;
        for (int i = 0; i < Ment; i++)
            if (labels[b*Ment + i] == e) s_idx[c++] = i;
        s_cnt = c;
    }
    __syncthreads();
    int cnt = s_cnt;
    const float* eb = ent + (size_t)b*Ment*HID;
    float* out = g_ent_emb + ((size_t)(b*NE + e))*HID;
    for (int d = tid; d < HID; d += blockDim.x) {
        float r;
        if (cnt == 0) {
            r = 0.f;
        } else {
            float mx = -3.4e38f, s = 0.f;
            for (int i = 0; i < cnt; i++) {
                float v = eb[(size_t)s_idx[i]*HID + d];
                if (v > mx) { s = s*expf(mx - v) + 1.f; mx = v; }
                else        { s += expf(v - mx); }
            }
            r = mx + logf(s);
        }
        out[d] = r;
    }
}

// ---------------- K2: per-entity mean attention ----------------
__global__ void k_attn_mean(const float* __restrict__ attn,
                            const int* __restrict__ labels)
{
    int e = blockIdx.x, h = blockIdx.y, b = blockIdx.z;
    __shared__ int s_idx[Ment];
    __shared__ int s_cnt;
    int tid = threadIdx.x;
    if (tid == 0) {
        int c = 0;
        for (int i = 0; i < Ment; i++)
            if (labels[b*Ment + i] == e) s_idx[c++] = i;
        s_cnt = c;
    }
    __syncthreads();
    int cnt = s_cnt;
    float inv = 1.f / (float)(cnt > 0 ? cnt : 1);
    const float* ab = attn + (((size_t)b*NH + h)*Ment)*Lseq;
    float* out = g_attn_mean + (((size_t)(b*NE + e))*NH + h)*Lseq;
    for (int l = tid; l < Lseq; l += blockDim.x) {
        float s = 0.f;
        for (int i = 0; i < cnt; i++) s += ab[(size_t)s_idx[i]*Lseq + l];
        out[l] = s * inv;
    }
}

// ---------------- K3: hta -> split bf16 ----------------
__global__ void k_hta(const int* __restrict__ hts)
{
    int r = blockIdx.x, b = blockIdx.y;
    int r2 = b*Rht + r;
    int e0 = hts[(size_t)r2*2 + 0];
    int e1 = hts[(size_t)r2*2 + 1];
    const float* a0 = g_attn_mean + ((size_t)(b*NE + e0))*NH*Lseq;
    const float* a1 = g_attn_mean + ((size_t)(b*NE + e1))*NH*Lseq;
    int tid = threadIdx.x;
    int l0 = tid*4;
    float4 acc = make_float4(0.f,0.f,0.f,0.f);
#pragma unroll
    for (int h = 0; h < NH; h++) {
        float4 x = *(const float4*)&a0[h*Lseq + l0];
        float4 y = *(const float4*)&a1[h*Lseq + l0];
        acc.x += x.x*y.x; acc.y += x.y*y.y;
        acc.z += x.z*y.z; acc.w += x.w*y.w;
    }
    acc.x *= (1.f/NH); acc.y *= (1.f/NH); acc.z *= (1.f/NH); acc.w *= (1.f/NH);
    __shared__ float red[256];
    red[tid] = acc.x + acc.y + acc.z + acc.w;
    __syncthreads();
    for (int o = 128; o > 0; o >>= 1) {
        if (tid < o) red[tid] += red[tid + o];
        __syncthreads();
    }
    float sc = 1.f / (red[0] + 1e-5f);
    uint32_t h0, l0p, h1, l1p;
    split2(acc.x*sc, acc.y*sc, h0, l0p);
    split2(acc.z*sc, acc.w*sc, h1, l1p);
    size_t o = (size_t)r2*(Lseq/2) + tid*2;
    g_htaHi[o] = h0;  g_htaHi[o+1] = h1;
    g_htaLo[o] = l0p; g_htaLo[o+1] = l1p;
}

// ---------------- K5: gather -> split bf16 X ----------------
__global__ void k_gather(const int* __restrict__ hts)
{
    int r2 = blockIdx.x;
    int b = r2 / Rht;
    int e0 = hts[(size_t)r2*2 + 0];
    int e1 = hts[(size_t)r2*2 + 1];
    const float* emb0 = g_ent_emb + ((size_t)(b*NE + e0))*HID;
    const float* emb1 = g_ent_emb + ((size_t)(b*NE + e1))*HID;
    const float* rel  = g_rel + (size_t)r2*HID;
    for (int u = threadIdx.x; u < HID; u += 256) {
        uint32_t hp, lp;
        if (u < HID/2) {
            float2 v0 = *(const float2*)&emb0[2*u];
            split2(v0.x, v0.y, hp, lp);
            g_XHi[(size_t)r2*HID + u] = hp;
            g_XLo[(size_t)r2*HID + u] = lp;
            float2 v1 = *(const float2*)&emb1[2*u];
            split2(v1.x, v1.y, hp, lp);
            g_XHi[(size_t)(NROW + r2)*HID + u] = hp;
            g_XLo[(size_t)(NROW + r2)*HID + u] = lp;
        } else {
            float2 rv = *(const float2*)&rel[2*u - HID];
            split2(rv.x, rv.y, hp, lp);
            g_XHi[(size_t)r2*HID + u] = hp;
            g_XLo[(size_t)r2*HID + u] = lp;
            g_XHi[(size_t)(NROW + r2)*HID + u] = hp;
            g_XLo[(size_t)(NROW + r2)*HID + u] = lp;
        }
    }
}

// ---------------- split + transpose: [z][K][N] f32 -> [z][N][K/2] 16bitx2 ----
// FMT 0 = bf16 hi/lo, FMT 2 = fp16 hi only
template<int FMT>
__global__ void __launch_bounds__(256)
k_splitT(const float* __restrict__ in,
         uint32_t* __restrict__ outHi, uint32_t* __restrict__ outLo,
         int K, int N, long sIn, long sOut)
{
    __shared__ float s[128][65];
    in    += (size_t)blockIdx.z * sIn;
    outHi += (size_t)blockIdx.z * sOut;
    if (FMT == 0) outLo += (size_t)blockIdx.z * sOut;
    int k0 = blockIdx.x*128, n0 = blockIdx.y*64;
    int tid = threadIdx.x;
#pragma unroll
    for (int u = 0; u < 8; u++) {
        int idx = tid + u*256;
        int kk = idx >> 4;
        int cc = (idx & 15) * 4;
        float4 v = *(const float4*)&in[(size_t)(k0+kk)*N + n0 + cc];
        s[kk][cc+0] = v.x; s[kk][cc+1] = v.y;
        s[kk][cc+2] = v.z; s[kk][cc+3] = v.w;
    }
    __syncthreads();
    int K2 = K >> 1;
#pragma unroll
    for (int u = 0; u < 4; u++) {
        int idx = tid + u*256;
        int nn = idx >> 4, q = idx & 15;
        uint32_t hi[4], lo[4];
#pragma unroll
        for (int i = 0; i < 4; i++) {
            if (FMT == 0) split2(s[q*8 + i*2][nn], s[q*8 + i*2 + 1][nn], hi[i], lo[i]);
            else          hi[i] = pack_h2(s[q*8 + i*2][nn], s[q*8 + i*2 + 1][nn]);
        }
        size_t o = (size_t)(n0+nn)*K2 + (k0 >> 1) + q*4;
        *(uint4*)&outHi[o] = make_uint4(hi[0], hi[1], hi[2], hi[3]);
        if (FMT == 0)
            *(uint4*)&outLo[o] = make_uint4(lo[0], lo[1], lo[2], lo[3]);
    }
}

__global__ void k_bias2(const float* __restrict__ b0, const float* __restrict__ b1)
{
    int i = threadIdx.x + blockIdx.x*256;
    if (i < EMB) { g_bias_ht[i] = b0[i]; g_bias_ht[EMB+i] = b1[i]; }
}

// ---------------- generic 3-split bf16 mma GEMM ----------------
template<int ACT>
__global__ void __launch_bounds__(256, 1)
k_gemm_split(const uint32_t* __restrict__ Ahi, const uint32_t* __restrict__ Alo,
             const uint32_t* __restrict__ Bhi, const uint32_t* __restrict__ Blo,
             const float* __restrict__ bias, float* __restrict__ C,
             int K, int N, long sA, long sB, long sC)
{
    extern __shared__ char smem[];
    uint32_t sb = smem_u32(smem);
    int tid = threadIdx.x, lid = tid & 31, wid = tid >> 5;
    int row0 = blockIdx.y*128, col0 = blockIdx.x*128;
    Ahi += (size_t)blockIdx.z * sA;  Alo += (size_t)blockIdx.z * sA;
    Bhi += (size_t)blockIdx.z * sB;  Blo += (size_t)blockIdx.z * sB;
    C   += (size_t)blockIdx.z * sC;
    const float* bz = bias ? bias + (size_t)blockIdx.z * N : nullptr;
    int K2 = K >> 1, nchunk = K >> 6;
    int wm = (wid >> 1)*32, wn = (wid & 1)*64;
    int msel = lid >> 3, r8 = lid & 7;

    float acc[2][8][4];
#pragma unroll
    for (int i = 0; i < 2; i++)
#pragma unroll
        for (int n = 0; n < 8; n++)
#pragma unroll
            for (int q = 0; q < 4; q++) acc[i][n][q] = 0.f;

#define GLOAD(c) { \
    uint32_t base = sb + (uint32_t)((c)&1)*65536u; \
    _Pragma("unroll") \
    for (int p = 0; p < 4; p++) { \
        int idx = tid + p*256; int r = idx >> 3, seg = idx & 7; \
        uint32_t off = SWZ((uint32_t)(r*128 + seg*16)); \
        size_t goA = (size_t)(row0+r)*K2 + (size_t)(c)*32 + seg*4; \
        size_t goB = (size_t)(col0+r)*K2 + (size_t)(c)*32 + seg*4; \
        CPA16(base + off,          Ahi + goA); \
        CPA16(base + 16384u + off, Alo + goA); \
        CPA16(base + 32768u + off, Bhi + goB); \
        CPA16(base + 49152u + off, Blo + goB); \
    } }

    GLOAD(0);
    asm volatile("cp.async.commit_group;");

#pragma unroll 1
    for (int c = 0; c < nchunk; ++c) {
        if (c + 1 < nchunk) GLOAD(c + 1);
        asm volatile("cp.async.commit_group;");
        asm volatile("cp.async.wait_group 1;");
        __syncthreads();

        uint32_t abase = sb + (uint32_t)(c & 1)*65536u;
        uint32_t bbase = abase + 32768u;
#pragma unroll
        for (int s = 0; s < 4; ++s) {
            uint32_t ah[2][4], al[2][4];
#pragma unroll
            for (int i = 0; i < 2; ++i) {
                uint32_t off = SWZ((uint32_t)((wm + i*16 + (lid & 15))*128
                                              + s*32 + (lid >> 4)*16));
                LDX4(ah[i], abase + off);
                LDX4(al[i], abase + 16384u + off);
            }
            uint32_t bh[16], bl[16];
#pragma unroll
            for (int pq = 0; pq < 4; ++pq) {
                uint32_t off = SWZ((uint32_t)((wn + (pq*2 + (msel >> 1))*8 + r8)*128
                                              + s*32 + (msel & 1)*16));
                LDX4(&bh[pq*4], bbase + off);
                LDX4(&bl[pq*4], bbase + 16384u + off);
            }
#pragma unroll
            for (int i = 0; i < 2; ++i)
#pragma unroll
                for (int n = 0; n < 8; ++n) {
                    MMA16816(acc[i][n], ah[i][0],ah[i][1],ah[i][2],ah[i][3], bh[n*2], bh[n*2+1]);
                    MMA16816(acc[i][n], ah[i][0],ah[i][1],ah[i][2],ah[i][3], bl[n*2], bl[n*2+1]);
                    MMA16816(acc[i][n], al[i][0],al[i][1],al[i][2],al[i][3], bh[n*2], bh[n*2+1]);
                }
        }
        __syncthreads();
    }
#undef GLOAD

#pragma unroll
    for (int i = 0; i < 2; ++i) {
        int gr = row0 + wm + i*16 + (lid >> 2);
#pragma unroll
        for (int n = 0; n < 8; ++n) {
            int gc = col0 + wn + n*8 + (lid & 3)*2;
            float b0v = bz ? bz[gc] : 0.f, b1v = bz ? bz[gc+1] : 0.f;
            float v0 = acc[i][n][0] + b0v, v1 = acc[i][n][1] + b1v;
            float v2 = acc[i][n][2] + b0v, v3 = acc[i][n][3] + b1v;
            if (ACT == 1) { v0 = tanhf(v0); v1 = tanhf(v1); v2 = tanhf(v2); v3 = tanhf(v3); }
            *(float2*)&C[(size_t)gr*N + gc]     = make_float2(v0, v1);
            *(float2*)&C[(size_t)(gr+8)*N + gc] = make_float2(v2, v3);
        }
    }
}

// ---------------- fp32 SIMT sgemm (small tails: cls/proj) ----------------
template<int BM, int BN, int BK, int TM, int TN, int ACT>
__global__ __launch_bounds__((BM/TM)*(BN/TN))
void sgemm(const float* __restrict__ A, const float* __restrict__ B,
           const float* __restrict__ bias, float* __restrict__ C,
           int M, int N, int K)
{
    constexpr int THREADS = (BM/TM)*(BN/TN);
    __shared__ float As[BK][BM + 4];
    __shared__ float Bs[BK][BN];
    int tid = threadIdx.x;
    int tx = tid % (BN/TN);
    int ty = tid / (BN/TN);
    int row0 = blockIdx.y * BM, col0 = blockIdx.x * BN;
    float acc[TM][TN] = {};
    constexpr int AE = BM*BK/THREADS;
    constexpr int BE = BK*BN/THREADS;

    for (int k0 = 0; k0 < K; k0 += BK) {
#pragma unroll
        for (int u = 0; u < AE; u++) {
            int idx = tid + u*THREADS;
            int r = idx / BK, c = idx % BK;
            float v = 0.f;
            int gr = row0 + r;
            if (gr < M) v = A[(size_t)gr*K + k0 + c];
            As[c][r] = v;
        }
#pragma unroll
        for (int u = 0; u < BE; u++) {
            int idx = tid + u*THREADS;
            int r = idx / BN, c = idx % BN;
            float v = 0.f;
            int gc = col0 + c;
            if (gc < N) v = B[(size_t)(k0 + r)*N + gc];
            Bs[r][c] = v;
        }
        __syncthreads();
#pragma unroll
        for (int kk = 0; kk < BK; kk++) {
            float af[TM], bf[TN];
#pragma unroll
            for (int i = 0; i < TM; i += 4)
                *reinterpret_cast<float4*>(&af[i]) =
                    *reinterpret_cast<const float4*>(&As[kk][ty*TM + i]);
#pragma unroll
            for (int j = 0; j < TN; j += 4)
                *reinterpret_cast<float4*>(&bf[j]) =
                    *reinterpret_cast<const float4*>(&Bs[kk][tx*TN + j]);
#pragma unroll
            for (int i = 0; i < TM; i++)
#pragma unroll
                for (int j = 0; j < TN; j++)
                    acc[i][j] += af[i] * bf[j];
        }
        __syncthreads();
    }
#pragma unroll
    for (int i = 0; i < TM; i++) {
        int gr = row0 + ty*TM + i;
        if (gr >= M) continue;
#pragma unroll
        for (int j = 0; j < TN; j++) {
            int gc = col0 + tx*TN + j;
            if (gc >= N) continue;
            float v = acc[i][j];
            if (bias) v += bias[gc];
            if (ACT == 1) v = tanhf(v);
            C[(size_t)gr*N + gc] = v;
        }
    }
}

// ---------------- bilinear GEMM via fp16 mma (1-pass, N-tile 96) ----------
#define BIL_SH_OFF 24576
#define BIL_ST_OFF (24576 + 34816)
#define BIL_SMEM   (24576 + 2*34816)   // 94208

__device__ __forceinline__ void bil_load_B(uint32_t sb, int c, int col0, int tid)
{
    uint32_t dH = sb + (uint32_t)(c & 1)*12288u;
#pragma unroll
    for (int p = 0; p < 3; p++) {
        int idx = tid + p*256;
        int n = idx >> 3, seg = idx & 7;
        size_t go = (size_t)(col0 + n)*(KBIL/2) + (size_t)c*32 + seg*4;
        uint32_t off = SWZ((uint32_t)(n*128 + seg*16));
        CPA16(dH + off, g_WbilHi + go);
    }
}

__global__ void __launch_bounds__(256, 1)
k_bilinear_mma(const float* __restrict__ h, const float* __restrict__ t,
               const float* __restrict__ bias, float* __restrict__ out)
{
    extern __shared__ char smem[];
    uint32_t sb = smem_u32(smem);
    float* s_h = (float*)(smem + BIL_SH_OFF);   // [128][68]
    float* s_t = (float*)(smem + BIL_ST_OFF);   // [128][68]
    int tid = threadIdx.x, lid = tid & 31, wid = tid >> 5;
    int row0 = blockIdx.y * 128, col0 = blockIdx.x * 96;
    int wm = (wid >> 1) * 32;
    int wn = (wid & 1) * 48;

    float acc[2][6][4];
#pragma unroll
    for (int i = 0; i < 2; i++)
#pragma unroll
        for (int n = 0; n < 6; n++)
#pragma unroll
            for (int q = 0; q < 4; q++) acc[i][n][q] = 0.f;

    bil_load_B(sb, 0, col0, tid);
    asm volatile("cp.async.commit_group;");

#pragma unroll 1
    for (int c = 0; c < NCHUNK; ++c) {
        int j = c >> 6, a = c & 63, buf = c & 1;

        if (c + 1 < NCHUNK) bil_load_B(sb, c + 1, col0, tid);
        asm volatile("cp.async.commit_group;");
        asm volatile("cp.async.wait_group 1;");

        if (a == 0) {
            for (int idx = tid; idx < 128*16; idx += 256) {
                int rr = idx >> 4, cc = (idx & 15) * 4;
                *(float4*)&s_h[rr*68 + cc] =
                    *(const float4*)&h[(size_t)(row0+rr)*EMB + j*64 + cc];
                *(float4*)&s_t[rr*68 + cc] =
                    *(const float4*)&t[(size_t)(row0+rr)*EMB + j*64 + cc];
            }
        }
        __syncthreads();

        uint32_t bbase = sb + (uint32_t)buf*12288u;
        float h0[2], h1[2];
#pragma unroll
        for (int i = 0; i < 2; i++) {
            int r0 = wm + i*16 + (lid >> 2);
            h0[i] = s_h[r0*68 + a];
            h1[i] = s_h[(r0 + 8)*68 + a];
        }

        int msel = lid >> 3, r8 = lid & 7;
#pragma unroll
        for (int s = 0; s < 4; ++s) {
            uint32_t bh[12];
#pragma unroll
            for (int pq = 0; pq < 3; ++pq) {
                uint32_t off = SWZ((uint32_t)((wn + (pq*2 + (msel >> 1))*8 + r8)*128
                                              + s*32 + (msel & 1)*16));
                LDX4(&bh[pq*4], bbase + off);
            }
#pragma unroll
            for (int i = 0; i < 2; ++i) {
                int rb = (wm + i*16 + (lid >> 2))*68;
                int cc = s*16 + (lid & 3)*2;
                float2 ta = *(float2*)&s_t[rb + cc];
                float2 tb = *(float2*)&s_t[rb + cc + 8];
                float2 tc = *(float2*)&s_t[rb + 8*68 + cc];
                float2 td = *(float2*)&s_t[rb + 8*68 + cc + 8];
                uint32_t ah[4];
                ah[0] = pack_h2(h0[i]*ta.x, h0[i]*ta.y);
                ah[1] = pack_h2(h1[i]*tc.x, h1[i]*tc.y);
                ah[2] = pack_h2(h0[i]*tb.x, h0[i]*tb.y);
                ah[3] = pack_h2(h1[i]*td.x, h1[i]*td.y);
#pragma unroll
                for (int n = 0; n < 6; ++n)
                    MMA16816H(acc[i][n], ah[0],ah[1],ah[2],ah[3], bh[n*2], bh[n*2+1]);
            }
        }
        __syncthreads();
    }

#pragma unroll
    for (int i = 0; i < 2; ++i) {
        int gr = row0 + wm + i*16 + (lid >> 2);
#pragma unroll
        for (int n = 0; n < 6; ++n) {
            int gc = col0 + wn + n*8 + (lid & 3)*2;
            float2 v0 = make_float2(acc[i][n][0] + bias[gc],
                                    acc[i][n][1] + bias[gc+1]);
            float2 v1 = make_float2(acc[i][n][2] + bias[gc],
                                    acc[i][n][3] + bias[gc+1]);
            *(float2*)&out[(size_t)gr*EMB + gc]     = v0;
            *(float2*)&out[(size_t)(gr+8)*EMB + gc] = v1;
        }
    }
}

// ---------------- launch ----------------
extern "C" void kernel_launch(void* const* d_in, const int* in_sizes, int n_in,
                              void* d_out, int out_size)
{
    const float* seq    = (const float*)d_in[0];
    const float* ent    = (const float*)d_in[1];
    const float* attn   = (const float*)d_in[2];
    const int*   labels = (const int*)  d_in[3];
    const int*   hts    = (const int*)  d_in[4];
    const float* W_head = (const float*)d_in[5];
    const float* b_head = (const float*)d_in[6];
    const float* W_tail = (const float*)d_in[7];
    const float* b_tail = (const float*)d_in[8];
    const float* W_bil  = (const float*)d_in[9];
    const float* b_bil  = (const float*)d_in[10];
    const float* W_cls  = (const float*)d_in[11];
    const float* b_cls  = (const float*)d_in[12];
    const float* W_proj = (const float*)d_in[13];
    const float* b_proj = (const float*)d_in[14];

    float* out      = (float*)d_out;
    float* out_cls  = out + (size_t)NROW*EMB;
    float* out_proj = out_cls + (size_t)NROW*NCLS;

    void *p_rel, *p_ht, *p_biasht;
    void *p_WbHi, *p_WhtHi, *p_WhtLo, *p_seqHi, *p_seqLo;
    void *p_htaHi, *p_htaLo, *p_XHi, *p_XLo;
    cudaGetSymbolAddress(&p_rel,   g_rel);
    cudaGetSymbolAddress(&p_ht,    g_ht);
    cudaGetSymbolAddress(&p_biasht,g_bias_ht);
    cudaGetSymbolAddress(&p_WbHi,  g_WbilHi);
    cudaGetSymbolAddress(&p_WhtHi, g_WhtHi);
    cudaGetSymbolAddress(&p_WhtLo, g_WhtLo);
    cudaGetSymbolAddress(&p_seqHi, g_seqTHi);
    cudaGetSymbolAddress(&p_seqLo, g_seqTLo);
    cudaGetSymbolAddress(&p_htaHi, g_htaHi);
    cudaGetSymbolAddress(&p_htaLo, g_htaLo);
    cudaGetSymbolAddress(&p_XHi,   g_XHi);
    cudaGetSymbolAddress(&p_XLo,   g_XLo);

    cudaFuncSetAttribute(k_bilinear_mma,
                         cudaFuncAttributeMaxDynamicSharedMemorySize, BIL_SMEM);
    cudaFuncSetAttribute(k_gemm_split<0>,
                         cudaFuncAttributeMaxDynamicSharedMemorySize, 131072);
    cudaFuncSetAttribute(k_gemm_split<1>,
                         cudaFuncAttributeMaxDynamicSharedMemorySize, 131072);

    static cudaStream_t s1 = nullptr;
    static cudaEvent_t evFork = nullptr, evJoin = nullptr;
    if (!s1) {
        cudaStreamCreateWithFlags(&s1, cudaStreamNonBlocking);
        cudaEventCreateWithFlags(&evFork, cudaEventDisableTiming);
        cudaEventCreateWithFlags(&evJoin, cudaEventDisableTiming);
    }

    cudaEventRecord(evFork, 0);
    cudaStreamWaitEvent(s1, evFork, 0);

    // ---- weight preprocessing on s1 (concurrent with pooling chain)
    k_bias2<<<3, 256, 0, s1>>>(b_head, b_tail);
    k_splitT<0><<<dim3(2*HID/128, EMB/64), 256, 0, s1>>>(W_head,
        (uint32_t*)p_WhtHi, (uint32_t*)p_WhtLo, 2*HID, EMB, 0, 0);
    k_splitT<0><<<dim3(2*HID/128, EMB/64), 256, 0, s1>>>(W_tail,
        (uint32_t*)p_WhtHi + (size_t)EMB*HID, (uint32_t*)p_WhtLo + (size_t)EMB*HID,
        2*HID, EMB, 0, 0);
    k_splitT<2><<<dim3(KBIL/128, EMB/64), 256, 0, s1>>>(W_bil,
        (uint32_t*)p_WbHi, nullptr, KBIL, EMB, 0, 0);
    cudaEventRecord(evJoin, s1);

    // ---- pooling chain + rel on default stream
    k_splitT<0><<<dim3(Lseq/128, HID/64, Bdoc), 256>>>(seq,
        (uint32_t*)p_seqHi, (uint32_t*)p_seqLo, Lseq, HID,
        (long)Lseq*HID, (long)HID*(Lseq/2));
    k_ent_emb<<<dim3(NE, Bdoc), 256>>>(ent, labels);
    k_attn_mean<<<dim3(NE, NH, Bdoc), 256>>>(attn, labels);
    k_hta<<<dim3(Rht, Bdoc), 256>>>(hts);

    k_gemm_split<0><<<dim3(HID/128, Rht/128, Bdoc), 256, 131072>>>(
        (const uint32_t*)p_htaHi, (const uint32_t*)p_htaLo,
        (const uint32_t*)p_seqHi, (const uint32_t*)p_seqLo,
        nullptr, (float*)p_rel,
        Lseq, HID, (long)Rht*(Lseq/2), (long)HID*(Lseq/2), (long)Rht*HID);

    k_gather<<<NROW, 256>>>(hts);

    cudaStreamWaitEvent(0, evJoin, 0);

    // h and t in one launch (z = head/tail)
    k_gemm_split<1><<<dim3(EMB/128, NROW/128, 2), 256, 131072>>>(
        (const uint32_t*)p_XHi, (const uint32_t*)p_XLo,
        (const uint32_t*)p_WhtHi, (const uint32_t*)p_WhtLo,
        (const float*)p_biasht, (float*)p_ht,
        2*HID, EMB, (long)NROW*HID, (long)EMB*HID, (long)NROW*EMB);

    // bilinear (fp16 1-pass) -> d_out (embeds)
    k_bilinear_mma<<<dim3(EMB/96, NROW/128), 256, BIL_SMEM>>>(
        (const float*)p_ht, (const float*)p_ht + (size_t)NROW*EMB, b_bil, out);

    // class / proj logits
    sgemm<64,32,16,4,4,0><<<dim3((NCLS+31)/32, NROW/64), 128>>>(
        out, W_cls, b_cls, out_cls, NROW, NCLS, EMB);
    sgemm<64,32,16,4,4,1><<<dim3(NPROJ/32, NROW/64), 128>>>(
        out, W_proj, b_proj, out_proj, NROW, NPROJ, EMB);
}

// round 8
// speedup vs baseline: 6.1379x; 1.0851x over previous
#include <cuda_runtime.h>
#include <cuda_bf16.h>
#include <cuda_fp16.h>
#include <math.h>
#include <stdint.h>

// ---------------- problem constants ----------------
#define Bdoc 4
#define Lseq 1024
#define Ment 128
#define Rht  512
#define HID  1024
#define NH   16
#define NE   42
#define EMB  768
#define NBLK 12
#define NCLS 97
#define NPROJ 128
#define NROW (Bdoc*Rht)   // 2048
#define KBIL (EMB*64)     // 49152
#define NCHUNK (NBLK*64)  // 768

// ---------------- scratch ----------------
__device__ float g_ent_emb[Bdoc*NE*HID];
__device__ float g_attn_mean[Bdoc*NE*NH*Lseq];
__device__ float g_rel[NROW*HID];
__device__ float g_ht[2*NROW*EMB];                    // h then t (fp32)
__device__ float g_bias_ht[2*EMB];
// packed fp16x2 operands
__device__ uint32_t g_WbilHi[(size_t)EMB*KBIL/2];     // fp16, 75.5 MB
__device__ uint32_t g_WhtHi[2*EMB*HID];               // fp16 hi [2][768][1024]
__device__ uint32_t g_WhtLo[2*EMB*HID];               // fp16 lo
__device__ uint32_t g_seqTHi[Bdoc*HID*Lseq/2];        // fp16 hi
__device__ uint32_t g_seqTLo[Bdoc*HID*Lseq/2];        // fp16 lo
__device__ uint32_t g_htaH[NROW*Lseq/2];              // fp16 single
__device__ uint32_t g_XH[2*NROW*HID];                 // fp16 single [2][2048][1024]

// ---------------- helpers ----------------
__device__ __forceinline__ uint32_t smem_u32(const void* p) {
    uint32_t a;
    asm("{ .reg .u64 t; cvta.to.shared.u64 t, %1; cvt.u32.u64 %0, t; }"
        : "=r"(a) : "l"(p));
    return a;
}
#define SWZ(o) ((o) ^ ((((uint32_t)(o))>>3)&0x70))

#define MMA16816H(d, a0,a1,a2,a3, b0,b1) \
    asm volatile("mma.sync.aligned.m16n8k16.row.col.f32.f16.f16.f32 " \
        "{%0,%1,%2,%3},{%4,%5,%6,%7},{%8,%9},{%0,%1,%2,%3};" \
        : "+f"((d)[0]), "+f"((d)[1]), "+f"((d)[2]), "+f"((d)[3]) \
        : "r"(a0), "r"(a1), "r"(a2), "r"(a3), "r"(b0), "r"(b1))

#define LDX4(r, addr) \
    asm volatile("ldmatrix.sync.aligned.m8n8.x4.shared.b16 {%0,%1,%2,%3},[%4];" \
        : "=r"((r)[0]), "=r"((r)[1]), "=r"((r)[2]), "=r"((r)[3]) : "r"(addr))

#define CPA16(dst, src) \
    asm volatile("cp.async.cg.shared.global [%0], [%1], 16;" :: "r"(dst), "l"(src))

__device__ __forceinline__ uint32_t pack_h2(float x, float y) {
    uint32_t r;   // lo = x, hi = y
    asm("cvt.rn.f16x2.f32 %0, %1, %2;" : "=r"(r) : "f"(y), "f"(x));
    return r;
}
__device__ __forceinline__ void split2h(float x, float y, uint32_t& hp, uint32_t& lp) {
    hp = pack_h2(x, y);
    __half2 h2 = *reinterpret_cast<__half2*>(&hp);
    lp = pack_h2(x - __low2float(h2), y - __high2float(h2));
}

// ---------------- K1: entity logsumexp pooling ----------------
__global__ void k_ent_emb(const float* __restrict__ ent,
                          const int* __restrict__ labels)
{
    int e = blockIdx.x, b = blockIdx.y;
    __shared__ int s_idx[Ment];
    __shared__ int s_cnt;
    int tid = threadIdx.x;
    if (tid == 0) {
        int c = 0;
        for (int i = 0; i < Ment; i++)
            if (labels[b*Ment + i] == e) s_idx[c++] = i;
        s_cnt = c;
    }
    __syncthreads();
    int cnt = s_cnt;
    const float* eb = ent + (size_t)b*Ment*HID;
    float* out = g_ent_emb + ((size_t)(b*NE + e))*HID;
    for (int d = tid; d < HID; d += blockDim.x) {
        float r;
        if (cnt == 0) {
            r = 0.f;
        } else {
            float mx = -3.4e38f, s = 0.f;
            for (int i = 0; i < cnt; i++) {
                float v = eb[(size_t)s_idx[i]*HID + d];
                if (v > mx) { s = s*expf(mx - v) + 1.f; mx = v; }
                else        { s += expf(v - mx); }
            }
            r = mx + logf(s);
        }
        out[d] = r;
    }
}

// ---------------- K2: per-entity mean attention ----------------
__global__ void k_attn_mean(const float* __restrict__ attn,
                            const int* __restrict__ labels)
{
    int e = blockIdx.x, h = blockIdx.y, b = blockIdx.z;
    __shared__ int s_idx[Ment];
    __shared__ int s_cnt;
    int tid = threadIdx.x;
    if (tid == 0) {
        int c = 0;
        for (int i = 0; i < Ment; i++)
            if (labels[b*Ment + i] == e) s_idx[c++] = i;
        s_cnt = c;
    }
    __syncthreads();
    int cnt = s_cnt;
    float inv = 1.f / (float)(cnt > 0 ? cnt : 1);
    const float* ab = attn + (((size_t)b*NH + h)*Ment)*Lseq;
    float* out = g_attn_mean + (((size_t)(b*NE + e))*NH + h)*Lseq;
    for (int l = tid; l < Lseq; l += blockDim.x) {
        float s = 0.f;
        for (int i = 0; i < cnt; i++) s += ab[(size_t)s_idx[i]*Lseq + l];
        out[l] = s * inv;
    }
}

// ---------------- K3: hta -> single fp16 ----------------
__global__ void k_hta(const int* __restrict__ hts)
{
    int r = blockIdx.x, b = blockIdx.y;
    int r2 = b*Rht + r;
    int e0 = hts[(size_t)r2*2 + 0];
    int e1 = hts[(size_t)r2*2 + 1];
    const float* a0 = g_attn_mean + ((size_t)(b*NE + e0))*NH*Lseq;
    const float* a1 = g_attn_mean + ((size_t)(b*NE + e1))*NH*Lseq;
    int tid = threadIdx.x;
    int l0 = tid*4;
    float4 acc = make_float4(0.f,0.f,0.f,0.f);
#pragma unroll
    for (int h = 0; h < NH; h++) {
        float4 x = *(const float4*)&a0[h*Lseq + l0];
        float4 y = *(const float4*)&a1[h*Lseq + l0];
        acc.x += x.x*y.x; acc.y += x.y*y.y;
        acc.z += x.z*y.z; acc.w += x.w*y.w;
    }
    acc.x *= (1.f/NH); acc.y *= (1.f/NH); acc.z *= (1.f/NH); acc.w *= (1.f/NH);
    __shared__ float red[256];
    red[tid] = acc.x + acc.y + acc.z + acc.w;
    __syncthreads();
    for (int o = 128; o > 0; o >>= 1) {
        if (tid < o) red[tid] += red[tid + o];
        __syncthreads();
    }
    float sc = 1.f / (red[0] + 1e-5f);
    size_t o = (size_t)r2*(Lseq/2) + tid*2;
    g_htaH[o]   = pack_h2(acc.x*sc, acc.y*sc);
    g_htaH[o+1] = pack_h2(acc.z*sc, acc.w*sc);
}

// ---------------- K5: gather -> single fp16 X ----------------
__global__ void k_gather(const int* __restrict__ hts)
{
    int r2 = blockIdx.x;
    int b = r2 / Rht;
    int e0 = hts[(size_t)r2*2 + 0];
    int e1 = hts[(size_t)r2*2 + 1];
    const float* emb0 = g_ent_emb + ((size_t)(b*NE + e0))*HID;
    const float* emb1 = g_ent_emb + ((size_t)(b*NE + e1))*HID;
    const float* rel  = g_rel + (size_t)r2*HID;
    for (int u = threadIdx.x; u < HID; u += 256) {
        if (u < HID/2) {
            float2 v0 = *(const float2*)&emb0[2*u];
            g_XH[(size_t)r2*HID + u] = pack_h2(v0.x, v0.y);
            float2 v1 = *(const float2*)&emb1[2*u];
            g_XH[(size_t)(NROW + r2)*HID + u] = pack_h2(v1.x, v1.y);
        } else {
            float2 rv = *(const float2*)&rel[2*u - HID];
            uint32_t p = pack_h2(rv.x, rv.y);
            g_XH[(size_t)r2*HID + u] = p;
            g_XH[(size_t)(NROW + r2)*HID + u] = p;
        }
    }
}

// ---------------- split + transpose: [z][K][N] f32 -> [z][N][K/2] fp16x2 ----
// FMT 2 = fp16 hi only, FMT 3 = fp16 hi + lo
template<int FMT>
__global__ void __launch_bounds__(256)
k_splitT(const float* __restrict__ in,
         uint32_t* __restrict__ outHi, uint32_t* __restrict__ outLo,
         int K, int N, long sIn, long sOut)
{
    __shared__ float s[128][65];
    in    += (size_t)blockIdx.z * sIn;
    outHi += (size_t)blockIdx.z * sOut;
    if (FMT == 3) outLo += (size_t)blockIdx.z * sOut;
    int k0 = blockIdx.x*128, n0 = blockIdx.y*64;
    int tid = threadIdx.x;
#pragma unroll
    for (int u = 0; u < 8; u++) {
        int idx = tid + u*256;
        int kk = idx >> 4;
        int cc = (idx & 15) * 4;
        float4 v = *(const float4*)&in[(size_t)(k0+kk)*N + n0 + cc];
        s[kk][cc+0] = v.x; s[kk][cc+1] = v.y;
        s[kk][cc+2] = v.z; s[kk][cc+3] = v.w;
    }
    __syncthreads();
    int K2 = K >> 1;
#pragma unroll
    for (int u = 0; u < 4; u++) {
        int idx = tid + u*256;
        int nn = idx >> 4, q = idx & 15;
        uint32_t hi[4], lo[4];
#pragma unroll
        for (int i = 0; i < 4; i++) {
            if (FMT == 3) split2h(s[q*8 + i*2][nn], s[q*8 + i*2 + 1][nn], hi[i], lo[i]);
            else          hi[i] = pack_h2(s[q*8 + i*2][nn], s[q*8 + i*2 + 1][nn]);
        }
        size_t o = (size_t)(n0+nn)*K2 + (k0 >> 1) + q*4;
        *(uint4*)&outHi[o] = make_uint4(hi[0], hi[1], hi[2], hi[3]);
        if (FMT == 3)
            *(uint4*)&outLo[o] = make_uint4(lo[0], lo[1], lo[2], lo[3]);
    }
}

__global__ void k_bias2(const float* __restrict__ b0, const float* __restrict__ b1)
{
    int i = threadIdx.x + blockIdx.x*256;
    if (i < EMB) { g_bias_ht[i] = b0[i]; g_bias_ht[EMB+i] = b1[i]; }
}

// ---------------- 2-pass fp16 mma GEMM ----------------
// C[z][M][N] = act(A[z] @ B[z]^T + bias[z]); A fp16 [M][K/2], B fp16 hi/lo [N][K/2]
// CTA 128x128, chunk K=64, 256 threads, warps 4(M)x2(N).
template<int ACT>
__global__ void __launch_bounds__(256, 1)
k_gemm_split2(const uint32_t* __restrict__ Ah,
              const uint32_t* __restrict__ Bhi, const uint32_t* __restrict__ Blo,
              const float* __restrict__ bias, float* __restrict__ C,
              int K, int N, long sA, long sB, long sC)
{
    extern __shared__ char smem[];   // 2 bufs x (A 16K | Bhi 16K | Blo 16K) = 96KB
    uint32_t sb = smem_u32(smem);
    int tid = threadIdx.x, lid = tid & 31, wid = tid >> 5;
    int row0 = blockIdx.y*128, col0 = blockIdx.x*128;
    Ah  += (size_t)blockIdx.z * sA;
    Bhi += (size_t)blockIdx.z * sB;  Blo += (size_t)blockIdx.z * sB;
    C   += (size_t)blockIdx.z * sC;
    const float* bz = bias ? bias + (size_t)blockIdx.z * N : nullptr;
    int K2 = K >> 1, nchunk = K >> 6;
    int wm = (wid >> 1)*32, wn = (wid & 1)*64;
    int msel = lid >> 3, r8 = lid & 7;

    float acc[2][8][4];
#pragma unroll
    for (int i = 0; i < 2; i++)
#pragma unroll
        for (int n = 0; n < 8; n++)
#pragma unroll
            for (int q = 0; q < 4; q++) acc[i][n][q] = 0.f;

#define GLOAD2(c) { \
    uint32_t base = sb + (uint32_t)((c)&1)*49152u; \
    _Pragma("unroll") \
    for (int p = 0; p < 4; p++) { \
        int idx = tid + p*256; int r = idx >> 3, seg = idx & 7; \
        uint32_t off = SWZ((uint32_t)(r*128 + seg*16)); \
        size_t goA = (size_t)(row0+r)*K2 + (size_t)(c)*32 + seg*4; \
        size_t goB = (size_t)(col0+r)*K2 + (size_t)(c)*32 + seg*4; \
        CPA16(base + off,          Ah  + goA); \
        CPA16(base + 16384u + off, Bhi + goB); \
        CPA16(base + 32768u + off, Blo + goB); \
    } }

    GLOAD2(0);
    asm volatile("cp.async.commit_group;");

#pragma unroll 1
    for (int c = 0; c < nchunk; ++c) {
        if (c + 1 < nchunk) GLOAD2(c + 1);
        asm volatile("cp.async.commit_group;");
        asm volatile("cp.async.wait_group 1;");
        __syncthreads();

        uint32_t abase = sb + (uint32_t)(c & 1)*49152u;
        uint32_t bbase = abase + 16384u;
#pragma unroll
        for (int s = 0; s < 4; ++s) {
            uint32_t ah[2][4];
#pragma unroll
            for (int i = 0; i < 2; ++i) {
                uint32_t off = SWZ((uint32_t)((wm + i*16 + (lid & 15))*128
                                              + s*32 + (lid >> 4)*16));
                LDX4(ah[i], abase + off);
            }
            uint32_t bh[16], bl[16];
#pragma unroll
            for (int pq = 0; pq < 4; ++pq) {
                uint32_t off = SWZ((uint32_t)((wn + (pq*2 + (msel >> 1))*8 + r8)*128
                                              + s*32 + (msel & 1)*16));
                LDX4(&bh[pq*4], bbase + off);
                LDX4(&bl[pq*4], bbase + 16384u + off);
            }
#pragma unroll
            for (int i = 0; i < 2; ++i)
#pragma unroll
                for (int n = 0; n < 8; ++n) {
                    MMA16816H(acc[i][n], ah[i][0],ah[i][1],ah[i][2],ah[i][3], bh[n*2], bh[n*2+1]);
                    MMA16816H(acc[i][n], ah[i][0],ah[i][1],ah[i][2],ah[i][3], bl[n*2], bl[n*2+1]);
                }
        }
        __syncthreads();
    }
#undef GLOAD2

#pragma unroll
    for (int i = 0; i < 2; ++i) {
        int gr = row0 + wm + i*16 + (lid >> 2);
#pragma unroll
        for (int n = 0; n < 8; ++n) {
            int gc = col0 + wn + n*8 + (lid & 3)*2;
            float b0v = bz ? bz[gc] : 0.f, b1v = bz ? bz[gc+1] : 0.f;
            float v0 = acc[i][n][0] + b0v, v1 = acc[i][n][1] + b1v;
            float v2 = acc[i][n][2] + b0v, v3 = acc[i][n][3] + b1v;
            if (ACT == 1) { v0 = tanhf(v0); v1 = tanhf(v1); v2 = tanhf(v2); v3 = tanhf(v3); }
            *(float2*)&C[(size_t)gr*N + gc]     = make_float2(v0, v1);
            *(float2*)&C[(size_t)(gr+8)*N + gc] = make_float2(v2, v3);
        }
    }
}

// ---------------- fp32 SIMT sgemm (small tails: cls/proj) ----------------
template<int BM, int BN, int BK, int TM, int TN, int ACT>
__global__ __launch_bounds__((BM/TM)*(BN/TN))
void sgemm(const float* __restrict__ A, const float* __restrict__ B,
           const float* __restrict__ bias, float* __restrict__ C,
           int M, int N, int K)
{
    constexpr int THREADS = (BM/TM)*(BN/TN);
    __shared__ float As[BK][BM + 4];
    __shared__ float Bs[BK][BN];
    int tid = threadIdx.x;
    int tx = tid % (BN/TN);
    int ty = tid / (BN/TN);
    int row0 = blockIdx.y * BM, col0 = blockIdx.x * BN;
    float acc[TM][TN] = {};
    constexpr int AE = BM*BK/THREADS;
    constexpr int BE = BK*BN/THREADS;

    for (int k0 = 0; k0 < K; k0 += BK) {
#pragma unroll
        for (int u = 0; u < AE; u++) {
            int idx = tid + u*THREADS;
            int r = idx / BK, c = idx % BK;
            float v = 0.f;
            int gr = row0 + r;
            if (gr < M) v = A[(size_t)gr*K + k0 + c];
            As[c][r] = v;
        }
#pragma unroll
        for (int u = 0; u < BE; u++) {
            int idx = tid + u*THREADS;
            int r = idx / BN, c = idx % BN;
            float v = 0.f;
            int gc = col0 + c;
            if (gc < N) v = B[(size_t)(k0 + r)*N + gc];
            Bs[r][c] = v;
        }
        __syncthreads();
#pragma unroll
        for (int kk = 0; kk < BK; kk++) {
            float af[TM], bf[TN];
#pragma unroll
            for (int i = 0; i < TM; i += 4)
                *reinterpret_cast<float4*>(&af[i]) =
                    *reinterpret_cast<const float4*>(&As[kk][ty*TM + i]);
#pragma unroll
            for (int j = 0; j < TN; j += 4)
                *reinterpret_cast<float4*>(&bf[j]) =
                    *reinterpret_cast<const float4*>(&Bs[kk][tx*TN + j]);
#pragma unroll
            for (int i = 0; i < TM; i++)
#pragma unroll
                for (int j = 0; j < TN; j++)
                    acc[i][j] += af[i] * bf[j];
        }
        __syncthreads();
    }
#pragma unroll
    for (int i = 0; i < TM; i++) {
        int gr = row0 + ty*TM + i;
        if (gr >= M) continue;
#pragma unroll
        for (int j = 0; j < TN; j++) {
            int gc = col0 + tx*TN + j;
            if (gc >= N) continue;
            float v = acc[i][j];
            if (bias) v += bias[gc];
            if (ACT == 1) v = tanhf(v);
            C[(size_t)gr*N + gc] = v;
        }
    }
}

// ---------------- bilinear GEMM via fp16 mma (1-pass, N-tile 96) ----------
#define BIL_SH_OFF 24576
#define BIL_ST_OFF (24576 + 34816)
#define BIL_SMEM   (24576 + 2*34816)   // 94208

__device__ __forceinline__ void bil_load_B(uint32_t sb, int c, int col0, int tid)
{
    uint32_t dH = sb + (uint32_t)(c & 1)*12288u;
#pragma unroll
    for (int p = 0; p < 3; p++) {
        int idx = tid + p*256;
        int n = idx >> 3, seg = idx & 7;
        size_t go = (size_t)(col0 + n)*(KBIL/2) + (size_t)c*32 + seg*4;
        uint32_t off = SWZ((uint32_t)(n*128 + seg*16));
        CPA16(dH + off, g_WbilHi + go);
    }
}

__global__ void __launch_bounds__(256, 1)
k_bilinear_mma(const float* __restrict__ h, const float* __restrict__ t,
               const float* __restrict__ bias, float* __restrict__ out)
{
    extern __shared__ char smem[];
    uint32_t sb = smem_u32(smem);
    float* s_h = (float*)(smem + BIL_SH_OFF);   // [128][68]
    float* s_t = (float*)(smem + BIL_ST_OFF);   // [128][68]
    int tid = threadIdx.x, lid = tid & 31, wid = tid >> 5;
    int row0 = blockIdx.y * 128, col0 = blockIdx.x * 96;
    int wm = (wid >> 1) * 32;
    int wn = (wid & 1) * 48;

    float acc[2][6][4];
#pragma unroll
    for (int i = 0; i < 2; i++)
#pragma unroll
        for (int n = 0; n < 6; n++)
#pragma unroll
            for (int q = 0; q < 4; q++) acc[i][n][q] = 0.f;

    bil_load_B(sb, 0, col0, tid);
    asm volatile("cp.async.commit_group;");

#pragma unroll 1
    for (int c = 0; c < NCHUNK; ++c) {
        int j = c >> 6, a = c & 63, buf = c & 1;

        if (c + 1 < NCHUNK) bil_load_B(sb, c + 1, col0, tid);
        asm volatile("cp.async.commit_group;");
        asm volatile("cp.async.wait_group 1;");

        if (a == 0) {
            for (int idx = tid; idx < 128*16; idx += 256) {
                int rr = idx >> 4, cc = (idx & 15) * 4;
                *(float4*)&s_h[rr*68 + cc] =
                    *(const float4*)&h[(size_t)(row0+rr)*EMB + j*64 + cc];
                *(float4*)&s_t[rr*68 + cc] =
                    *(const float4*)&t[(size_t)(row0+rr)*EMB + j*64 + cc];
            }
        }
        __syncthreads();

        uint32_t bbase = sb + (uint32_t)buf*12288u;
        float h0[2], h1[2];
#pragma unroll
        for (int i = 0; i < 2; i++) {
            int r0 = wm + i*16 + (lid >> 2);
            h0[i] = s_h[r0*68 + a];
            h1[i] = s_h[(r0 + 8)*68 + a];
        }

        int msel = lid >> 3, r8 = lid & 7;
#pragma unroll
        for (int s = 0; s < 4; ++s) {
            uint32_t bh[12];
#pragma unroll
            for (int pq = 0; pq < 3; ++pq) {
                uint32_t off = SWZ((uint32_t)((wn + (pq*2 + (msel >> 1))*8 + r8)*128
                                              + s*32 + (msel & 1)*16));
                LDX4(&bh[pq*4], bbase + off);
            }
#pragma unroll
            for (int i = 0; i < 2; ++i) {
                int rb = (wm + i*16 + (lid >> 2))*68;
                int cc = s*16 + (lid & 3)*2;
                float2 ta = *(float2*)&s_t[rb + cc];
                float2 tb = *(float2*)&s_t[rb + cc + 8];
                float2 tc = *(float2*)&s_t[rb + 8*68 + cc];
                float2 td = *(float2*)&s_t[rb + 8*68 + cc + 8];
                uint32_t ah[4];
                ah[0] = pack_h2(h0[i]*ta.x, h0[i]*ta.y);
                ah[1] = pack_h2(h1[i]*tc.x, h1[i]*tc.y);
                ah[2] = pack_h2(h0[i]*tb.x, h0[i]*tb.y);
                ah[3] = pack_h2(h1[i]*td.x, h1[i]*td.y);
#pragma unroll
                for (int n = 0; n < 6; ++n)
                    MMA16816H(acc[i][n], ah[0],ah[1],ah[2],ah[3], bh[n*2], bh[n*2+1]);
            }
        }
        __syncthreads();
    }

#pragma unroll
    for (int i = 0; i < 2; ++i) {
        int gr = row0 + wm + i*16 + (lid >> 2);
#pragma unroll
        for (int n = 0; n < 6; ++n) {
            int gc = col0 + wn + n*8 + (lid & 3)*2;
            float2 v0 = make_float2(acc[i][n][0] + bias[gc],
                                    acc[i][n][1] + bias[gc+1]);
            float2 v1 = make_float2(acc[i][n][2] + bias[gc],
                                    acc[i][n][3] + bias[gc+1]);
            *(float2*)&out[(size_t)gr*EMB + gc]     = v0;
            *(float2*)&out[(size_t)(gr+8)*EMB + gc] = v1;
        }
    }
}

// ---------------- launch ----------------
extern "C" void kernel_launch(void* const* d_in, const int* in_sizes, int n_in,
                              void* d_out, int out_size)
{
    const float* seq    = (const float*)d_in[0];
    const float* ent    = (const float*)d_in[1];
    const float* attn   = (const float*)d_in[2];
    const int*   labels = (const int*)  d_in[3];
    const int*   hts    = (const int*)  d_in[4];
    const float* W_head = (const float*)d_in[5];
    const float* b_head = (const float*)d_in[6];
    const float* W_tail = (const float*)d_in[7];
    const float* b_tail = (const float*)d_in[8];
    const float* W_bil  = (const float*)d_in[9];
    const float* b_bil  = (const float*)d_in[10];
    const float* W_cls  = (const float*)d_in[11];
    const float* b_cls  = (const float*)d_in[12];
    const float* W_proj = (const float*)d_in[13];
    const float* b_proj = (const float*)d_in[14];

    float* out      = (float*)d_out;
    float* out_cls  = out + (size_t)NROW*EMB;
    float* out_proj = out_cls + (size_t)NROW*NCLS;

    void *p_rel, *p_ht, *p_biasht;
    void *p_WbHi, *p_WhtHi, *p_WhtLo, *p_seqHi, *p_seqLo;
    void *p_htaH, *p_XH;
    cudaGetSymbolAddress(&p_rel,   g_rel);
    cudaGetSymbolAddress(&p_ht,    g_ht);
    cudaGetSymbolAddress(&p_biasht,g_bias_ht);
    cudaGetSymbolAddress(&p_WbHi,  g_WbilHi);
    cudaGetSymbolAddress(&p_WhtHi, g_WhtHi);
    cudaGetSymbolAddress(&p_WhtLo, g_WhtLo);
    cudaGetSymbolAddress(&p_seqHi, g_seqTHi);
    cudaGetSymbolAddress(&p_seqLo, g_seqTLo);
    cudaGetSymbolAddress(&p_htaH,  g_htaH);
    cudaGetSymbolAddress(&p_XH,    g_XH);

    cudaFuncSetAttribute(k_bilinear_mma,
                         cudaFuncAttributeMaxDynamicSharedMemorySize, BIL_SMEM);
    cudaFuncSetAttribute(k_gemm_split2<0>,
                         cudaFuncAttributeMaxDynamicSharedMemorySize, 98304);
    cudaFuncSetAttribute(k_gemm_split2<1>,
                         cudaFuncAttributeMaxDynamicSharedMemorySize, 98304);

    static cudaStream_t s1 = nullptr;
    static cudaEvent_t evFork = nullptr, evSeq = nullptr, evJoin = nullptr,
                       evBil = nullptr, evProj = nullptr;
    if (!s1) {
        cudaStreamCreateWithFlags(&s1, cudaStreamNonBlocking);
        cudaEventCreateWithFlags(&evFork, cudaEventDisableTiming);
        cudaEventCreateWithFlags(&evSeq,  cudaEventDisableTiming);
        cudaEventCreateWithFlags(&evJoin, cudaEventDisableTiming);
        cudaEventCreateWithFlags(&evBil,  cudaEventDisableTiming);
        cudaEventCreateWithFlags(&evProj, cudaEventDisableTiming);
    }

    cudaEventRecord(evFork, 0);
    cudaStreamWaitEvent(s1, evFork, 0);

    // ---- s1: seq split first (needed by rel), then weights ----
    k_splitT<3><<<dim3(Lseq/128, HID/64, Bdoc), 256, 0, s1>>>(seq,
        (uint32_t*)p_seqHi, (uint32_t*)p_seqLo, Lseq, HID,
        (long)Lseq*HID, (long)HID*(Lseq/2));
    cudaEventRecord(evSeq, s1);
    k_bias2<<<3, 256, 0, s1>>>(b_head, b_tail);
    k_splitT<3><<<dim3(2*HID/128, EMB/64), 256, 0, s1>>>(W_head,
        (uint32_t*)p_WhtHi, (uint32_t*)p_WhtLo, 2*HID, EMB, 0, 0);
    k_splitT<3><<<dim3(2*HID/128, EMB/64), 256, 0, s1>>>(W_tail,
        (uint32_t*)p_WhtHi + (size_t)EMB*HID, (uint32_t*)p_WhtLo + (size_t)EMB*HID,
        2*HID, EMB, 0, 0);
    k_splitT<2><<<dim3(KBIL/128, EMB/64), 256, 0, s1>>>(W_bil,
        (uint32_t*)p_WbHi, nullptr, KBIL, EMB, 0, 0);
    cudaEventRecord(evJoin, s1);

    // ---- main: pooling chain ----
    k_ent_emb<<<dim3(NE, Bdoc), 256>>>(ent, labels);
    k_attn_mean<<<dim3(NE, NH, Bdoc), 256>>>(attn, labels);
    k_hta<<<dim3(Rht, Bdoc), 256>>>(hts);

    // rel = hta @ seq (2-pass fp16)
    cudaStreamWaitEvent(0, evSeq, 0);
    k_gemm_split2<0><<<dim3(HID/128, Rht/128, Bdoc), 256, 98304>>>(
        (const uint32_t*)p_htaH,
        (const uint32_t*)p_seqHi, (const uint32_t*)p_seqLo,
        nullptr, (float*)p_rel,
        Lseq, HID, (long)Rht*(Lseq/2), (long)HID*(Lseq/2), (long)Rht*HID);

    k_gather<<<NROW, 256>>>(hts);

    cudaStreamWaitEvent(0, evJoin, 0);

    // h and t in one launch (z = head/tail), 2-pass fp16
    k_gemm_split2<1><<<dim3(EMB/128, NROW/128, 2), 256, 98304>>>(
        (const uint32_t*)p_XH,
        (const uint32_t*)p_WhtHi, (const uint32_t*)p_WhtLo,
        (const float*)p_biasht, (float*)p_ht,
        2*HID, EMB, (long)NROW*HID, (long)EMB*HID, (long)NROW*EMB);

    // bilinear (fp16 1-pass) -> d_out (embeds)
    k_bilinear_mma<<<dim3(EMB/96, NROW/128), 256, BIL_SMEM>>>(
        (const float*)p_ht, (const float*)p_ht + (size_t)NROW*EMB, b_bil, out);
    cudaEventRecord(evBil, 0);

    // proj on s1 (concurrent with cls)
    cudaStreamWaitEvent(s1, evBil, 0);
    sgemm<64,32,16,4,4,1><<<dim3(NPROJ/32, NROW/64), 128, 0, s1>>>(
        out, W_proj, b_proj, out_proj, NROW, NPROJ, EMB);
    cudaEventRecord(evProj, s1);

    // cls on main
    sgemm<64,32,16,4,4,0><<<dim3((NCLS+31)/32, NROW/64), 128>>>(
        out, W_cls, b_cls, out_cls, NROW, NCLS, EMB);
    cudaStreamWaitEvent(0, evProj, 0);
}

// round 9
// speedup vs baseline: 6.4959x; 1.0583x over previous
#include <cuda_runtime.h>
#include <cuda_bf16.h>
#include <cuda_fp16.h>
#include <math.h>
#include <stdint.h>

// ---------------- problem constants ----------------
#define Bdoc 4
#define Lseq 1024
#define Ment 128
#define Rht  512
#define HID  1024
#define NH   16
#define NE   42
#define EMB  768
#define NBLK 12
#define NCLS 97
#define NPROJ 128
#define NROW (Bdoc*Rht)   // 2048
#define KBIL (EMB*64)     // 49152
#define NCHUNK (NBLK*64)  // 768

// ---------------- scratch ----------------
__device__ float g_ent_emb[Bdoc*NE*HID];
__device__ float g_attn_mean[Bdoc*NE*NH*Lseq];
__device__ float g_rel[NROW*HID];
__device__ float g_ht[2*NROW*EMB];                    // h then t (fp32)
__device__ float g_bias_ht[2*EMB];
// packed fp16x2 operands (single-precision fp16 everywhere now)
__device__ uint32_t g_WbilHi[(size_t)EMB*KBIL/2];     // 75.5 MB
__device__ uint32_t g_WhtHi[2*EMB*HID];               // [2][768][1024]
__device__ uint32_t g_seqTHi[Bdoc*HID*Lseq/2];        // [4][1024][512]
__device__ uint32_t g_htaH[NROW*Lseq/2];
__device__ uint32_t g_XH[2*NROW*HID];

// ---------------- helpers ----------------
__device__ __forceinline__ uint32_t smem_u32(const void* p) {
    uint32_t a;
    asm("{ .reg .u64 t; cvta.to.shared.u64 t, %1; cvt.u32.u64 %0, t; }"
        : "=r"(a) : "l"(p));
    return a;
}
#define SWZ(o) ((o) ^ ((((uint32_t)(o))>>3)&0x70))

#define MMA16816H(d, a0,a1,a2,a3, b0,b1) \
    asm volatile("mma.sync.aligned.m16n8k16.row.col.f32.f16.f16.f32 " \
        "{%0,%1,%2,%3},{%4,%5,%6,%7},{%8,%9},{%0,%1,%2,%3};" \
        : "+f"((d)[0]), "+f"((d)[1]), "+f"((d)[2]), "+f"((d)[3]) \
        : "r"(a0), "r"(a1), "r"(a2), "r"(a3), "r"(b0), "r"(b1))

#define LDX4(r, addr) \
    asm volatile("ldmatrix.sync.aligned.m8n8.x4.shared.b16 {%0,%1,%2,%3},[%4];" \
        : "=r"((r)[0]), "=r"((r)[1]), "=r"((r)[2]), "=r"((r)[3]) : "r"(addr))

#define CPA16(dst, src) \
    asm volatile("cp.async.cg.shared.global [%0], [%1], 16;" :: "r"(dst), "l"(src))

__device__ __forceinline__ uint32_t pack_h2(float x, float y) {
    uint32_t r;   // lo = x, hi = y
    asm("cvt.rn.f16x2.f32 %0, %1, %2;" : "=r"(r) : "f"(y), "f"(x));
    return r;
}

// ---------------- K1: entity logsumexp pooling ----------------
__global__ void k_ent_emb(const float* __restrict__ ent,
                          const int* __restrict__ labels)
{
    int e = blockIdx.x, b = blockIdx.y;
    __shared__ int s_idx[Ment];
    __shared__ int s_cnt;
    int tid = threadIdx.x;
    if (tid == 0) {
        int c = 0;
        for (int i = 0; i < Ment; i++)
            if (labels[b*Ment + i] == e) s_idx[c++] = i;
        s_cnt = c;
    }
    __syncthreads();
    int cnt = s_cnt;
    const float* eb = ent + (size_t)b*Ment*HID;
    float* out = g_ent_emb + ((size_t)(b*NE + e))*HID;
    for (int d = tid; d < HID; d += blockDim.x) {
        float r;
        if (cnt == 0) {
            r = 0.f;
        } else {
            float mx = -3.4e38f, s = 0.f;
            for (int i = 0; i < cnt; i++) {
                float v = eb[(size_t)s_idx[i]*HID + d];
                if (v > mx) { s = s*expf(mx - v) + 1.f; mx = v; }
                else        { s += expf(v - mx); }
            }
            r = mx + logf(s);
        }
        out[d] = r;
    }
}

// ---------------- K2: per-entity mean attention ----------------
__global__ void k_attn_mean(const float* __restrict__ attn,
                            const int* __restrict__ labels)
{
    int e = blockIdx.x, h = blockIdx.y, b = blockIdx.z;
    __shared__ int s_idx[Ment];
    __shared__ int s_cnt;
    int tid = threadIdx.x;
    if (tid == 0) {
        int c = 0;
        for (int i = 0; i < Ment; i++)
            if (labels[b*Ment + i] == e) s_idx[c++] = i;
        s_cnt = c;
    }
    __syncthreads();
    int cnt = s_cnt;
    float inv = 1.f / (float)(cnt > 0 ? cnt : 1);
    const float* ab = attn + (((size_t)b*NH + h)*Ment)*Lseq;
    float* out = g_attn_mean + (((size_t)(b*NE + e))*NH + h)*Lseq;
    for (int l = tid; l < Lseq; l += blockDim.x) {
        float s = 0.f;
        for (int i = 0; i < cnt; i++) s += ab[(size_t)s_idx[i]*Lseq + l];
        out[l] = s * inv;
    }
}

// ---------------- K3: hta -> single fp16 ----------------
__global__ void k_hta(const int* __restrict__ hts)
{
    int r = blockIdx.x, b = blockIdx.y;
    int r2 = b*Rht + r;
    int e0 = hts[(size_t)r2*2 + 0];
    int e1 = hts[(size_t)r2*2 + 1];
    const float* a0 = g_attn_mean + ((size_t)(b*NE + e0))*NH*Lseq;
    const float* a1 = g_attn_mean + ((size_t)(b*NE + e1))*NH*Lseq;
    int tid = threadIdx.x;
    int l0 = tid*4;
    float4 acc = make_float4(0.f,0.f,0.f,0.f);
#pragma unroll
    for (int h = 0; h < NH; h++) {
        float4 x = *(const float4*)&a0[h*Lseq + l0];
        float4 y = *(const float4*)&a1[h*Lseq + l0];
        acc.x += x.x*y.x; acc.y += x.y*y.y;
        acc.z += x.z*y.z; acc.w += x.w*y.w;
    }
    acc.x *= (1.f/NH); acc.y *= (1.f/NH); acc.z *= (1.f/NH); acc.w *= (1.f/NH);
    __shared__ float red[256];
    red[tid] = acc.x + acc.y + acc.z + acc.w;
    __syncthreads();
    for (int o = 128; o > 0; o >>= 1) {
        if (tid < o) red[tid] += red[tid + o];
        __syncthreads();
    }
    float sc = 1.f / (red[0] + 1e-5f);
    size_t o = (size_t)r2*(Lseq/2) + tid*2;
    g_htaH[o]   = pack_h2(acc.x*sc, acc.y*sc);
    g_htaH[o+1] = pack_h2(acc.z*sc, acc.w*sc);
}

// ---------------- K5: gather -> single fp16 X ----------------
__global__ void k_gather(const int* __restrict__ hts)
{
    int r2 = blockIdx.x;
    int b = r2 / Rht;
    int e0 = hts[(size_t)r2*2 + 0];
    int e1 = hts[(size_t)r2*2 + 1];
    const float* emb0 = g_ent_emb + ((size_t)(b*NE + e0))*HID;
    const float* emb1 = g_ent_emb + ((size_t)(b*NE + e1))*HID;
    const float* rel  = g_rel + (size_t)r2*HID;
    for (int u = threadIdx.x; u < HID; u += 256) {
        if (u < HID/2) {
            float2 v0 = *(const float2*)&emb0[2*u];
            g_XH[(size_t)r2*HID + u] = pack_h2(v0.x, v0.y);
            float2 v1 = *(const float2*)&emb1[2*u];
            g_XH[(size_t)(NROW + r2)*HID + u] = pack_h2(v1.x, v1.y);
        } else {
            float2 rv = *(const float2*)&rel[2*u - HID];
            uint32_t p = pack_h2(rv.x, rv.y);
            g_XH[(size_t)r2*HID + u] = p;
            g_XH[(size_t)(NROW + r2)*HID + u] = p;
        }
    }
}

// ---------------- split + transpose: [z][K][N] f32 -> [z][N][K/2] fp16x2 ----
__global__ void __launch_bounds__(256)
k_splitT(const float* __restrict__ in, uint32_t* __restrict__ outHi,
         int K, int N, long sIn, long sOut)
{
    __shared__ float s[128][65];
    in    += (size_t)blockIdx.z * sIn;
    outHi += (size_t)blockIdx.z * sOut;
    int k0 = blockIdx.x*128, n0 = blockIdx.y*64;
    int tid = threadIdx.x;
#pragma unroll
    for (int u = 0; u < 8; u++) {
        int idx = tid + u*256;
        int kk = idx >> 4;
        int cc = (idx & 15) * 4;
        float4 v = *(const float4*)&in[(size_t)(k0+kk)*N + n0 + cc];
        s[kk][cc+0] = v.x; s[kk][cc+1] = v.y;
        s[kk][cc+2] = v.z; s[kk][cc+3] = v.w;
    }
    __syncthreads();
    int K2 = K >> 1;
#pragma unroll
    for (int u = 0; u < 4; u++) {
        int idx = tid + u*256;
        int nn = idx >> 4, q = idx & 15;
        uint32_t hi[4];
#pragma unroll
        for (int i = 0; i < 4; i++)
            hi[i] = pack_h2(s[q*8 + i*2][nn], s[q*8 + i*2 + 1][nn]);
        size_t o = (size_t)(n0+nn)*K2 + (k0 >> 1) + q*4;
        *(uint4*)&outHi[o] = make_uint4(hi[0], hi[1], hi[2], hi[3]);
    }
}

__global__ void k_bias2(const float* __restrict__ b0, const float* __restrict__ b1)
{
    int i = threadIdx.x + blockIdx.x*256;
    if (i < EMB) { g_bias_ht[i] = b0[i]; g_bias_ht[EMB+i] = b1[i]; }
}

// ---------------- 1-pass fp16 mma GEMM ----------------
// C[z][M][N] = act(A[z] @ B[z]^T + bias[z]); A fp16 [M][K/2], B fp16 [N][K/2]
// CTA 128x128, chunk K=64, 256 threads, warps 4(M)x2(N).
template<int ACT>
__global__ void __launch_bounds__(256, 1)
k_gemm_h(const uint32_t* __restrict__ Ah, const uint32_t* __restrict__ Bh,
         const float* __restrict__ bias, float* __restrict__ C,
         int K, int N, long sA, long sB, long sC)
{
    extern __shared__ char smem[];   // 2 bufs x (A 16K | B 16K) = 64KB
    uint32_t sb = smem_u32(smem);
    int tid = threadIdx.x, lid = tid & 31, wid = tid >> 5;
    int row0 = blockIdx.y*128, col0 = blockIdx.x*128;
    Ah += (size_t)blockIdx.z * sA;
    Bh += (size_t)blockIdx.z * sB;
    C  += (size_t)blockIdx.z * sC;
    const float* bz = bias ? bias + (size_t)blockIdx.z * N : nullptr;
    int K2 = K >> 1, nchunk = K >> 6;
    int wm = (wid >> 1)*32, wn = (wid & 1)*64;
    int msel = lid >> 3, r8 = lid & 7;

    float acc[2][8][4];
#pragma unroll
    for (int i = 0; i < 2; i++)
#pragma unroll
        for (int n = 0; n < 8; n++)
#pragma unroll
            for (int q = 0; q < 4; q++) acc[i][n][q] = 0.f;

#define GLOADH(c) { \
    uint32_t base = sb + (uint32_t)((c)&1)*32768u; \
    _Pragma("unroll") \
    for (int p = 0; p < 4; p++) { \
        int idx = tid + p*256; int r = idx >> 3, seg = idx & 7; \
        uint32_t off = SWZ((uint32_t)(r*128 + seg*16)); \
        size_t goA = (size_t)(row0+r)*K2 + (size_t)(c)*32 + seg*4; \
        size_t goB = (size_t)(col0+r)*K2 + (size_t)(c)*32 + seg*4; \
        CPA16(base + off,          Ah + goA); \
        CPA16(base + 16384u + off, Bh + goB); \
    } }

    GLOADH(0);
    asm volatile("cp.async.commit_group;");

#pragma unroll 1
    for (int c = 0; c < nchunk; ++c) {
        if (c + 1 < nchunk) GLOADH(c + 1);
        asm volatile("cp.async.commit_group;");
        asm volatile("cp.async.wait_group 1;");
        __syncthreads();

        uint32_t abase = sb + (uint32_t)(c & 1)*32768u;
        uint32_t bbase = abase + 16384u;
#pragma unroll
        for (int s = 0; s < 4; ++s) {
            uint32_t ah[2][4];
#pragma unroll
            for (int i = 0; i < 2; ++i) {
                uint32_t off = SWZ((uint32_t)((wm + i*16 + (lid & 15))*128
                                              + s*32 + (lid >> 4)*16));
                LDX4(ah[i], abase + off);
            }
            uint32_t bh[16];
#pragma unroll
            for (int pq = 0; pq < 4; ++pq) {
                uint32_t off = SWZ((uint32_t)((wn + (pq*2 + (msel >> 1))*8 + r8)*128
                                              + s*32 + (msel & 1)*16));
                LDX4(&bh[pq*4], bbase + off);
            }
#pragma unroll
            for (int i = 0; i < 2; ++i)
#pragma unroll
                for (int n = 0; n < 8; ++n)
                    MMA16816H(acc[i][n], ah[i][0],ah[i][1],ah[i][2],ah[i][3], bh[n*2], bh[n*2+1]);
        }
        __syncthreads();
    }
#undef GLOADH

#pragma unroll
    for (int i = 0; i < 2; ++i) {
        int gr = row0 + wm + i*16 + (lid >> 2);
#pragma unroll
        for (int n = 0; n < 8; ++n) {
            int gc = col0 + wn + n*8 + (lid & 3)*2;
            float b0v = bz ? bz[gc] : 0.f, b1v = bz ? bz[gc+1] : 0.f;
            float v0 = acc[i][n][0] + b0v, v1 = acc[i][n][1] + b1v;
            float v2 = acc[i][n][2] + b0v, v3 = acc[i][n][3] + b1v;
            if (ACT == 1) { v0 = tanhf(v0); v1 = tanhf(v1); v2 = tanhf(v2); v3 = tanhf(v3); }
            *(float2*)&C[(size_t)gr*N + gc]     = make_float2(v0, v1);
            *(float2*)&C[(size_t)(gr+8)*N + gc] = make_float2(v2, v3);
        }
    }
}

// ---------------- fp32 SIMT sgemm (small tails: cls/proj) ----------------
template<int BM, int BN, int BK, int TM, int TN, int ACT>
__global__ __launch_bounds__((BM/TM)*(BN/TN))
void sgemm(const float* __restrict__ A, const float* __restrict__ B,
           const float* __restrict__ bias, float* __restrict__ C,
           int M, int N, int K)
{
    constexpr int THREADS = (BM/TM)*(BN/TN);
    __shared__ float As[BK][BM + 4];
    __shared__ float Bs[BK][BN];
    int tid = threadIdx.x;
    int tx = tid % (BN/TN);
    int ty = tid / (BN/TN);
    int row0 = blockIdx.y * BM, col0 = blockIdx.x * BN;
    float acc[TM][TN] = {};
    constexpr int AE = BM*BK/THREADS;
    constexpr int BE = BK*BN/THREADS;

    for (int k0 = 0; k0 < K; k0 += BK) {
#pragma unroll
        for (int u = 0; u < AE; u++) {
            int idx = tid + u*THREADS;
            int r = idx / BK, c = idx % BK;
            float v = 0.f;
            int gr = row0 + r;
            if (gr < M) v = A[(size_t)gr*K + k0 + c];
            As[c][r] = v;
        }
#pragma unroll
        for (int u = 0; u < BE; u++) {
            int idx = tid + u*THREADS;
            int r = idx / BN, c = idx % BN;
            float v = 0.f;
            int gc = col0 + c;
            if (gc < N) v = B[(size_t)(k0 + r)*N + gc];
            Bs[r][c] = v;
        }
        __syncthreads();
#pragma unroll
        for (int kk = 0; kk < BK; kk++) {
            float af[TM], bf[TN];
#pragma unroll
            for (int i = 0; i < TM; i += 4)
                *reinterpret_cast<float4*>(&af[i]) =
                    *reinterpret_cast<const float4*>(&As[kk][ty*TM + i]);
#pragma unroll
            for (int j = 0; j < TN; j += 4)
                *reinterpret_cast<float4*>(&bf[j]) =
                    *reinterpret_cast<const float4*>(&Bs[kk][tx*TN + j]);
#pragma unroll
            for (int i = 0; i < TM; i++)
#pragma unroll
                for (int j = 0; j < TN; j++)
                    acc[i][j] += af[i] * bf[j];
        }
        __syncthreads();
    }
#pragma unroll
    for (int i = 0; i < TM; i++) {
        int gr = row0 + ty*TM + i;
        if (gr >= M) continue;
#pragma unroll
        for (int j = 0; j < TN; j++) {
            int gc = col0 + tx*TN + j;
            if (gc >= N) continue;
            float v = acc[i][j];
            if (bias) v += bias[gc];
            if (ACT == 1) v = tanhf(v);
            C[(size_t)gr*N + gc] = v;
        }
    }
}

// ---------------- bilinear GEMM via fp16 mma (1-pass, N-tile 96) ----------
#define BIL_SH_OFF 24576
#define BIL_ST_OFF (24576 + 34816)
#define BIL_SMEM   (24576 + 2*34816)   // 94208

__device__ __forceinline__ void bil_load_B(uint32_t sb, int c, int col0, int tid)
{
    uint32_t dH = sb + (uint32_t)(c & 1)*12288u;
#pragma unroll
    for (int p = 0; p < 3; p++) {
        int idx = tid + p*256;
        int n = idx >> 3, seg = idx & 7;
        size_t go = (size_t)(col0 + n)*(KBIL/2) + (size_t)c*32 + seg*4;
        uint32_t off = SWZ((uint32_t)(n*128 + seg*16));
        CPA16(dH + off, g_WbilHi + go);
    }
}

__global__ void __launch_bounds__(256, 1)
k_bilinear_mma(const float* __restrict__ h, const float* __restrict__ t,
               const float* __restrict__ bias, float* __restrict__ out)
{
    extern __shared__ char smem[];
    uint32_t sb = smem_u32(smem);
    float* s_h = (float*)(smem + BIL_SH_OFF);   // [128][68]
    float* s_t = (float*)(smem + BIL_ST_OFF);   // [128][68]
    int tid = threadIdx.x, lid = tid & 31, wid = tid >> 5;
    int row0 = blockIdx.y * 128, col0 = blockIdx.x * 96;
    int wm = (wid >> 1) * 32;
    int wn = (wid & 1) * 48;

    float acc[2][6][4];
#pragma unroll
    for (int i = 0; i < 2; i++)
#pragma unroll
        for (int n = 0; n < 6; n++)
#pragma unroll
            for (int q = 0; q < 4; q++) acc[i][n][q] = 0.f;

    bil_load_B(sb, 0, col0, tid);
    asm volatile("cp.async.commit_group;");

#pragma unroll 1
    for (int c = 0; c < NCHUNK; ++c) {
        int j = c >> 6, a = c & 63, buf = c & 1;

        if (c + 1 < NCHUNK) bil_load_B(sb, c + 1, col0, tid);
        asm volatile("cp.async.commit_group;");
        asm volatile("cp.async.wait_group 1;");

        if (a == 0) {
            for (int idx = tid; idx < 128*16; idx += 256) {
                int rr = idx >> 4, cc = (idx & 15) * 4;
                *(float4*)&s_h[rr*68 + cc] =
                    *(const float4*)&h[(size_t)(row0+rr)*EMB + j*64 + cc];
                *(float4*)&s_t[rr*68 + cc] =
                    *(const float4*)&t[(size_t)(row0+rr)*EMB + j*64 + cc];
            }
        }
        __syncthreads();

        uint32_t bbase = sb + (uint32_t)buf*12288u;
        float h0[2], h1[2];
#pragma unroll
        for (int i = 0; i < 2; i++) {
            int r0 = wm + i*16 + (lid >> 2);
            h0[i] = s_h[r0*68 + a];
            h1[i] = s_h[(r0 + 8)*68 + a];
        }

        int msel = lid >> 3, r8 = lid & 7;
#pragma unroll
        for (int s = 0; s < 4; ++s) {
            uint32_t bh[12];
#pragma unroll
            for (int pq = 0; pq < 3; ++pq) {
                uint32_t off = SWZ((uint32_t)((wn + (pq*2 + (msel >> 1))*8 + r8)*128
                                              + s*32 + (msel & 1)*16));
                LDX4(&bh[pq*4], bbase + off);
            }
#pragma unroll
            for (int i = 0; i < 2; ++i) {
                int rb = (wm + i*16 + (lid >> 2))*68;
                int cc = s*16 + (lid & 3)*2;
                float2 ta = *(float2*)&s_t[rb + cc];
                float2 tb = *(float2*)&s_t[rb + cc + 8];
                float2 tc = *(float2*)&s_t[rb + 8*68 + cc];
                float2 td = *(float2*)&s_t[rb + 8*68 + cc + 8];
                uint32_t ah[4];
                ah[0] = pack_h2(h0[i]*ta.x, h0[i]*ta.y);
                ah[1] = pack_h2(h1[i]*tc.x, h1[i]*tc.y);
                ah[2] = pack_h2(h0[i]*tb.x, h0[i]*tb.y);
                ah[3] = pack_h2(h1[i]*td.x, h1[i]*td.y);
#pragma unroll
                for (int n = 0; n < 6; ++n)
                    MMA16816H(acc[i][n], ah[0],ah[1],ah[2],ah[3], bh[n*2], bh[n*2+1]);
            }
        }
        __syncthreads();
    }

#pragma unroll
    for (int i = 0; i < 2; ++i) {
        int gr = row0 + wm + i*16 + (lid >> 2);
#pragma unroll
        for (int n = 0; n < 6; ++n) {
            int gc = col0 + wn + n*8 + (lid & 3)*2;
            float2 v0 = make_float2(acc[i][n][0] + bias[gc],
                                    acc[i][n][1] + bias[gc+1]);
            float2 v1 = make_float2(acc[i][n][2] + bias[gc],
                                    acc[i][n][3] + bias[gc+1]);
            *(float2*)&out[(size_t)gr*EMB + gc]     = v0;
            *(float2*)&out[(size_t)(gr+8)*EMB + gc] = v1;
        }
    }
}

// ---------------- launch ----------------
extern "C" void kernel_launch(void* const* d_in, const int* in_sizes, int n_in,
                              void* d_out, int out_size)
{
    const float* seq    = (const float*)d_in[0];
    const float* ent    = (const float*)d_in[1];
    const float* attn   = (const float*)d_in[2];
    const int*   labels = (const int*)  d_in[3];
    const int*   hts    = (const int*)  d_in[4];
    const float* W_head = (const float*)d_in[5];
    const float* b_head = (const float*)d_in[6];
    const float* W_tail = (const float*)d_in[7];
    const float* b_tail = (const float*)d_in[8];
    const float* W_bil  = (const float*)d_in[9];
    const float* b_bil  = (const float*)d_in[10];
    const float* W_cls  = (const float*)d_in[11];
    const float* b_cls  = (const float*)d_in[12];
    const float* W_proj = (const float*)d_in[13];
    const float* b_proj = (const float*)d_in[14];

    float* out      = (float*)d_out;
    float* out_cls  = out + (size_t)NROW*EMB;
    float* out_proj = out_cls + (size_t)NROW*NCLS;

    void *p_rel, *p_ht, *p_biasht;
    void *p_WbHi, *p_WhtHi, *p_seqHi, *p_htaH, *p_XH;
    cudaGetSymbolAddress(&p_rel,   g_rel);
    cudaGetSymbolAddress(&p_ht,    g_ht);
    cudaGetSymbolAddress(&p_biasht,g_bias_ht);
    cudaGetSymbolAddress(&p_WbHi,  g_WbilHi);
    cudaGetSymbolAddress(&p_WhtHi, g_WhtHi);
    cudaGetSymbolAddress(&p_seqHi, g_seqTHi);
    cudaGetSymbolAddress(&p_htaH,  g_htaH);
    cudaGetSymbolAddress(&p_XH,    g_XH);

    cudaFuncSetAttribute(k_bilinear_mma,
                         cudaFuncAttributeMaxDynamicSharedMemorySize, BIL_SMEM);
    cudaFuncSetAttribute(k_gemm_h<0>,
                         cudaFuncAttributeMaxDynamicSharedMemorySize, 65536);
    cudaFuncSetAttribute(k_gemm_h<1>,
                         cudaFuncAttributeMaxDynamicSharedMemorySize, 65536);

    static cudaStream_t s1 = nullptr, s2 = nullptr;
    static cudaEvent_t evFork = nullptr, evSeq = nullptr, evJoin = nullptr,
                       evEnt = nullptr, evBil = nullptr, evProj = nullptr;
    if (!s1) {
        cudaStreamCreateWithFlags(&s1, cudaStreamNonBlocking);
        cudaStreamCreateWithFlags(&s2, cudaStreamNonBlocking);
        cudaEventCreateWithFlags(&evFork, cudaEventDisableTiming);
        cudaEventCreateWithFlags(&evSeq,  cudaEventDisableTiming);
        cudaEventCreateWithFlags(&evJoin, cudaEventDisableTiming);
        cudaEventCreateWithFlags(&evEnt,  cudaEventDisableTiming);
        cudaEventCreateWithFlags(&evBil,  cudaEventDisableTiming);
        cudaEventCreateWithFlags(&evProj, cudaEventDisableTiming);
    }

    cudaEventRecord(evFork, 0);
    cudaStreamWaitEvent(s1, evFork, 0);
    cudaStreamWaitEvent(s2, evFork, 0);

    // ---- s2: entity pooling (independent of attn path) ----
    k_ent_emb<<<dim3(NE, Bdoc), 256, 0, s2>>>(ent, labels);
    cudaEventRecord(evEnt, s2);

    // ---- s1: seq split (needed by rel), then weight splits ----
    k_splitT<<<dim3(Lseq/128, HID/64, Bdoc), 256, 0, s1>>>(seq,
        (uint32_t*)p_seqHi, Lseq, HID, (long)Lseq*HID, (long)HID*(Lseq/2));
    cudaEventRecord(evSeq, s1);
    k_bias2<<<3, 256, 0, s1>>>(b_head, b_tail);
    k_splitT<<<dim3(2*HID/128, EMB/64), 256, 0, s1>>>(W_head,
        (uint32_t*)p_WhtHi, 2*HID, EMB, 0, 0);
    k_splitT<<<dim3(2*HID/128, EMB/64), 256, 0, s1>>>(W_tail,
        (uint32_t*)p_WhtHi + (size_t)EMB*HID, 2*HID, EMB, 0, 0);
    k_splitT<<<dim3(KBIL/128, EMB/64), 256, 0, s1>>>(W_bil,
        (uint32_t*)p_WbHi, KBIL, EMB, 0, 0);
    cudaEventRecord(evJoin, s1);

    // ---- main: attention pooling chain ----
    k_attn_mean<<<dim3(NE, NH, Bdoc), 256>>>(attn, labels);
    k_hta<<<dim3(Rht, Bdoc), 256>>>(hts);

    // rel = hta @ seq (1-pass fp16)
    cudaStreamWaitEvent(0, evSeq, 0);
    k_gemm_h<0><<<dim3(HID/128, Rht/128, Bdoc), 256, 65536>>>(
        (const uint32_t*)p_htaH, (const uint32_t*)p_seqHi,
        nullptr, (float*)p_rel,
        Lseq, HID, (long)Rht*(Lseq/2), (long)HID*(Lseq/2), (long)Rht*HID);

    cudaStreamWaitEvent(0, evEnt, 0);
    k_gather<<<NROW, 256>>>(hts);

    cudaStreamWaitEvent(0, evJoin, 0);

    // h and t in one launch (z = head/tail), 1-pass fp16
    k_gemm_h<1><<<dim3(EMB/128, NROW/128, 2), 256, 65536>>>(
        (const uint32_t*)p_XH, (const uint32_t*)p_WhtHi,
        (const float*)p_biasht, (float*)p_ht,
        2*HID, EMB, (long)NROW*HID, (long)EMB*HID, (long)NROW*EMB);

    // bilinear (fp16 1-pass) -> d_out (embeds)
    k_bilinear_mma<<<dim3(EMB/96, NROW/128), 256, BIL_SMEM>>>(
        (const float*)p_ht, (const float*)p_ht + (size_t)NROW*EMB, b_bil, out);
    cudaEventRecord(evBil, 0);

    // proj on s1 (concurrent with cls)
    cudaStreamWaitEvent(s1, evBil, 0);
    sgemm<64,32,16,4,4,1><<<dim3(NPROJ/32, NROW/64), 128, 0, s1>>>(
        out, W_proj, b_proj, out_proj, NROW, NPROJ, EMB);
    cudaEventRecord(evProj, s1);

    // cls on main
    sgemm<64,32,16,4,4,0><<<dim3((NCLS+31)/32, NROW/64), 128>>>(
        out, W_cls, b_cls, out_cls, NROW, NCLS, EMB);
    cudaStreamWaitEvent(0, evProj, 0);
}

// round 10
// speedup vs baseline: 8.1397x; 1.2531x over previous
#include <cuda_runtime.h>
#include <cuda_bf16.h>
#include <cuda_fp16.h>
#include <math.h>
#include <stdint.h>

// ---------------- problem constants ----------------
#define Bdoc 4
#define Lseq 1024
#define Ment 128
#define Rht  512
#define HID  1024
#define NH   16
#define NE   42
#define EMB  768
#define NBLK 12
#define NCLS 97
#define NPROJ 128
#define NROW (Bdoc*Rht)   // 2048
#define KBIL (EMB*64)     // 49152
#define NITER 384         // bilinear iters (K=128 each)

// ---------------- scratch ----------------
__device__ float g_ent_emb[Bdoc*NE*HID];
__device__ float g_attn_mean[Bdoc*NE*NH*Lseq];
__device__ float g_rel[NROW*HID];
__device__ float g_ht[2*NROW*EMB];                    // h then t (fp32)
__device__ float g_bias_ht[2*EMB];
// packed fp16x2 operands
__device__ uint32_t g_WbilHi[(size_t)EMB*KBIL/2];     // 75.5 MB
__device__ uint32_t g_WhtHi[2*EMB*HID];
__device__ uint32_t g_seqTHi[Bdoc*HID*Lseq/2];
__device__ uint32_t g_htaH[NROW*Lseq/2];
__device__ uint32_t g_XH[2*NROW*HID];

// ---------------- helpers ----------------
__device__ __forceinline__ uint32_t smem_u32(const void* p) {
    uint32_t a;
    asm("{ .reg .u64 t; cvta.to.shared.u64 t, %1; cvt.u32.u64 %0, t; }"
        : "=r"(a) : "l"(p));
    return a;
}
#define SWZ(o) ((o) ^ ((((uint32_t)(o))>>3)&0x70))

#define MMA16816H(d, a0,a1,a2,a3, b0,b1) \
    asm volatile("mma.sync.aligned.m16n8k16.row.col.f32.f16.f16.f32 " \
        "{%0,%1,%2,%3},{%4,%5,%6,%7},{%8,%9},{%0,%1,%2,%3};" \
        : "+f"((d)[0]), "+f"((d)[1]), "+f"((d)[2]), "+f"((d)[3]) \
        : "r"(a0), "r"(a1), "r"(a2), "r"(a3), "r"(b0), "r"(b1))

#define LDX4(r, addr) \
    asm volatile("ldmatrix.sync.aligned.m8n8.x4.shared.b16 {%0,%1,%2,%3},[%4];" \
        : "=r"((r)[0]), "=r"((r)[1]), "=r"((r)[2]), "=r"((r)[3]) : "r"(addr))

#define CPA16(dst, src) \
    asm volatile("cp.async.cg.shared.global [%0], [%1], 16;" :: "r"(dst), "l"(src))

__device__ __forceinline__ uint32_t pack_h2(float x, float y) {
    uint32_t r;   // lo = x, hi = y
    asm("cvt.rn.f16x2.f32 %0, %1, %2;" : "=r"(r) : "f"(y), "f"(x));
    return r;
}

// ---------------- K1: entity logsumexp pooling ----------------
__global__ void k_ent_emb(const float* __restrict__ ent,
                          const int* __restrict__ labels)
{
    int e = blockIdx.x, b = blockIdx.y;
    __shared__ int s_idx[Ment];
    __shared__ int s_cnt;
    int tid = threadIdx.x;
    if (tid == 0) {
        int c = 0;
        for (int i = 0; i < Ment; i++)
            if (labels[b*Ment + i] == e) s_idx[c++] = i;
        s_cnt = c;
    }
    __syncthreads();
    int cnt = s_cnt;
    const float* eb = ent + (size_t)b*Ment*HID;
    float* out = g_ent_emb + ((size_t)(b*NE + e))*HID;
    for (int d = tid; d < HID; d += blockDim.x) {
        float r;
        if (cnt == 0) {
            r = 0.f;
        } else {
            float mx = -3.4e38f, s = 0.f;
            for (int i = 0; i < cnt; i++) {
                float v = eb[(size_t)s_idx[i]*HID + d];
                if (v > mx) { s = s*expf(mx - v) + 1.f; mx = v; }
                else        { s += expf(v - mx); }
            }
            r = mx + logf(s);
        }
        out[d] = r;
    }
}

// ---------------- K2: per-entity mean attention ----------------
__global__ void k_attn_mean(const float* __restrict__ attn,
                            const int* __restrict__ labels)
{
    int e = blockIdx.x, h = blockIdx.y, b = blockIdx.z;
    __shared__ int s_idx[Ment];
    __shared__ int s_cnt;
    int tid = threadIdx.x;
    if (tid == 0) {
        int c = 0;
        for (int i = 0; i < Ment; i++)
            if (labels[b*Ment + i] == e) s_idx[c++] = i;
        s_cnt = c;
    }
    __syncthreads();
    int cnt = s_cnt;
    float inv = 1.f / (float)(cnt > 0 ? cnt : 1);
    const float* ab = attn + (((size_t)b*NH + h)*Ment)*Lseq;
    float* out = g_attn_mean + (((size_t)(b*NE + e))*NH + h)*Lseq;
    for (int l = tid; l < Lseq; l += blockDim.x) {
        float s = 0.f;
        for (int i = 0; i < cnt; i++) s += ab[(size_t)s_idx[i]*Lseq + l];
        out[l] = s * inv;
    }
}

// ---------------- K3: hta -> single fp16 ----------------
__global__ void k_hta(const int* __restrict__ hts)
{
    int r = blockIdx.x, b = blockIdx.y;
    int r2 = b*Rht + r;
    int e0 = hts[(size_t)r2*2 + 0];
    int e1 = hts[(size_t)r2*2 + 1];
    const float* a0 = g_attn_mean + ((size_t)(b*NE + e0))*NH*Lseq;
    const float* a1 = g_attn_mean + ((size_t)(b*NE + e1))*NH*Lseq;
    int tid = threadIdx.x;
    int l0 = tid*4;
    float4 acc = make_float4(0.f,0.f,0.f,0.f);
#pragma unroll
    for (int h = 0; h < NH; h++) {
        float4 x = *(const float4*)&a0[h*Lseq + l0];
        float4 y = *(const float4*)&a1[h*Lseq + l0];
        acc.x += x.x*y.x; acc.y += x.y*y.y;
        acc.z += x.z*y.z; acc.w += x.w*y.w;
    }
    acc.x *= (1.f/NH); acc.y *= (1.f/NH); acc.z *= (1.f/NH); acc.w *= (1.f/NH);
    __shared__ float red[256];
    red[tid] = acc.x + acc.y + acc.z + acc.w;
    __syncthreads();
    for (int o = 128; o > 0; o >>= 1) {
        if (tid < o) red[tid] += red[tid + o];
        __syncthreads();
    }
    float sc = 1.f / (red[0] + 1e-5f);
    size_t o = (size_t)r2*(Lseq/2) + tid*2;
    g_htaH[o]   = pack_h2(acc.x*sc, acc.y*sc);
    g_htaH[o+1] = pack_h2(acc.z*sc, acc.w*sc);
}

// ---------------- K5: gather -> single fp16 X ----------------
__global__ void k_gather(const int* __restrict__ hts)
{
    int r2 = blockIdx.x;
    int b = r2 / Rht;
    int e0 = hts[(size_t)r2*2 + 0];
    int e1 = hts[(size_t)r2*2 + 1];
    const float* emb0 = g_ent_emb + ((size_t)(b*NE + e0))*HID;
    const float* emb1 = g_ent_emb + ((size_t)(b*NE + e1))*HID;
    const float* rel  = g_rel + (size_t)r2*HID;
    for (int u = threadIdx.x; u < HID; u += 256) {
        if (u < HID/2) {
            float2 v0 = *(const float2*)&emb0[2*u];
            g_XH[(size_t)r2*HID + u] = pack_h2(v0.x, v0.y);
            float2 v1 = *(const float2*)&emb1[2*u];
            g_XH[(size_t)(NROW + r2)*HID + u] = pack_h2(v1.x, v1.y);
        } else {
            float2 rv = *(const float2*)&rel[2*u - HID];
            uint32_t p = pack_h2(rv.x, rv.y);
            g_XH[(size_t)r2*HID + u] = p;
            g_XH[(size_t)(NROW + r2)*HID + u] = p;
        }
    }
}

// ---------------- split + transpose: [z][K][N] f32 -> [z][N][K/2] fp16x2 ----
__global__ void __launch_bounds__(256)
k_splitT(const float* __restrict__ in, uint32_t* __restrict__ outHi,
         int K, int N, long sIn, long sOut)
{
    __shared__ float s[128][65];
    in    += (size_t)blockIdx.z * sIn;
    outHi += (size_t)blockIdx.z * sOut;
    int k0 = blockIdx.x*128, n0 = blockIdx.y*64;
    int tid = threadIdx.x;
#pragma unroll
    for (int u = 0; u < 8; u++) {
        int idx = tid + u*256;
        int kk = idx >> 4;
        int cc = (idx & 15) * 4;
        float4 v = *(const float4*)&in[(size_t)(k0+kk)*N + n0 + cc];
        s[kk][cc+0] = v.x; s[kk][cc+1] = v.y;
        s[kk][cc+2] = v.z; s[kk][cc+3] = v.w;
    }
    __syncthreads();
    int K2 = K >> 1;
#pragma unroll
    for (int u = 0; u < 4; u++) {
        int idx = tid + u*256;
        int nn = idx >> 4, q = idx & 15;
        uint32_t hi[4];
#pragma unroll
        for (int i = 0; i < 4; i++)
            hi[i] = pack_h2(s[q*8 + i*2][nn], s[q*8 + i*2 + 1][nn]);
        size_t o = (size_t)(n0+nn)*K2 + (k0 >> 1) + q*4;
        *(uint4*)&outHi[o] = make_uint4(hi[0], hi[1], hi[2], hi[3]);
    }
}

__global__ void k_bias2(const float* __restrict__ b0, const float* __restrict__ b1)
{
    int i = threadIdx.x + blockIdx.x*256;
    if (i < EMB) { g_bias_ht[i] = b0[i]; g_bias_ht[EMB+i] = b1[i]; }
}

// ---------------- 1-pass fp16 mma GEMM, templated N-tile ----------------
// C[z][M][N] = act(A[z] @ B[z]^T + bias[z]); A fp16 [M][K/2], B fp16 [N][K/2]
// CTA tile 128 x NT, chunk K=64, 256 threads, warps 4(M) x 2(N).
template<int ACT, int NT>
__global__ void __launch_bounds__(256, 1)
k_gemm_h(const uint32_t* __restrict__ Ah, const uint32_t* __restrict__ Bh,
         const float* __restrict__ bias, float* __restrict__ C,
         int K, int N, long sA, long sB, long sC)
{
    constexpr int NFR  = NT/16;             // n-frags per warp
    constexpr int BUFB = 16384 + NT*128;    // bytes per stage
    extern __shared__ char smem[];
    uint32_t sb = smem_u32(smem);
    int tid = threadIdx.x, lid = tid & 31, wid = tid >> 5;
    int row0 = blockIdx.y*128, col0 = blockIdx.x*NT;
    Ah += (size_t)blockIdx.z * sA;
    Bh += (size_t)blockIdx.z * sB;
    C  += (size_t)blockIdx.z * sC;
    const float* bz = bias ? bias + (size_t)blockIdx.z * N : nullptr;
    int K2 = K >> 1, nchunk = K >> 6;
    int wm = (wid >> 1)*32, wn = (wid & 1)*(NT/2);
    int msel = lid >> 3, r8 = lid & 7;

    float acc[2][NFR][4];
#pragma unroll
    for (int i = 0; i < 2; i++)
#pragma unroll
        for (int n = 0; n < NFR; n++)
#pragma unroll
            for (int q = 0; q < 4; q++) acc[i][n][q] = 0.f;

#define GLOADH(c) { \
    uint32_t base = sb + (uint32_t)((c)&1)*BUFB; \
    _Pragma("unroll") \
    for (int p = 0; p < 4; p++) { \
        int idx = tid + p*256; int r = idx >> 3, seg = idx & 7; \
        size_t goA = (size_t)(row0+r)*K2 + (size_t)(c)*32 + seg*4; \
        CPA16(base + SWZ((uint32_t)(r*128 + seg*16)), Ah + goA); \
    } \
    _Pragma("unroll") \
    for (int p = 0; p < NT/32; p++) { \
        int idx = tid + p*256; int r = idx >> 3, seg = idx & 7; \
        size_t goB = (size_t)(col0+r)*K2 + (size_t)(c)*32 + seg*4; \
        CPA16(base + 16384u + SWZ((uint32_t)(r*128 + seg*16)), Bh + goB); \
    } }

    GLOADH(0);
    asm volatile("cp.async.commit_group;");

#pragma unroll 1
    for (int c = 0; c < nchunk; ++c) {
        if (c + 1 < nchunk) GLOADH(c + 1);
        asm volatile("cp.async.commit_group;");
        asm volatile("cp.async.wait_group 1;");
        __syncthreads();

        uint32_t abase = sb + (uint32_t)(c & 1)*BUFB;
        uint32_t bbase = abase + 16384u;
#pragma unroll
        for (int s = 0; s < 4; ++s) {
            uint32_t ah[2][4];
#pragma unroll
            for (int i = 0; i < 2; ++i) {
                uint32_t off = SWZ((uint32_t)((wm + i*16 + (lid & 15))*128
                                              + s*32 + (lid >> 4)*16));
                LDX4(ah[i], abase + off);
            }
            uint32_t bh[2*NFR];
#pragma unroll
            for (int pq = 0; pq < NT/32; ++pq) {
                uint32_t off = SWZ((uint32_t)((wn + (pq*2 + (msel >> 1))*8 + r8)*128
                                              + s*32 + (msel & 1)*16));
                LDX4(&bh[pq*4], bbase + off);
            }
#pragma unroll
            for (int i = 0; i < 2; ++i)
#pragma unroll
                for (int n = 0; n < NFR; ++n)
                    MMA16816H(acc[i][n], ah[i][0],ah[i][1],ah[i][2],ah[i][3], bh[n*2], bh[n*2+1]);
        }
        __syncthreads();
    }
#undef GLOADH

#pragma unroll
    for (int i = 0; i < 2; ++i) {
        int gr = row0 + wm + i*16 + (lid >> 2);
#pragma unroll
        for (int n = 0; n < NFR; ++n) {
            int gc = col0 + wn + n*8 + (lid & 3)*2;
            float b0v = bz ? bz[gc] : 0.f, b1v = bz ? bz[gc+1] : 0.f;
            float v0 = acc[i][n][0] + b0v, v1 = acc[i][n][1] + b1v;
            float v2 = acc[i][n][2] + b0v, v3 = acc[i][n][3] + b1v;
            if (ACT == 1) { v0 = tanhf(v0); v1 = tanhf(v1); v2 = tanhf(v2); v3 = tanhf(v3); }
            *(float2*)&C[(size_t)gr*N + gc]     = make_float2(v0, v1);
            *(float2*)&C[(size_t)(gr+8)*N + gc] = make_float2(v2, v3);
        }
    }
}

// ---------------- fp32 SIMT sgemm (small tails: cls/proj) ----------------
template<int BM, int BN, int BK, int TM, int TN, int ACT>
__global__ __launch_bounds__((BM/TM)*(BN/TN))
void sgemm(const float* __restrict__ A, const float* __restrict__ B,
           const float* __restrict__ bias, float* __restrict__ C,
           int M, int N, int K)
{
    constexpr int THREADS = (BM/TM)*(BN/TN);
    __shared__ float As[BK][BM + 4];
    __shared__ float Bs[BK][BN];
    int tid = threadIdx.x;
    int tx = tid % (BN/TN);
    int ty = tid / (BN/TN);
    int row0 = blockIdx.y * BM, col0 = blockIdx.x * BN;
    float acc[TM][TN] = {};
    constexpr int AE = BM*BK/THREADS;
    constexpr int BE = BK*BN/THREADS;

    for (int k0 = 0; k0 < K; k0 += BK) {
#pragma unroll
        for (int u = 0; u < AE; u++) {
            int idx = tid + u*THREADS;
            int r = idx / BK, c = idx % BK;
            float v = 0.f;
            int gr = row0 + r;
            if (gr < M) v = A[(size_t)gr*K + k0 + c];
            As[c][r] = v;
        }
#pragma unroll
        for (int u = 0; u < BE; u++) {
            int idx = tid + u*THREADS;
            int r = idx / BN, c = idx % BN;
            float v = 0.f;
            int gc = col0 + c;
            if (gc < N) v = B[(size_t)(k0 + r)*N + gc];
            Bs[r][c] = v;
        }
        __syncthreads();
#pragma unroll
        for (int kk = 0; kk < BK; kk++) {
            float af[TM], bf[TN];
#pragma unroll
            for (int i = 0; i < TM; i += 4)
                *reinterpret_cast<float4*>(&af[i]) =
                    *reinterpret_cast<const float4*>(&As[kk][ty*TM + i]);
#pragma unroll
            for (int j = 0; j < TN; j += 4)
                *reinterpret_cast<float4*>(&bf[j]) =
                    *reinterpret_cast<const float4*>(&Bs[kk][tx*TN + j]);
#pragma unroll
            for (int i = 0; i < TM; i++)
#pragma unroll
                for (int j = 0; j < TN; j++)
                    acc[i][j] += af[i] * bf[j];
        }
        __syncthreads();
    }
#pragma unroll
    for (int i = 0; i < TM; i++) {
        int gr = row0 + ty*TM + i;
        if (gr >= M) continue;
#pragma unroll
        for (int j = 0; j < TN; j++) {
            int gc = col0 + tx*TN + j;
            if (gc >= N) continue;
            float v = acc[i][j];
            if (bias) v += bias[gc];
            if (ACT == 1) v = tanhf(v);
            C[(size_t)gr*N + gc] = v;
        }
    }
}

// ---------------- bilinear GEMM via fp16 mma (1-pass, K=128/iter) ----------
// 3-stage cp.async pipeline, one barrier per iteration.
#define BIL_BUF   24576u                    // per stage: 2 chunks x 12KB
#define BIL_SH_OFF (3*24576)
#define BIL_ST_OFF (3*24576 + 34816)
#define BIL_SMEM   (3*24576 + 2*34816)      // 143360

__device__ __forceinline__ void bil_load2(uint32_t sb, int it, int col0, int tid)
{
    uint32_t dH = sb + (uint32_t)(it % 3)*BIL_BUF;
#pragma unroll
    for (int half = 0; half < 2; ++half) {
        int c = it*2 + half;
#pragma unroll
        for (int p = 0; p < 3; p++) {
            int idx = tid + p*256;
            int n = idx >> 3, seg = idx & 7;
            size_t go = (size_t)(col0 + n)*(KBIL/2) + (size_t)c*32 + seg*4;
            CPA16(dH + half*12288u + SWZ((uint32_t)(n*128 + seg*16)), g_WbilHi + go);
        }
    }
}

__global__ void __launch_bounds__(256, 1)
k_bilinear_mma(const float* __restrict__ h, const float* __restrict__ t,
               const float* __restrict__ bias, float* __restrict__ out)
{
    extern __shared__ char smem[];
    uint32_t sb = smem_u32(smem);
    float* s_h = (float*)(smem + BIL_SH_OFF);   // [128][68]
    float* s_t = (float*)(smem + BIL_ST_OFF);   // [128][68]
    int tid = threadIdx.x, lid = tid & 31, wid = tid >> 5;
    int row0 = blockIdx.y * 128, col0 = blockIdx.x * 96;
    int wm = (wid >> 1) * 32;
    int wn = (wid & 1) * 48;
    int msel = lid >> 3, r8 = lid & 7;

    float acc[2][6][4];
#pragma unroll
    for (int i = 0; i < 2; i++)
#pragma unroll
        for (int n = 0; n < 6; n++)
#pragma unroll
            for (int q = 0; q < 4; q++) acc[i][n][q] = 0.f;

    // prologue: stages 0 and 1 in flight
    bil_load2(sb, 0, col0, tid);
    asm volatile("cp.async.commit_group;");
    bil_load2(sb, 1, col0, tid);
    asm volatile("cp.async.commit_group;");

#pragma unroll 1
    for (int it = 0; it < NITER; ++it) {
        asm volatile("cp.async.wait_group 1;");   // stage `it` ready (own)
        __syncthreads();                          // all threads' stage-it data visible;
                                                  // all warps done computing it-1
        if ((it & 31) == 0) {                     // new j-block: reload h/t slices
            int j = it >> 5;
            for (int idx = tid; idx < 128*16; idx += 256) {
                int rr = idx >> 4, cc = (idx & 15) * 4;
                *(float4*)&s_h[rr*68 + cc] =
                    *(const float4*)&h[(size_t)(row0+rr)*EMB + j*64 + cc];
                *(float4*)&s_t[rr*68 + cc] =
                    *(const float4*)&t[(size_t)(row0+rr)*EMB + j*64 + cc];
            }
            __syncthreads();
        }

        uint32_t stage = sb + (uint32_t)(it % 3)*BIL_BUF;
#pragma unroll
        for (int half = 0; half < 2; ++half) {
            int a = (it*2 + half) & 63;
            uint32_t bbase = stage + half*12288u;
            float h0[2], h1[2];
#pragma unroll
            for (int i = 0; i < 2; i++) {
                int r0 = wm + i*16 + (lid >> 2);
                h0[i] = s_h[r0*68 + a];
                h1[i] = s_h[(r0 + 8)*68 + a];
            }
#pragma unroll
            for (int s = 0; s < 4; ++s) {
                uint32_t bh[12];
#pragma unroll
                for (int pq = 0; pq < 3; ++pq) {
                    uint32_t off = SWZ((uint32_t)((wn + (pq*2 + (msel >> 1))*8 + r8)*128
                                                  + s*32 + (msel & 1)*16));
                    LDX4(&bh[pq*4], bbase + off);
                }
#pragma unroll
                for (int i = 0; i < 2; ++i) {
                    int rb = (wm + i*16 + (lid >> 2))*68;
                    int cc = s*16 + (lid & 3)*2;
                    float2 ta = *(float2*)&s_t[rb + cc];
                    float2 tb = *(float2*)&s_t[rb + cc + 8];
                    float2 tc = *(float2*)&s_t[rb + 8*68 + cc];
                    float2 td = *(float2*)&s_t[rb + 8*68 + cc + 8];
                    uint32_t ah[4];
                    ah[0] = pack_h2(h0[i]*ta.x, h0[i]*ta.y);
                    ah[1] = pack_h2(h1[i]*tc.x, h1[i]*tc.y);
                    ah[2] = pack_h2(h0[i]*tb.x, h0[i]*tb.y);
                    ah[3] = pack_h2(h1[i]*td.x, h1[i]*td.y);
#pragma unroll
                    for (int n = 0; n < 6; ++n)
                        MMA16816H(acc[i][n], ah[0],ah[1],ah[2],ah[3], bh[n*2], bh[n*2+1]);
                }
            }
        }

        // issue stage it+2 (buffer (it+2)%3 was last read at iter it-1;
        // the barrier above guarantees every warp is past that)
        if (it + 2 < NITER) bil_load2(sb, it + 2, col0, tid);
        asm volatile("cp.async.commit_group;");
    }

#pragma unroll
    for (int i = 0; i < 2; ++i) {
        int gr = row0 + wm + i*16 + (lid >> 2);
#pragma unroll
        for (int n = 0; n < 6; ++n) {
            int gc = col0 + wn + n*8 + (lid & 3)*2;
            float2 v0 = make_float2(acc[i][n][0] + bias[gc],
                                    acc[i][n][1] + bias[gc+1]);
            float2 v1 = make_float2(acc[i][n][2] + bias[gc],
                                    acc[i][n][3] + bias[gc+1]);
            *(float2*)&out[(size_t)gr*EMB + gc]     = v0;
            *(float2*)&out[(size_t)(gr+8)*EMB + gc] = v1;
        }
    }
}

// ---------------- launch ----------------
extern "C" void kernel_launch(void* const* d_in, const int* in_sizes, int n_in,
                              void* d_out, int out_size)
{
    const float* seq    = (const float*)d_in[0];
    const float* ent    = (const float*)d_in[1];
    const float* attn   = (const float*)d_in[2];
    const int*   labels = (const int*)  d_in[3];
    const int*   hts    = (const int*)  d_in[4];
    const float* W_head = (const float*)d_in[5];
    const float* b_head = (const float*)d_in[6];
    const float* W_tail = (const float*)d_in[7];
    const float* b_tail = (const float*)d_in[8];
    const float* W_bil  = (const float*)d_in[9];
    const float* b_bil  = (const float*)d_in[10];
    const float* W_cls  = (const float*)d_in[11];
    const float* b_cls  = (const float*)d_in[12];
    const float* W_proj = (const float*)d_in[13];
    const float* b_proj = (const float*)d_in[14];

    float* out      = (float*)d_out;
    float* out_cls  = out + (size_t)NROW*EMB;
    float* out_proj = out_cls + (size_t)NROW*NCLS;

    void *p_rel, *p_ht, *p_biasht;
    void *p_WbHi, *p_WhtHi, *p_seqHi, *p_htaH, *p_XH;
    cudaGetSymbolAddress(&p_rel,   g_rel);
    cudaGetSymbolAddress(&p_ht,    g_ht);
    cudaGetSymbolAddress(&p_biasht,g_bias_ht);
    cudaGetSymbolAddress(&p_WbHi,  g_WbilHi);
    cudaGetSymbolAddress(&p_WhtHi, g_WhtHi);
    cudaGetSymbolAddress(&p_seqHi, g_seqTHi);
    cudaGetSymbolAddress(&p_htaH,  g_htaH);
    cudaGetSymbolAddress(&p_XH,    g_XH);

    cudaFuncSetAttribute(k_bilinear_mma,
                         cudaFuncAttributeMaxDynamicSharedMemorySize, BIL_SMEM);
    cudaFuncSetAttribute(k_gemm_h<0,128>,
                         cudaFuncAttributeMaxDynamicSharedMemorySize, 65536);
    cudaFuncSetAttribute(k_gemm_h<1,64>,
                         cudaFuncAttributeMaxDynamicSharedMemorySize, 49152);

    static cudaStream_t s1 = nullptr, s2 = nullptr;
    static cudaEvent_t evFork = nullptr, evSeq = nullptr, evJoin = nullptr,
                       evEnt = nullptr, evBil = nullptr, evProj = nullptr;
    if (!s1) {
        cudaStreamCreateWithFlags(&s1, cudaStreamNonBlocking);
        cudaStreamCreateWithFlags(&s2, cudaStreamNonBlocking);
        cudaEventCreateWithFlags(&evFork, cudaEventDisableTiming);
        cudaEventCreateWithFlags(&evSeq,  cudaEventDisableTiming);
        cudaEventCreateWithFlags(&evJoin, cudaEventDisableTiming);
        cudaEventCreateWithFlags(&evEnt,  cudaEventDisableTiming);
        cudaEventCreateWithFlags(&evBil,  cudaEventDisableTiming);
        cudaEventCreateWithFlags(&evProj, cudaEventDisableTiming);
    }

    cudaEventRecord(evFork, 0);
    cudaStreamWaitEvent(s1, evFork, 0);
    cudaStreamWaitEvent(s2, evFork, 0);

    // ---- s2: entity pooling (independent of attn path) ----
    k_ent_emb<<<dim3(NE, Bdoc), 256, 0, s2>>>(ent, labels);
    cudaEventRecord(evEnt, s2);

    // ---- s1: seq split (needed by rel), then weight splits ----
    k_splitT<<<dim3(Lseq/128, HID/64, Bdoc), 256, 0, s1>>>(seq,
        (uint32_t*)p_seqHi, Lseq, HID, (long)Lseq*HID, (long)HID*(Lseq/2));
    cudaEventRecord(evSeq, s1);
    k_bias2<<<3, 256, 0, s1>>>(b_head, b_tail);
    k_splitT<<<dim3(2*HID/128, EMB/64), 256, 0, s1>>>(W_head,
        (uint32_t*)p_WhtHi, 2*HID, EMB, 0, 0);
    k_splitT<<<dim3(2*HID/128, EMB/64), 256, 0, s1>>>(W_tail,
        (uint32_t*)p_WhtHi + (size_t)EMB*HID, 2*HID, EMB, 0, 0);
    k_splitT<<<dim3(KBIL/128, EMB/64), 256, 0, s1>>>(W_bil,
        (uint32_t*)p_WbHi, KBIL, EMB, 0, 0);
    cudaEventRecord(evJoin, s1);

    // ---- main: attention pooling chain ----
    k_attn_mean<<<dim3(NE, NH, Bdoc), 256>>>(attn, labels);
    k_hta<<<dim3(Rht, Bdoc), 256>>>(hts);

    // rel = hta @ seq (1-pass fp16, N-tile 128)
    cudaStreamWaitEvent(0, evSeq, 0);
    k_gemm_h<0,128><<<dim3(HID/128, Rht/128, Bdoc), 256, 65536>>>(
        (const uint32_t*)p_htaH, (const uint32_t*)p_seqHi,
        nullptr, (float*)p_rel,
        Lseq, HID, (long)Rht*(Lseq/2), (long)HID*(Lseq/2), (long)Rht*HID);

    cudaStreamWaitEvent(0, evEnt, 0);
    k_gather<<<NROW, 256>>>(hts);

    cudaStreamWaitEvent(0, evJoin, 0);

    // h and t in one launch (z = head/tail), 1-pass fp16, N-tile 64
    k_gemm_h<1,64><<<dim3(EMB/64, NROW/128, 2), 256, 49152>>>(
        (const uint32_t*)p_XH, (const uint32_t*)p_WhtHi,
        (const float*)p_biasht, (float*)p_ht,
        2*HID, EMB, (long)NROW*HID, (long)EMB*HID, (long)NROW*EMB);

    // bilinear (fp16 1-pass, 3-stage pipeline) -> d_out (embeds)
    k_bilinear_mma<<<dim3(EMB/96, NROW/128), 256, BIL_SMEM>>>(
        (const float*)p_ht, (const float*)p_ht + (size_t)NROW*EMB, b_bil, out);
    cudaEventRecord(evBil, 0);

    // proj on s1 (concurrent with cls)
    cudaStreamWaitEvent(s1, evBil, 0);
    sgemm<64,32,16,4,4,1><<<dim3(NPROJ/32, NROW/64), 128, 0, s1>>>(
        out, W_proj, b_proj, out_proj, NROW, NPROJ, EMB);
    cudaEventRecord(evProj, s1);

    // cls on main
    sgemm<64,32,16,4,4,0><<<dim3((NCLS+31)/32, NROW/64), 128>>>(
        out, W_cls, b_cls, out_cls, NROW, NCLS, EMB);
    cudaStreamWaitEvent(0, evProj, 0);
}